// round 3
// baseline (speedup 1.0000x reference)
#include <cuda_runtime.h>
#include <math.h>

#define BB 2
#define TT 2048
#define CC 2048
#define NH 16
#define NKV 4
#define DH 128
#define BT (BB*TT)          // 4096
#define KVC (2*NKV*DH)      // 1024

// ---------------- scratch (static device globals; no allocation) ----------------
__device__ float g_qlin[BB*TT*CC];     // 33.5 MB
__device__ float g_kvlin[BB*TT*KVC];   // 16.8 MB
__device__ float g_q[BB*NH*TT*DH];     // 33.5 MB
__device__ float g_k[BB*NKV*TT*DH];    // 8.4 MB
__device__ float g_v[BB*NKV*TT*DH];    // 8.4 MB
__device__ float g_attn[BB*TT*CC];     // 33.5 MB

// ---------------- GEMM: C[M,N] = A[M,K] @ B[N,K]^T (all fp32, row-major) --------
// 128x128 block tile, BK=16, 256 threads, 8x8 microtile (split 4+4 at +64)
#define GSTR 132   // padded smem row stride (floats), 16B-aligned (132*4=528=33*16)
__global__ void __launch_bounds__(256) gemm_abt(const float* __restrict__ A,
                                                const float* __restrict__ B,
                                                float* __restrict__ C,
                                                int M, int N, int K) {
    __shared__ float As[16*GSTR];
    __shared__ float Bs[16*GSTR];
    const int tid = threadIdx.x;
    const int m0 = blockIdx.y * 128, n0 = blockIdx.x * 128;
    const int tx = tid & 15, ty = tid >> 4;
    const int lr = tid >> 2, lk = (tid & 3) << 2;

    float acc[8][8];
#pragma unroll
    for (int i = 0; i < 8; i++)
#pragma unroll
        for (int j = 0; j < 8; j++) acc[i][j] = 0.f;

    for (int k0 = 0; k0 < K; k0 += 16) {
#pragma unroll
        for (int rr = 0; rr < 2; rr++) {
            int r = lr + rr * 64;
            float4 a = *(const float4*)(A + (size_t)(m0 + r) * K + k0 + lk);
            As[(lk + 0) * GSTR + r] = a.x;
            As[(lk + 1) * GSTR + r] = a.y;
            As[(lk + 2) * GSTR + r] = a.z;
            As[(lk + 3) * GSTR + r] = a.w;
            float4 b = *(const float4*)(B + (size_t)(n0 + r) * K + k0 + lk);
            Bs[(lk + 0) * GSTR + r] = b.x;
            Bs[(lk + 1) * GSTR + r] = b.y;
            Bs[(lk + 2) * GSTR + r] = b.z;
            Bs[(lk + 3) * GSTR + r] = b.w;
        }
        __syncthreads();
#pragma unroll
        for (int kk = 0; kk < 16; kk++) {
            float a[8], b[8];
            *(float4*)(a)     = *(const float4*)&As[kk * GSTR + ty * 4];
            *(float4*)(a + 4) = *(const float4*)&As[kk * GSTR + ty * 4 + 64];
            *(float4*)(b)     = *(const float4*)&Bs[kk * GSTR + tx * 4];
            *(float4*)(b + 4) = *(const float4*)&Bs[kk * GSTR + tx * 4 + 64];
#pragma unroll
            for (int i = 0; i < 8; i++)
#pragma unroll
                for (int j = 0; j < 8; j++) acc[i][j] += a[i] * b[j];
        }
        __syncthreads();
    }
#pragma unroll
    for (int i = 0; i < 8; i++) {
        int r = m0 + ((i < 4) ? (ty * 4 + i) : (64 + ty * 4 + i - 4));
        *(float4*)(C + (size_t)r * N + n0 + tx * 4) =
            make_float4(acc[i][0], acc[i][1], acc[i][2], acc[i][3]);
        *(float4*)(C + (size_t)r * N + n0 + 64 + tx * 4) =
            make_float4(acc[i][4], acc[i][5], acc[i][6], acc[i][7]);
    }
}

// ------------- fused RMSNorm + rotary, warp per (b,t,h) row; transpose out ------
// NOTE: reference's _apply_rotary uses x.shape[-3] (= the HEAD axis after the
// (0,2,1,3) transpose) as the position axis. So the rotation angle is
// h * freq[j], identical for every timestep. Not t * freq[j].
__global__ void normrope_kernel(const float* __restrict__ in, float* __restrict__ out,
                                int rowstride, int nheads) {
    int w = (blockIdx.x * blockDim.x + threadIdx.x) >> 5;
    int lane = threadIdx.x & 31;
    int total = BB * TT * nheads;
    if (w >= total) return;
    int h = w % nheads;
    int t = (w / nheads) % TT;
    int b = w / (nheads * TT);

    const float* src = in + (size_t)(b * TT + t) * rowstride + h * DH;
    float4 v = *(const float4*)(src + lane * 4);
    float ss = v.x * v.x + v.y * v.y + v.z * v.z + v.w * v.w;
#pragma unroll
    for (int o = 16; o; o >>= 1) ss += __shfl_xor_sync(0xffffffffu, ss, o);
    float scale = rsqrtf(ss * (1.0f / 128.0f) + 1.1920929e-07f);

    float x[4] = {v.x * scale, v.y * scale, v.z * scale, v.w * scale};
    float y[4];
#pragma unroll
    for (int i = 0; i < 4; i++) {
        float part = __shfl_xor_sync(0xffffffffu, x[i], 16);
        int d = lane * 4 + i;
        int j = d & 63;
        float freq = (j < 32) ? powf(1.0f / 1024.0f, (float)j * (1.0f / 31.0f)) : 0.0f;
        float s, c;
        sincosf((float)h * freq, &s, &c);   // position = HEAD index (see note)
        if (d < 64) y[i] = x[i] * c + part * s;     // y1 = x1*cos + x2*sin
        else        y[i] = -part * s + x[i] * c;    // y2 = -x1*sin + x2*cos
    }
    float* dst = out + ((size_t)(b * nheads + h) * TT + t) * DH + lane * 4;
    *(float4*)dst = make_float4(y[0], y[1], y[2], y[3]);
}

// ------------- V transpose: kv_lin[.., 512 + h*128 + d] -> [b,h,t,d] ------------
__global__ void vtrans_kernel(const float* __restrict__ kvlin, float* __restrict__ out) {
    int idx = blockIdx.x * blockDim.x + threadIdx.x;
    const int total = BB * TT * NKV * DH / 4;
    if (idx >= total) return;
    int d4 = idx & (DH / 4 - 1);
    int h = (idx >> 5) & (NKV - 1);
    int t = (idx >> 7) & (TT - 1);
    int b = idx >> 18;
    float4 v = *(const float4*)(kvlin + (size_t)(b * TT + t) * KVC + NKV * DH + h * DH + d4 * 4);
    *(float4*)(out + ((size_t)(b * NKV + h) * TT + t) * DH + d4 * 4) = v;
}

// ------------- flash attention fp32: 64q x 64k tiles, 256 threads --------------
#define FBQ 64
#define FBK 64
#define SSTR 65
#define FLASH_SMEM ((3 * 64 * 128 + 64 * SSTR + 3 * 64) * 4)

extern __shared__ float fsm[];
__global__ void __launch_bounds__(256) flash_kernel(const float* __restrict__ Q,
                                                    const float* __restrict__ K,
                                                    const float* __restrict__ V,
                                                    float* __restrict__ O) {
    float* Qs = fsm;                    // 64*128
    float* Ks = Qs + 64 * 128;          // 64*128
    float* Vs = Ks + 64 * 128;          // 64*128
    float* Ss = Vs + 64 * 128;          // 64*65
    float* m_s = Ss + 64 * SSTR;
    float* l_s = m_s + 64;
    float* corr_s = l_s + 64;

    const int tid = threadIdx.x;
    const int qt = blockIdx.x, h = blockIdx.y, b = blockIdx.z;
    const int kvh = h >> 2;  // rep = NH/NKV = 4

    const float* Qp = Q + ((size_t)(b * NH + h) * TT + qt * FBQ) * DH;
    const float* Kp = K + (size_t)(b * NKV + kvh) * TT * DH;
    const float* Vp = V + (size_t)(b * NKV + kvh) * TT * DH;

#pragma unroll
    for (int it = 0; it < 8; it++) {
        int idx = tid + it * 256;
        int r = idx >> 5, d4 = (idx & 31) * 4;
        *(float4*)&Qs[r * 128 + d4] = *(const float4*)(Qp + r * DH + d4);
    }
    if (tid < 64) { m_s[tid] = -1e30f; l_s[tid] = 0.f; }

    float acc[8][4];
#pragma unroll
    for (int j = 0; j < 8; j++)
#pragma unroll
        for (int jj = 0; jj < 4; jj++) acc[j][jj] = 0.f;

    const int tx = tid & 15, ty = tid >> 4;
    const int vrow = tid >> 2, vc = (tid & 3) * 4;
    const float scl = 0.08838834764831845f;  // 1/sqrt(128)
    const int ntiles = qt + 1;

    for (int kt = 0; kt < ntiles; kt++) {
        __syncthreads();
#pragma unroll
        for (int it = 0; it < 8; it++) {
            int idx = tid + it * 256;
            int r = idx >> 5, d4 = (idx & 31) * 4;
            *(float4*)&Ks[r * 128 + d4] = *(const float4*)(Kp + (kt * FBK + r) * DH + d4);
            *(float4*)&Vs[r * 128 + d4] = *(const float4*)(Vp + (kt * FBK + r) * DH + d4);
        }
        __syncthreads();

        // ---- S = Q @ K^T (per-thread 4x4, bank-conflict-free via d rotation) ----
        float s[4][4];
#pragma unroll
        for (int i = 0; i < 4; i++)
#pragma unroll
            for (int j = 0; j < 4; j++) s[i][j] = 0.f;
        const int rot = tx * 4;
#pragma unroll 8
        for (int dd = 0; dd < 128; dd += 4) {
            int d = (dd + rot) & 127;
            float4 a0 = *(const float4*)&Qs[(ty * 4 + 0) * 128 + d];
            float4 a1 = *(const float4*)&Qs[(ty * 4 + 1) * 128 + d];
            float4 a2 = *(const float4*)&Qs[(ty * 4 + 2) * 128 + d];
            float4 a3 = *(const float4*)&Qs[(ty * 4 + 3) * 128 + d];
            float4 b0 = *(const float4*)&Ks[(tx * 4 + 0) * 128 + d];
            float4 b1 = *(const float4*)&Ks[(tx * 4 + 1) * 128 + d];
            float4 b2 = *(const float4*)&Ks[(tx * 4 + 2) * 128 + d];
            float4 b3 = *(const float4*)&Ks[(tx * 4 + 3) * 128 + d];
            float4 aa[4] = {a0, a1, a2, a3};
            float4 bb[4] = {b0, b1, b2, b3};
#pragma unroll
            for (int i = 0; i < 4; i++)
#pragma unroll
                for (int j = 0; j < 4; j++)
                    s[i][j] += aa[i].x * bb[j].x + aa[i].y * bb[j].y +
                               aa[i].z * bb[j].z + aa[i].w * bb[j].w;
        }

        // ---- online softmax (rows owned by aligned 16-lane groups) ----
#pragma unroll
        for (int i = 0; i < 4; i++) {
            int rloc = ty * 4 + i;
            int rg = qt * FBQ + rloc;
            float rowmax = -1e30f;
#pragma unroll
            for (int j = 0; j < 4; j++) {
                int cg = kt * FBK + tx * 4 + j;
                s[i][j] = (cg <= rg) ? s[i][j] * scl : -1e30f;
                rowmax = fmaxf(rowmax, s[i][j]);
            }
#pragma unroll
            for (int o = 8; o; o >>= 1)
                rowmax = fmaxf(rowmax, __shfl_xor_sync(0xffffffffu, rowmax, o));
            float m_old = m_s[rloc];
            float m_new = fmaxf(m_old, rowmax);
            float rs = 0.f;
#pragma unroll
            for (int j = 0; j < 4; j++) {
                float p = __expf(s[i][j] - m_new);
                Ss[rloc * SSTR + tx * 4 + j] = p;
                rs += p;
            }
#pragma unroll
            for (int o = 8; o; o >>= 1) rs += __shfl_xor_sync(0xffffffffu, rs, o);
            if (tx == 0) {
                float cr = __expf(m_old - m_new);
                corr_s[rloc] = cr;
                l_s[rloc] = l_s[rloc] * cr + rs;
                m_s[rloc] = m_new;
            }
        }
        __syncthreads();

        // ---- O = O*corr + P @ V  (cols vc + 16*j: conflict-free) ----
        float cr = corr_s[vrow];
#pragma unroll
        for (int j = 0; j < 8; j++)
#pragma unroll
            for (int jj = 0; jj < 4; jj++) acc[j][jj] *= cr;
#pragma unroll 4
        for (int k = 0; k < FBK; k++) {
            float p = Ss[vrow * SSTR + k];
#pragma unroll
            for (int j = 0; j < 8; j++) {
                float4 vv = *(const float4*)&Vs[k * 128 + vc + j * 16];
                acc[j][0] += p * vv.x;
                acc[j][1] += p * vv.y;
                acc[j][2] += p * vv.z;
                acc[j][3] += p * vv.w;
            }
        }
    }

    float linv = 1.0f / l_s[vrow];
    float* Op = O + ((size_t)b * TT + qt * FBQ + vrow) * CC + h * DH;
#pragma unroll
    for (int j = 0; j < 8; j++)
        *(float4*)(Op + vc + j * 16) =
            make_float4(acc[j][0] * linv, acc[j][1] * linv, acc[j][2] * linv, acc[j][3] * linv);
}

// ------------- tail zero for the extra scalar output ---------------------------
__global__ void tailzero_kernel(float* out, int start, int total) {
    int i = start + blockIdx.x * blockDim.x + threadIdx.x;
    if (i < total) out[i] = 0.f;
}

// ------------- launcher --------------------------------------------------------
extern "C" void kernel_launch(void* const* d_in, const int* in_sizes, int n_in,
                              void* d_out, int out_size) {
    const float* x     = (const float*)d_in[0];
    const float* Wq    = (const float*)d_in[1];
    const float* Wkv   = (const float*)d_in[2];
    const float* Wproj = (const float*)d_in[3];
    // d_in[4] = tok_masks (all ones; unused by reference math)
    float* out = (float*)d_out;

    float *qlin, *kvlin, *qb, *kb, *vb, *attn;
    cudaGetSymbolAddress((void**)&qlin, g_qlin);
    cudaGetSymbolAddress((void**)&kvlin, g_kvlin);
    cudaGetSymbolAddress((void**)&qb, g_q);
    cudaGetSymbolAddress((void**)&kb, g_k);
    cudaGetSymbolAddress((void**)&vb, g_v);
    cudaGetSymbolAddress((void**)&attn, g_attn);

    // 1) Q = x @ Wq^T   [4096, 2048]
    {
        dim3 g(CC / 128, BT / 128);
        gemm_abt<<<g, 256>>>(x, Wq, qlin, BT, CC, CC);
    }
    // 2) KV = x @ Wkv^T [4096, 1024]
    {
        dim3 g(KVC / 128, BT / 128);
        gemm_abt<<<g, 256>>>(x, Wkv, kvlin, BT, KVC, CC);
    }
    // 3) RMSNorm + RoPE on Q -> [b,h,t,d]
    {
        int rows = BB * TT * NH;
        normrope_kernel<<<(rows * 32 + 255) / 256, 256>>>(qlin, qb, CC, NH);
    }
    // 4) RMSNorm + RoPE on K -> [b,kvh,t,d]
    {
        int rows = BB * TT * NKV;
        normrope_kernel<<<(rows * 32 + 255) / 256, 256>>>(kvlin, kb, KVC, NKV);
    }
    // 5) V transpose
    {
        int total = BB * TT * NKV * DH / 4;
        vtrans_kernel<<<(total + 255) / 256, 256>>>(kvlin, vb);
    }
    // 6) flash attention -> attn [b,t, h*dh]
    {
        cudaFuncSetAttribute(flash_kernel, cudaFuncAttributeMaxDynamicSharedMemorySize,
                             FLASH_SMEM);
        dim3 g(TT / FBQ, NH, BB);
        flash_kernel<<<g, 256, FLASH_SMEM>>>(qb, kb, vb, attn);
    }
    // 7) y = attn @ Wproj^T -> out
    {
        dim3 g(CC / 128, BT / 128);
        gemm_abt<<<g, 256>>>(attn, Wproj, out, BT, CC, CC);
    }
    // 8) trailing scalar output (0.0f)
    {
        int btc = BB * TT * CC;
        if (out_size > btc) {
            int rem = out_size - btc;
            tailzero_kernel<<<(rem + 255) / 256, 256>>>(out, btc, out_size);
        }
    }
}

// round 6
// speedup vs baseline: 1.3582x; 1.3582x over previous
#include <cuda_runtime.h>
#include <cuda_bf16.h>
#include <math.h>
#include <stdint.h>

#define BB 2
#define TT 2048
#define CC 2048
#define NH 16
#define NKV 4
#define DH 128
#define BT (BB*TT)          // 4096
#define KVC (2*NKV*DH)      // 1024

// ---------------- scratch (static device globals; no allocation) ----------------
__device__ float g_qlin[BB*TT*CC];
__device__ float g_kvlin[BB*TT*KVC];
__device__ float g_q[BB*NH*TT*DH];
__device__ float g_k[BB*NKV*TT*DH];
__device__ float g_v[BB*NKV*TT*DH];
__device__ float g_attn[BB*TT*CC];
// bf16 hi/lo split operands for tensor-core GEMMs
__device__ __nv_bfloat16 g_xhi[BT*CC],   g_xlo[BT*CC];
__device__ __nv_bfloat16 g_wqhi[CC*CC],  g_wqlo[CC*CC];
__device__ __nv_bfloat16 g_wkvhi[KVC*CC],g_wkvlo[KVC*CC];
__device__ __nv_bfloat16 g_wphi[CC*CC],  g_wplo[CC*CC];
__device__ __nv_bfloat16 g_ahi[BT*CC],   g_alo[BT*CC];

// ======================= warp-MMA helpers (sm_80+ portable) =====================
__device__ __forceinline__ uint32_t smem_to_u32(const void* p) {
    uint32_t a;
    asm("{ .reg .u64 t; cvta.to.shared.u64 t, %1; cvt.u32.u64 %0, t; }" : "=r"(a) : "l"(p));
    return a;
}
__device__ __forceinline__ void ldsm_x4(uint32_t& r0, uint32_t& r1, uint32_t& r2,
                                        uint32_t& r3, uint32_t addr) {
    asm volatile("ldmatrix.sync.aligned.m8n8.x4.shared.b16 {%0,%1,%2,%3}, [%4];"
                 : "=r"(r0), "=r"(r1), "=r"(r2), "=r"(r3) : "r"(addr));
}
__device__ __forceinline__ void mma_bf16(float* d, const uint32_t* a, const uint32_t* b) {
    asm volatile("mma.sync.aligned.m16n8k16.row.col.f32.bf16.bf16.f32 "
                 "{%0,%1,%2,%3}, {%4,%5,%6,%7}, {%8,%9}, {%0,%1,%2,%3};"
                 : "+f"(d[0]), "+f"(d[1]), "+f"(d[2]), "+f"(d[3])
                 : "r"(a[0]), "r"(a[1]), "r"(a[2]), "r"(a[3]), "r"(b[0]), "r"(b[1]));
}
#define SWZ(o) ((o) ^ (((o) >> 3) & 0x70))

// ================= HMMA GEMM: C[M,N] fp32 = A[M,K] @ B[N,K]^T ===================
// bf16x3 split: AhiBhi + AhiBlo + AloBhi, fp32 accum in registers.
// CTA 128x128, 8 warps (4M x 2N), warp tile 32x64, K-chunk 64, dbl-buffered smem.
#define GT_KC 64
#define GT_TILEB (128*128)        // 128 rows x 128 bytes (64 bf16)
#define GT_STAGEB (4*GT_TILEB)    // Ahi, Alo, Bhi, Blo = 64 KB
#define GT_SMEM (2*GT_STAGEB)     // 128 KB

extern __shared__ char gsm[];

__global__ void __launch_bounds__(256) gemm_mma(
        const __nv_bfloat16* __restrict__ Ahi, const __nv_bfloat16* __restrict__ Alo,
        const __nv_bfloat16* __restrict__ Bhi, const __nv_bfloat16* __restrict__ Blo,
        float* __restrict__ C, int N, int K) {
    const int tid = threadIdx.x;
    const int wid = tid >> 5, lane = tid & 31;
    const int wm = wid & 3, wn = wid >> 2;       // 4 M-warps x 2 N-warps
    const int m0 = blockIdx.y * 128, n0 = blockIdx.x * 128;
    const int NIT = K / GT_KC;
    uint32_t sb = smem_to_u32(gsm);

    const int lr = tid >> 3, lc = tid & 7;       // ldg/sts mapping: row, 16B-group

    float acc[2][8][4];
#pragma unroll
    for (int i = 0; i < 2; i++)
#pragma unroll
        for (int j = 0; j < 8; j++)
#pragma unroll
            for (int q = 0; q < 4; q++) acc[i][j][q] = 0.f;

    uint4 buf[16];   // 4 tiles x 4 vectors per thread

    // gmem -> regs for chunk k0 (4 tiles)
    auto ldg_all = [&](int k0) {
        const __nv_bfloat16* srcs[4] = {Ahi, Alo, Bhi, Blo};
        const int r0s[4] = {m0, m0, n0, n0};
#pragma unroll
        for (int tle = 0; tle < 4; tle++) {
#pragma unroll
            for (int i = 0; i < 4; i++) {
                int idx = tid + i * 256;
                int r = idx >> 3, cg = idx & 7;
                buf[tle * 4 + i] = *(const uint4*)(srcs[tle] +
                        (size_t)(r0s[tle] + r) * K + k0 + cg * 8);
            }
        }
    };
    // regs -> smem stage
    auto sts_all = [&](int stage) {
        char* st = gsm + stage * GT_STAGEB;
#pragma unroll
        for (int tle = 0; tle < 4; tle++) {
            char* dst = st + tle * GT_TILEB;
#pragma unroll
            for (int i = 0; i < 4; i++) {
                int idx = tid + i * 256;
                uint32_t off = (uint32_t)((idx >> 3) * 128 + (idx & 7) * 16);
                *(uint4*)(dst + SWZ(off)) = buf[tle * 4 + i];
            }
        }
    };

    ldg_all(0);
    sts_all(0);
    __syncthreads();

    for (int it = 0; it < NIT; it++) {
        if (it + 1 < NIT) ldg_all((it + 1) * GT_KC);

        uint32_t stb = sb + (it & 1) * GT_STAGEB;
        uint32_t smAhi = stb, smAlo = stb + GT_TILEB;
        uint32_t smBhi = stb + 2 * GT_TILEB, smBlo = stb + 3 * GT_TILEB;

#pragma unroll
        for (int ks = 0; ks < 4; ks++) {
            uint32_t colb = (uint32_t)(ks * 32 + (lane >> 4) * 16);
            uint32_t aHi[2][4], aLo[2][4];
#pragma unroll
            for (int mt = 0; mt < 2; mt++) {
                uint32_t off = (uint32_t)((wm * 32 + mt * 16 + (lane & 15)) * 128) + colb;
                uint32_t so = SWZ(off);
                ldsm_x4(aHi[mt][0], aHi[mt][1], aHi[mt][2], aHi[mt][3], smAhi + so);
                ldsm_x4(aLo[mt][0], aLo[mt][1], aLo[mt][2], aLo[mt][3], smAlo + so);
            }
            uint32_t bHi[8][2], bLo[8][2];
#pragma unroll
            for (int nt2 = 0; nt2 < 4; nt2++) {
                uint32_t off = (uint32_t)((wn * 64 + nt2 * 16 + (lane & 15)) * 128) + colb;
                uint32_t so = SWZ(off);
                uint32_t r0, r1, r2, r3;
                ldsm_x4(r0, r1, r2, r3, smBhi + so);
                bHi[2 * nt2][0] = r0; bHi[2 * nt2][1] = r2;
                bHi[2 * nt2 + 1][0] = r1; bHi[2 * nt2 + 1][1] = r3;
                ldsm_x4(r0, r1, r2, r3, smBlo + so);
                bLo[2 * nt2][0] = r0; bLo[2 * nt2][1] = r2;
                bLo[2 * nt2 + 1][0] = r1; bLo[2 * nt2 + 1][1] = r3;
            }
#pragma unroll
            for (int mt = 0; mt < 2; mt++)
#pragma unroll
                for (int nt = 0; nt < 8; nt++) {
                    mma_bf16(acc[mt][nt], aHi[mt], bHi[nt]);
                    mma_bf16(acc[mt][nt], aHi[mt], bLo[nt]);
                    mma_bf16(acc[mt][nt], aLo[mt], bHi[nt]);
                }
        }
        __syncthreads();
        if (it + 1 < NIT) {
            sts_all((it + 1) & 1);
            __syncthreads();
        }
    }

    // epilogue: D fragment -> gmem (float2 per quadrant)
#pragma unroll
    for (int mt = 0; mt < 2; mt++) {
        int row = m0 + wm * 32 + mt * 16 + (lane >> 2);
#pragma unroll
        for (int nt = 0; nt < 8; nt++) {
            int col = n0 + wn * 64 + nt * 8 + 2 * (lane & 3);
            *(float2*)(C + (size_t)row * N + col) =
                make_float2(acc[mt][nt][0], acc[mt][nt][1]);
            *(float2*)(C + (size_t)(row + 8) * N + col) =
                make_float2(acc[mt][nt][2], acc[mt][nt][3]);
        }
    }
}

// =================== fp32 -> bf16 hi/lo split (elementwise) =====================
__global__ void split_kernel(const float* __restrict__ in, __nv_bfloat16* __restrict__ hi,
                             __nv_bfloat16* __restrict__ lo, int n4) {
    int i = blockIdx.x * blockDim.x + threadIdx.x;
    if (i >= n4) return;
    float4 v = ((const float4*)in)[i];
    float vv[4] = {v.x, v.y, v.z, v.w};
    ushort4 uh, ul;
    unsigned short* ph = &uh.x; unsigned short* pl = &ul.x;
#pragma unroll
    for (int j = 0; j < 4; j++) {
        __nv_bfloat16 h = __float2bfloat16(vv[j]);
        __nv_bfloat16 l = __float2bfloat16(vv[j] - __bfloat162float(h));
        ph[j] = __bfloat16_as_ushort(h);
        pl[j] = __bfloat16_as_ushort(l);
    }
    ((ushort4*)hi)[i] = uh;
    ((ushort4*)lo)[i] = ul;
}

// ------------- fused RMSNorm + rotary (position = HEAD index!) ------------------
__global__ void normrope_kernel(const float* __restrict__ in, float* __restrict__ out,
                                int rowstride, int nheads) {
    int w = (blockIdx.x * blockDim.x + threadIdx.x) >> 5;
    int lane = threadIdx.x & 31;
    int total = BB * TT * nheads;
    if (w >= total) return;
    int h = w % nheads;
    int t = (w / nheads) % TT;
    int b = w / (nheads * TT);

    const float* src = in + (size_t)(b * TT + t) * rowstride + h * DH;
    float4 v = *(const float4*)(src + lane * 4);
    float ss = v.x * v.x + v.y * v.y + v.z * v.z + v.w * v.w;
#pragma unroll
    for (int o = 16; o; o >>= 1) ss += __shfl_xor_sync(0xffffffffu, ss, o);
    float scale = rsqrtf(ss * (1.0f / 128.0f) + 1.1920929e-07f);

    float x[4] = {v.x * scale, v.y * scale, v.z * scale, v.w * scale};
    float y[4];
#pragma unroll
    for (int i = 0; i < 4; i++) {
        float part = __shfl_xor_sync(0xffffffffu, x[i], 16);
        int d = lane * 4 + i;
        int j = d & 63;
        float freq = (j < 32) ? powf(1.0f / 1024.0f, (float)j * (1.0f / 31.0f)) : 0.0f;
        float s, c;
        sincosf((float)h * freq, &s, &c);
        if (d < 64) y[i] = x[i] * c + part * s;
        else        y[i] = -part * s + x[i] * c;
    }
    float* dst = out + ((size_t)(b * nheads + h) * TT + t) * DH + lane * 4;
    *(float4*)dst = make_float4(y[0], y[1], y[2], y[3]);
}

// ------------- V transpose ------------------------------------------------------
__global__ void vtrans_kernel(const float* __restrict__ kvlin, float* __restrict__ out) {
    int idx = blockIdx.x * blockDim.x + threadIdx.x;
    const int total = BB * TT * NKV * DH / 4;
    if (idx >= total) return;
    int d4 = idx & (DH / 4 - 1);
    int h = (idx >> 5) & (NKV - 1);
    int t = (idx >> 7) & (TT - 1);
    int b = idx >> 18;
    float4 v = *(const float4*)(kvlin + (size_t)(b * TT + t) * KVC + NKV * DH + h * DH + d4 * 4);
    *(float4*)(out + ((size_t)(b * NKV + h) * TT + t) * DH + d4 * 4) = v;
}

// ------------- flash attention fp32 (unchanged, known good) --------------------
#define FBQ 64
#define FBK 64
#define SSTR 65
#define FLASH_SMEM ((3 * 64 * 128 + 64 * SSTR + 3 * 64) * 4)

extern __shared__ float fsm[];
__global__ void __launch_bounds__(256) flash_kernel(const float* __restrict__ Q,
                                                    const float* __restrict__ K,
                                                    const float* __restrict__ V,
                                                    float* __restrict__ O) {
    float* Qs = fsm;
    float* Ks = Qs + 64 * 128;
    float* Vs = Ks + 64 * 128;
    float* Ss = Vs + 64 * 128;
    float* m_s = Ss + 64 * SSTR;
    float* l_s = m_s + 64;
    float* corr_s = l_s + 64;

    const int tid = threadIdx.x;
    const int qt = blockIdx.x, h = blockIdx.y, b = blockIdx.z;
    const int kvh = h >> 2;

    const float* Qp = Q + ((size_t)(b * NH + h) * TT + qt * FBQ) * DH;
    const float* Kp = K + (size_t)(b * NKV + kvh) * TT * DH;
    const float* Vp = V + (size_t)(b * NKV + kvh) * TT * DH;

#pragma unroll
    for (int it = 0; it < 8; it++) {
        int idx = tid + it * 256;
        int r = idx >> 5, d4 = (idx & 31) * 4;
        *(float4*)&Qs[r * 128 + d4] = *(const float4*)(Qp + r * DH + d4);
    }
    if (tid < 64) { m_s[tid] = -1e30f; l_s[tid] = 0.f; }

    float acc[8][4];
#pragma unroll
    for (int j = 0; j < 8; j++)
#pragma unroll
        for (int jj = 0; jj < 4; jj++) acc[j][jj] = 0.f;

    const int tx = tid & 15, ty = tid >> 4;
    const int vrow = tid >> 2, vc = (tid & 3) * 4;
    const float scl = 0.08838834764831845f;
    const int ntiles = qt + 1;

    for (int kt = 0; kt < ntiles; kt++) {
        __syncthreads();
#pragma unroll
        for (int it = 0; it < 8; it++) {
            int idx = tid + it * 256;
            int r = idx >> 5, d4 = (idx & 31) * 4;
            *(float4*)&Ks[r * 128 + d4] = *(const float4*)(Kp + (kt * FBK + r) * DH + d4);
            *(float4*)&Vs[r * 128 + d4] = *(const float4*)(Vp + (kt * FBK + r) * DH + d4);
        }
        __syncthreads();

        float s[4][4];
#pragma unroll
        for (int i = 0; i < 4; i++)
#pragma unroll
            for (int j = 0; j < 4; j++) s[i][j] = 0.f;
        const int rot = tx * 4;
#pragma unroll 8
        for (int dd = 0; dd < 128; dd += 4) {
            int d = (dd + rot) & 127;
            float4 a0 = *(const float4*)&Qs[(ty * 4 + 0) * 128 + d];
            float4 a1 = *(const float4*)&Qs[(ty * 4 + 1) * 128 + d];
            float4 a2 = *(const float4*)&Qs[(ty * 4 + 2) * 128 + d];
            float4 a3 = *(const float4*)&Qs[(ty * 4 + 3) * 128 + d];
            float4 b0 = *(const float4*)&Ks[(tx * 4 + 0) * 128 + d];
            float4 b1 = *(const float4*)&Ks[(tx * 4 + 1) * 128 + d];
            float4 b2 = *(const float4*)&Ks[(tx * 4 + 2) * 128 + d];
            float4 b3 = *(const float4*)&Ks[(tx * 4 + 3) * 128 + d];
            float4 aa[4] = {a0, a1, a2, a3};
            float4 bb[4] = {b0, b1, b2, b3};
#pragma unroll
            for (int i = 0; i < 4; i++)
#pragma unroll
                for (int j = 0; j < 4; j++)
                    s[i][j] += aa[i].x * bb[j].x + aa[i].y * bb[j].y +
                               aa[i].z * bb[j].z + aa[i].w * bb[j].w;
        }

#pragma unroll
        for (int i = 0; i < 4; i++) {
            int rloc = ty * 4 + i;
            int rg = qt * FBQ + rloc;
            float rowmax = -1e30f;
#pragma unroll
            for (int j = 0; j < 4; j++) {
                int cg = kt * FBK + tx * 4 + j;
                s[i][j] = (cg <= rg) ? s[i][j] * scl : -1e30f;
                rowmax = fmaxf(rowmax, s[i][j]);
            }
#pragma unroll
            for (int o = 8; o; o >>= 1)
                rowmax = fmaxf(rowmax, __shfl_xor_sync(0xffffffffu, rowmax, o));
            float m_old = m_s[rloc];
            float m_new = fmaxf(m_old, rowmax);
            float rs = 0.f;
#pragma unroll
            for (int j = 0; j < 4; j++) {
                float p = __expf(s[i][j] - m_new);
                Ss[rloc * SSTR + tx * 4 + j] = p;
                rs += p;
            }
#pragma unroll
            for (int o = 8; o; o >>= 1) rs += __shfl_xor_sync(0xffffffffu, rs, o);
            if (tx == 0) {
                float cr = __expf(m_old - m_new);
                corr_s[rloc] = cr;
                l_s[rloc] = l_s[rloc] * cr + rs;
                m_s[rloc] = m_new;
            }
        }
        __syncthreads();

        float cr = corr_s[vrow];
#pragma unroll
        for (int j = 0; j < 8; j++)
#pragma unroll
            for (int jj = 0; jj < 4; jj++) acc[j][jj] *= cr;
#pragma unroll 4
        for (int k = 0; k < FBK; k++) {
            float p = Ss[vrow * SSTR + k];
#pragma unroll
            for (int j = 0; j < 8; j++) {
                float4 vv = *(const float4*)&Vs[k * 128 + vc + j * 16];
                acc[j][0] += p * vv.x;
                acc[j][1] += p * vv.y;
                acc[j][2] += p * vv.z;
                acc[j][3] += p * vv.w;
            }
        }
    }

    float linv = 1.0f / l_s[vrow];
    float* Op = O + ((size_t)b * TT + qt * FBQ + vrow) * CC + h * DH;
#pragma unroll
    for (int j = 0; j < 8; j++)
        *(float4*)(Op + vc + j * 16) =
            make_float4(acc[j][0] * linv, acc[j][1] * linv, acc[j][2] * linv, acc[j][3] * linv);
}

// ------------- tail zero --------------------------------------------------------
__global__ void tailzero_kernel(float* out, int start, int total) {
    int i = start + blockIdx.x * blockDim.x + threadIdx.x;
    if (i < total) out[i] = 0.f;
}

// ------------- launcher --------------------------------------------------------
extern "C" void kernel_launch(void* const* d_in, const int* in_sizes, int n_in,
                              void* d_out, int out_size) {
    const float* x     = (const float*)d_in[0];
    const float* Wq    = (const float*)d_in[1];
    const float* Wkv   = (const float*)d_in[2];
    const float* Wproj = (const float*)d_in[3];
    float* out = (float*)d_out;

    float *qlin, *kvlin, *qb, *kb, *vb, *attn;
    __nv_bfloat16 *xhi, *xlo, *wqhi, *wqlo, *wkvhi, *wkvlo, *wphi, *wplo, *ahi, *alo;
    cudaGetSymbolAddress((void**)&qlin, g_qlin);
    cudaGetSymbolAddress((void**)&kvlin, g_kvlin);
    cudaGetSymbolAddress((void**)&qb, g_q);
    cudaGetSymbolAddress((void**)&kb, g_k);
    cudaGetSymbolAddress((void**)&vb, g_v);
    cudaGetSymbolAddress((void**)&attn, g_attn);
    cudaGetSymbolAddress((void**)&xhi, g_xhi);   cudaGetSymbolAddress((void**)&xlo, g_xlo);
    cudaGetSymbolAddress((void**)&wqhi, g_wqhi); cudaGetSymbolAddress((void**)&wqlo, g_wqlo);
    cudaGetSymbolAddress((void**)&wkvhi, g_wkvhi); cudaGetSymbolAddress((void**)&wkvlo, g_wkvlo);
    cudaGetSymbolAddress((void**)&wphi, g_wphi); cudaGetSymbolAddress((void**)&wplo, g_wplo);
    cudaGetSymbolAddress((void**)&ahi, g_ahi);   cudaGetSymbolAddress((void**)&alo, g_alo);

    cudaFuncSetAttribute(gemm_mma, cudaFuncAttributeMaxDynamicSharedMemorySize, GT_SMEM);
    cudaFuncSetAttribute(flash_kernel, cudaFuncAttributeMaxDynamicSharedMemorySize, FLASH_SMEM);

    // 0) split fp32 operands into bf16 hi/lo
    {
        int n4;
        n4 = BT * CC / 4;  split_kernel<<<(n4 + 255) / 256, 256>>>(x, xhi, xlo, n4);
        n4 = CC * CC / 4;  split_kernel<<<(n4 + 255) / 256, 256>>>(Wq, wqhi, wqlo, n4);
        n4 = KVC * CC / 4; split_kernel<<<(n4 + 255) / 256, 256>>>(Wkv, wkvhi, wkvlo, n4);
        n4 = CC * CC / 4;  split_kernel<<<(n4 + 255) / 256, 256>>>(Wproj, wphi, wplo, n4);
    }
    // 1) Q = x @ Wq^T  (HMMA bf16x3)
    {
        dim3 g(CC / 128, BT / 128);
        gemm_mma<<<g, 256, GT_SMEM>>>(xhi, xlo, wqhi, wqlo, qlin, CC, CC);
    }
    // 2) KV = x @ Wkv^T
    {
        dim3 g(KVC / 128, BT / 128);
        gemm_mma<<<g, 256, GT_SMEM>>>(xhi, xlo, wkvhi, wkvlo, kvlin, KVC, CC);
    }
    // 3) RMSNorm + RoPE on Q
    {
        int rows = BB * TT * NH;
        normrope_kernel<<<(rows * 32 + 255) / 256, 256>>>(qlin, qb, CC, NH);
    }
    // 4) RMSNorm + RoPE on K
    {
        int rows = BB * TT * NKV;
        normrope_kernel<<<(rows * 32 + 255) / 256, 256>>>(kvlin, kb, KVC, NKV);
    }
    // 5) V transpose
    {
        int total = BB * TT * NKV * DH / 4;
        vtrans_kernel<<<(total + 255) / 256, 256>>>(kvlin, vb);
    }
    // 6) flash attention -> attn
    {
        dim3 g(TT / FBQ, NH, BB);
        flash_kernel<<<g, 256, FLASH_SMEM>>>(qb, kb, vb, attn);
    }
    // 7) y = attn @ Wproj^T
    {
        int n4 = BT * CC / 4;
        split_kernel<<<(n4 + 255) / 256, 256>>>(attn, ahi, alo, n4);
        dim3 g(CC / 128, BT / 128);
        gemm_mma<<<g, 256, GT_SMEM>>>(ahi, alo, wphi, wplo, out, CC, CC);
    }
    // 8) trailing scalar output
    {
        int btc = BB * TT * CC;
        if (out_size > btc) {
            int rem = out_size - btc;
            tailzero_kernel<<<(rem + 255) / 256, 256>>>(out, btc, out_size);
        }
    }
}

// round 8
// speedup vs baseline: 1.4160x; 1.0426x over previous
#include <cuda_runtime.h>
#include <cuda_bf16.h>
#include <math.h>
#include <stdint.h>

#define BB 2
#define TT 2048
#define CC 2048
#define NH 16
#define NKV 4
#define DH 128
#define BT (BB*TT)          // 4096
#define KVC (2*NKV*DH)      // 1024

// ---------------- scratch (static device globals; no allocation) ----------------
__device__ float g_qlin[BB*TT*CC];
__device__ float g_kvlin[BB*TT*KVC];
__device__ float g_q[BB*NH*TT*DH];
__device__ float g_k[BB*NKV*TT*DH];
__device__ float g_v[BB*NKV*TT*DH];
__device__ float g_attn[BB*TT*CC];
// bf16 hi/lo split operands for tensor-core GEMMs
__device__ __nv_bfloat16 g_xhi[BT*CC],   g_xlo[BT*CC];
__device__ __nv_bfloat16 g_wqhi[CC*CC],  g_wqlo[CC*CC];
__device__ __nv_bfloat16 g_wkvhi[KVC*CC],g_wkvlo[KVC*CC];
__device__ __nv_bfloat16 g_wphi[CC*CC],  g_wplo[CC*CC];
__device__ __nv_bfloat16 g_ahi[BT*CC],   g_alo[BT*CC];

// ======================= warp-MMA helpers (sm_80+ portable) =====================
__device__ __forceinline__ uint32_t smem_to_u32(const void* p) {
    uint32_t a;
    asm("{ .reg .u64 t; cvta.to.shared.u64 t, %1; cvt.u32.u64 %0, t; }" : "=r"(a) : "l"(p));
    return a;
}
__device__ __forceinline__ void ldsm_x4(uint32_t& r0, uint32_t& r1, uint32_t& r2,
                                        uint32_t& r3, uint32_t addr) {
    asm volatile("ldmatrix.sync.aligned.m8n8.x4.shared.b16 {%0,%1,%2,%3}, [%4];"
                 : "=r"(r0), "=r"(r1), "=r"(r2), "=r"(r3) : "r"(addr));
}
__device__ __forceinline__ void mma_bf16(float* d, const uint32_t* a, const uint32_t* b) {
    asm volatile("mma.sync.aligned.m16n8k16.row.col.f32.bf16.bf16.f32 "
                 "{%0,%1,%2,%3}, {%4,%5,%6,%7}, {%8,%9}, {%0,%1,%2,%3};"
                 : "+f"(d[0]), "+f"(d[1]), "+f"(d[2]), "+f"(d[3])
                 : "r"(a[0]), "r"(a[1]), "r"(a[2]), "r"(a[3]), "r"(b[0]), "r"(b[1]));
}
#define SWZ(o) ((o) ^ (((o) >> 3) & 0x70))
#define CP_ASYNC16(dst, src) \
    asm volatile("cp.async.cg.shared.global [%0], [%1], 16;" :: "r"(dst), "l"(src))
#define CP_COMMIT() asm volatile("cp.async.commit_group;" ::: "memory")
#define CP_WAIT(n)  asm volatile("cp.async.wait_group %0;" :: "n"(n) : "memory")

// ================= HMMA GEMM: C[M,N] fp32 = A[M,K] @ B[N,K]^T ===================
// bf16x3 split: AhiBhi + AhiBlo + AloBhi, fp32 accum in registers.
// CTA 128x128, 8 warps (4M x 2N), warp tile 32x64, K-chunk 64.
// cp.async (LDGSTS) double-buffered smem pipeline — no register staging.
#define GT_KC 64
#define GT_TILEB (128*128)        // 128 rows x 128 bytes (64 bf16)
#define GT_STAGEB (4*GT_TILEB)    // Ahi, Alo, Bhi, Blo = 64 KB
#define GT_SMEM (2*GT_STAGEB)     // 128 KB

extern __shared__ char gsm[];

__global__ void __launch_bounds__(256) gemm_mma(
        const __nv_bfloat16* __restrict__ Ahi, const __nv_bfloat16* __restrict__ Alo,
        const __nv_bfloat16* __restrict__ Bhi, const __nv_bfloat16* __restrict__ Blo,
        float* __restrict__ C, int N, int K) {
    const int tid = threadIdx.x;
    const int wid = tid >> 5, lane = tid & 31;
    const int wm = wid & 3, wn = wid >> 2;       // 4 M-warps x 2 N-warps
    const int m0 = blockIdx.y * 128, n0 = blockIdx.x * 128;
    const int NIT = K / GT_KC;
    uint32_t sb = smem_to_u32(gsm);

    float acc[2][8][4];
#pragma unroll
    for (int i = 0; i < 2; i++)
#pragma unroll
        for (int j = 0; j < 8; j++)
#pragma unroll
            for (int q = 0; q < 4; q++) acc[i][j][q] = 0.f;

    // async gmem -> smem stage (4 tiles x 16B per thread x 4 iters = 64 KB total)
    auto cp_stage = [&](int stage, int k0) {
        uint32_t st = sb + stage * GT_STAGEB;
        const __nv_bfloat16* srcs[4] = {Ahi, Alo, Bhi, Blo};
        const int r0s[4] = {m0, m0, n0, n0};
#pragma unroll
        for (int tle = 0; tle < 4; tle++) {
#pragma unroll
            for (int i = 0; i < 4; i++) {
                int idx = tid + i * 256;
                int r = idx >> 3, cg = idx & 7;
                uint32_t off = (uint32_t)(r * 128 + cg * 16);
                CP_ASYNC16(st + tle * GT_TILEB + SWZ(off),
                           srcs[tle] + (size_t)(r0s[tle] + r) * K + k0 + cg * 8);
            }
        }
    };

    cp_stage(0, 0);
    CP_COMMIT();

    for (int it = 0; it < NIT; it++) {
        if (it + 1 < NIT) {
            cp_stage((it + 1) & 1, (it + 1) * GT_KC);
            CP_COMMIT();
            CP_WAIT(1);            // stage `it` resident; stage it+1 in flight
        } else {
            CP_WAIT(0);
        }
        __syncthreads();

        uint32_t stb = sb + (it & 1) * GT_STAGEB;
        uint32_t smAhi = stb, smAlo = stb + GT_TILEB;
        uint32_t smBhi = stb + 2 * GT_TILEB, smBlo = stb + 3 * GT_TILEB;

#pragma unroll
        for (int ks = 0; ks < 4; ks++) {
            uint32_t colb = (uint32_t)(ks * 32 + (lane >> 4) * 16);
            uint32_t aHi[2][4], aLo[2][4];
#pragma unroll
            for (int mt = 0; mt < 2; mt++) {
                uint32_t off = (uint32_t)((wm * 32 + mt * 16 + (lane & 15)) * 128) + colb;
                uint32_t so = SWZ(off);
                ldsm_x4(aHi[mt][0], aHi[mt][1], aHi[mt][2], aHi[mt][3], smAhi + so);
                ldsm_x4(aLo[mt][0], aLo[mt][1], aLo[mt][2], aLo[mt][3], smAlo + so);
            }
            uint32_t bHi[8][2], bLo[8][2];
#pragma unroll
            for (int nt2 = 0; nt2 < 4; nt2++) {
                uint32_t off = (uint32_t)((wn * 64 + nt2 * 16 + (lane & 15)) * 128) + colb;
                uint32_t so = SWZ(off);
                uint32_t r0, r1, r2, r3;
                ldsm_x4(r0, r1, r2, r3, smBhi + so);
                bHi[2 * nt2][0] = r0; bHi[2 * nt2][1] = r2;
                bHi[2 * nt2 + 1][0] = r1; bHi[2 * nt2 + 1][1] = r3;
                ldsm_x4(r0, r1, r2, r3, smBlo + so);
                bLo[2 * nt2][0] = r0; bLo[2 * nt2][1] = r2;
                bLo[2 * nt2 + 1][0] = r1; bLo[2 * nt2 + 1][1] = r3;
            }
#pragma unroll
            for (int mt = 0; mt < 2; mt++)
#pragma unroll
                for (int nt = 0; nt < 8; nt++) {
                    mma_bf16(acc[mt][nt], aHi[mt], bHi[nt]);
                    mma_bf16(acc[mt][nt], aHi[mt], bLo[nt]);
                    mma_bf16(acc[mt][nt], aLo[mt], bHi[nt]);
                }
        }
        __syncthreads();   // compute(it) done before next iter's cp.async reuses buffer
    }

    // epilogue: D fragment -> gmem (float2 per quadrant)
#pragma unroll
    for (int mt = 0; mt < 2; mt++) {
        int row = m0 + wm * 32 + mt * 16 + (lane >> 2);
#pragma unroll
        for (int nt = 0; nt < 8; nt++) {
            int col = n0 + wn * 64 + nt * 8 + 2 * (lane & 3);
            *(float2*)(C + (size_t)row * N + col) =
                make_float2(acc[mt][nt][0], acc[mt][nt][1]);
            *(float2*)(C + (size_t)(row + 8) * N + col) =
                make_float2(acc[mt][nt][2], acc[mt][nt][3]);
        }
    }
}

// =================== fp32 -> bf16 hi/lo split (elementwise) =====================
__global__ void split_kernel(const float* __restrict__ in, __nv_bfloat16* __restrict__ hi,
                             __nv_bfloat16* __restrict__ lo, int n4) {
    int i = blockIdx.x * blockDim.x + threadIdx.x;
    if (i >= n4) return;
    float4 v = ((const float4*)in)[i];
    float vv[4] = {v.x, v.y, v.z, v.w};
    ushort4 uh, ul;
    unsigned short* ph = &uh.x; unsigned short* pl = &ul.x;
#pragma unroll
    for (int j = 0; j < 4; j++) {
        __nv_bfloat16 h = __float2bfloat16(vv[j]);
        __nv_bfloat16 l = __float2bfloat16(vv[j] - __bfloat162float(h));
        ph[j] = __bfloat16_as_ushort(h);
        pl[j] = __bfloat16_as_ushort(l);
    }
    ((ushort4*)hi)[i] = uh;
    ((ushort4*)lo)[i] = ul;
}

// ------------- fused RMSNorm + rotary (position = HEAD index!) ------------------
__global__ void normrope_kernel(const float* __restrict__ in, float* __restrict__ out,
                                int rowstride, int nheads) {
    int w = (blockIdx.x * blockDim.x + threadIdx.x) >> 5;
    int lane = threadIdx.x & 31;
    int total = BB * TT * nheads;
    if (w >= total) return;
    int h = w % nheads;
    int t = (w / nheads) % TT;
    int b = w / (nheads * TT);

    const float* src = in + (size_t)(b * TT + t) * rowstride + h * DH;
    float4 v = *(const float4*)(src + lane * 4);
    float ss = v.x * v.x + v.y * v.y + v.z * v.z + v.w * v.w;
#pragma unroll
    for (int o = 16; o; o >>= 1) ss += __shfl_xor_sync(0xffffffffu, ss, o);
    float scale = rsqrtf(ss * (1.0f / 128.0f) + 1.1920929e-07f);

    float x[4] = {v.x * scale, v.y * scale, v.z * scale, v.w * scale};
    float y[4];
#pragma unroll
    for (int i = 0; i < 4; i++) {
        float part = __shfl_xor_sync(0xffffffffu, x[i], 16);
        int d = lane * 4 + i;
        int j = d & 63;
        float freq = (j < 32) ? powf(1.0f / 1024.0f, (float)j * (1.0f / 31.0f)) : 0.0f;
        float s, c;
        sincosf((float)h * freq, &s, &c);
        if (d < 64) y[i] = x[i] * c + part * s;
        else        y[i] = -part * s + x[i] * c;
    }
    float* dst = out + ((size_t)(b * nheads + h) * TT + t) * DH + lane * 4;
    *(float4*)dst = make_float4(y[0], y[1], y[2], y[3]);
}

// ------------- V transpose ------------------------------------------------------
__global__ void vtrans_kernel(const float* __restrict__ kvlin, float* __restrict__ out) {
    int idx = blockIdx.x * blockDim.x + threadIdx.x;
    const int total = BB * TT * NKV * DH / 4;
    if (idx >= total) return;
    int d4 = idx & (DH / 4 - 1);
    int h = (idx >> 5) & (NKV - 1);
    int t = (idx >> 7) & (TT - 1);
    int b = idx >> 18;
    float4 v = *(const float4*)(kvlin + (size_t)(b * TT + t) * KVC + NKV * DH + h * DH + d4 * 4);
    *(float4*)(out + ((size_t)(b * NKV + h) * TT + t) * DH + d4 * 4) = v;
}

// ------------- flash attention fp32 (unchanged, known good) --------------------
#define FBQ 64
#define FBK 64
#define SSTR 65
#define FLASH_SMEM ((3 * 64 * 128 + 64 * SSTR + 3 * 64) * 4)

extern __shared__ float fsm[];
__global__ void __launch_bounds__(256) flash_kernel(const float* __restrict__ Q,
                                                    const float* __restrict__ K,
                                                    const float* __restrict__ V,
                                                    float* __restrict__ O) {
    float* Qs = fsm;
    float* Ks = Qs + 64 * 128;
    float* Vs = Ks + 64 * 128;
    float* Ss = Vs + 64 * 128;
    float* m_s = Ss + 64 * SSTR;
    float* l_s = m_s + 64;
    float* corr_s = l_s + 64;

    const int tid = threadIdx.x;
    const int qt = blockIdx.x, h = blockIdx.y, b = blockIdx.z;
    const int kvh = h >> 2;

    const float* Qp = Q + ((size_t)(b * NH + h) * TT + qt * FBQ) * DH;
    const float* Kp = K + (size_t)(b * NKV + kvh) * TT * DH;
    const float* Vp = V + (size_t)(b * NKV + kvh) * TT * DH;

#pragma unroll
    for (int it = 0; it < 8; it++) {
        int idx = tid + it * 256;
        int r = idx >> 5, d4 = (idx & 31) * 4;
        *(float4*)&Qs[r * 128 + d4] = *(const float4*)(Qp + r * DH + d4);
    }
    if (tid < 64) { m_s[tid] = -1e30f; l_s[tid] = 0.f; }

    float acc[8][4];
#pragma unroll
    for (int j = 0; j < 8; j++)
#pragma unroll
        for (int jj = 0; jj < 4; jj++) acc[j][jj] = 0.f;

    const int tx = tid & 15, ty = tid >> 4;
    const int vrow = tid >> 2, vc = (tid & 3) * 4;
    const float scl = 0.08838834764831845f;
    const int ntiles = qt + 1;

    for (int kt = 0; kt < ntiles; kt++) {
        __syncthreads();
#pragma unroll
        for (int it = 0; it < 8; it++) {
            int idx = tid + it * 256;
            int r = idx >> 5, d4 = (idx & 31) * 4;
            *(float4*)&Ks[r * 128 + d4] = *(const float4*)(Kp + (kt * FBK + r) * DH + d4);
            *(float4*)&Vs[r * 128 + d4] = *(const float4*)(Vp + (kt * FBK + r) * DH + d4);
        }
        __syncthreads();

        float s[4][4];
#pragma unroll
        for (int i = 0; i < 4; i++)
#pragma unroll
            for (int j = 0; j < 4; j++) s[i][j] = 0.f;
        const int rot = tx * 4;
#pragma unroll 8
        for (int dd = 0; dd < 128; dd += 4) {
            int d = (dd + rot) & 127;
            float4 a0 = *(const float4*)&Qs[(ty * 4 + 0) * 128 + d];
            float4 a1 = *(const float4*)&Qs[(ty * 4 + 1) * 128 + d];
            float4 a2 = *(const float4*)&Qs[(ty * 4 + 2) * 128 + d];
            float4 a3 = *(const float4*)&Qs[(ty * 4 + 3) * 128 + d];
            float4 b0 = *(const float4*)&Ks[(tx * 4 + 0) * 128 + d];
            float4 b1 = *(const float4*)&Ks[(tx * 4 + 1) * 128 + d];
            float4 b2 = *(const float4*)&Ks[(tx * 4 + 2) * 128 + d];
            float4 b3 = *(const float4*)&Ks[(tx * 4 + 3) * 128 + d];
            float4 aa[4] = {a0, a1, a2, a3};
            float4 bb[4] = {b0, b1, b2, b3};
#pragma unroll
            for (int i = 0; i < 4; i++)
#pragma unroll
                for (int j = 0; j < 4; j++)
                    s[i][j] += aa[i].x * bb[j].x + aa[i].y * bb[j].y +
                               aa[i].z * bb[j].z + aa[i].w * bb[j].w;
        }

#pragma unroll
        for (int i = 0; i < 4; i++) {
            int rloc = ty * 4 + i;
            int rg = qt * FBQ + rloc;
            float rowmax = -1e30f;
#pragma unroll
            for (int j = 0; j < 4; j++) {
                int cg = kt * FBK + tx * 4 + j;
                s[i][j] = (cg <= rg) ? s[i][j] * scl : -1e30f;
                rowmax = fmaxf(rowmax, s[i][j]);
            }
#pragma unroll
            for (int o = 8; o; o >>= 1)
                rowmax = fmaxf(rowmax, __shfl_xor_sync(0xffffffffu, rowmax, o));
            float m_old = m_s[rloc];
            float m_new = fmaxf(m_old, rowmax);
            float rs = 0.f;
#pragma unroll
            for (int j = 0; j < 4; j++) {
                float p = __expf(s[i][j] - m_new);
                Ss[rloc * SSTR + tx * 4 + j] = p;
                rs += p;
            }
#pragma unroll
            for (int o = 8; o; o >>= 1) rs += __shfl_xor_sync(0xffffffffu, rs, o);
            if (tx == 0) {
                float cr = __expf(m_old - m_new);
                corr_s[rloc] = cr;
                l_s[rloc] = l_s[rloc] * cr + rs;
                m_s[rloc] = m_new;
            }
        }
        __syncthreads();

        float cr = corr_s[vrow];
#pragma unroll
        for (int j = 0; j < 8; j++)
#pragma unroll
            for (int jj = 0; jj < 4; jj++) acc[j][jj] *= cr;
#pragma unroll 4
        for (int k = 0; k < FBK; k++) {
            float p = Ss[vrow * SSTR + k];
#pragma unroll
            for (int j = 0; j < 8; j++) {
                float4 vv = *(const float4*)&Vs[k * 128 + vc + j * 16];
                acc[j][0] += p * vv.x;
                acc[j][1] += p * vv.y;
                acc[j][2] += p * vv.z;
                acc[j][3] += p * vv.w;
            }
        }
    }

    float linv = 1.0f / l_s[vrow];
    float* Op = O + ((size_t)b * TT + qt * FBQ + vrow) * CC + h * DH;
#pragma unroll
    for (int j = 0; j < 8; j++)
        *(float4*)(Op + vc + j * 16) =
            make_float4(acc[j][0] * linv, acc[j][1] * linv, acc[j][2] * linv, acc[j][3] * linv);
}

// ------------- tail zero --------------------------------------------------------
__global__ void tailzero_kernel(float* out, int start, int total) {
    int i = start + blockIdx.x * blockDim.x + threadIdx.x;
    if (i < total) out[i] = 0.f;
}

// ------------- launcher --------------------------------------------------------
extern "C" void kernel_launch(void* const* d_in, const int* in_sizes, int n_in,
                              void* d_out, int out_size) {
    const float* x     = (const float*)d_in[0];
    const float* Wq    = (const float*)d_in[1];
    const float* Wkv   = (const float*)d_in[2];
    const float* Wproj = (const float*)d_in[3];
    float* out = (float*)d_out;

    float *qlin, *kvlin, *qb, *kb, *vb, *attn;
    __nv_bfloat16 *xhi, *xlo, *wqhi, *wqlo, *wkvhi, *wkvlo, *wphi, *wplo, *ahi, *alo;
    cudaGetSymbolAddress((void**)&qlin, g_qlin);
    cudaGetSymbolAddress((void**)&kvlin, g_kvlin);
    cudaGetSymbolAddress((void**)&qb, g_q);
    cudaGetSymbolAddress((void**)&kb, g_k);
    cudaGetSymbolAddress((void**)&vb, g_v);
    cudaGetSymbolAddress((void**)&attn, g_attn);
    cudaGetSymbolAddress((void**)&xhi, g_xhi);   cudaGetSymbolAddress((void**)&xlo, g_xlo);
    cudaGetSymbolAddress((void**)&wqhi, g_wqhi); cudaGetSymbolAddress((void**)&wqlo, g_wqlo);
    cudaGetSymbolAddress((void**)&wkvhi, g_wkvhi); cudaGetSymbolAddress((void**)&wkvlo, g_wkvlo);
    cudaGetSymbolAddress((void**)&wphi, g_wphi); cudaGetSymbolAddress((void**)&wplo, g_wplo);
    cudaGetSymbolAddress((void**)&ahi, g_ahi);   cudaGetSymbolAddress((void**)&alo, g_alo);

    cudaFuncSetAttribute(gemm_mma, cudaFuncAttributeMaxDynamicSharedMemorySize, GT_SMEM);
    cudaFuncSetAttribute(flash_kernel, cudaFuncAttributeMaxDynamicSharedMemorySize, FLASH_SMEM);

    // 0) split fp32 operands into bf16 hi/lo
    {
        int n4;
        n4 = BT * CC / 4;  split_kernel<<<(n4 + 255) / 256, 256>>>(x, xhi, xlo, n4);
        n4 = CC * CC / 4;  split_kernel<<<(n4 + 255) / 256, 256>>>(Wq, wqhi, wqlo, n4);
        n4 = KVC * CC / 4; split_kernel<<<(n4 + 255) / 256, 256>>>(Wkv, wkvhi, wkvlo, n4);
        n4 = CC * CC / 4;  split_kernel<<<(n4 + 255) / 256, 256>>>(Wproj, wphi, wplo, n4);
    }
    // 1) Q = x @ Wq^T  (HMMA bf16x3, cp.async pipeline)
    {
        dim3 g(CC / 128, BT / 128);
        gemm_mma<<<g, 256, GT_SMEM>>>(xhi, xlo, wqhi, wqlo, qlin, CC, CC);
    }
    // 2) KV = x @ Wkv^T
    {
        dim3 g(KVC / 128, BT / 128);
        gemm_mma<<<g, 256, GT_SMEM>>>(xhi, xlo, wkvhi, wkvlo, kvlin, KVC, CC);
    }
    // 3) RMSNorm + RoPE on Q
    {
        int rows = BB * TT * NH;
        normrope_kernel<<<(rows * 32 + 255) / 256, 256>>>(qlin, qb, CC, NH);
    }
    // 4) RMSNorm + RoPE on K
    {
        int rows = BB * TT * NKV;
        normrope_kernel<<<(rows * 32 + 255) / 256, 256>>>(kvlin, kb, KVC, NKV);
    }
    // 5) V transpose
    {
        int total = BB * TT * NKV * DH / 4;
        vtrans_kernel<<<(total + 255) / 256, 256>>>(kvlin, vb);
    }
    // 6) flash attention -> attn
    {
        dim3 g(TT / FBQ, NH, BB);
        flash_kernel<<<g, 256, FLASH_SMEM>>>(qb, kb, vb, attn);
    }
    // 7) y = attn @ Wproj^T
    {
        int n4 = BT * CC / 4;
        split_kernel<<<(n4 + 255) / 256, 256>>>(attn, ahi, alo, n4);
        dim3 g(CC / 128, BT / 128);
        gemm_mma<<<g, 256, GT_SMEM>>>(ahi, alo, wphi, wplo, out, CC, CC);
    }
    // 8) trailing scalar output
    {
        int btc = BB * TT * CC;
        if (out_size > btc) {
            int rem = out_size - btc;
            tailzero_kernel<<<(rem + 255) / 256, 256>>>(out, btc, out_size);
        }
    }
}

// round 9
// speedup vs baseline: 3.1940x; 2.2556x over previous
#include <cuda_runtime.h>
#include <cuda_bf16.h>
#include <math.h>
#include <stdint.h>

#define BB 2
#define TT 2048
#define CC 2048
#define NH 16
#define NKV 4
#define DH 128
#define BT (BB*TT)          // 4096
#define KVC (2*NKV*DH)      // 1024

// ---------------- scratch (static device globals; no allocation) ----------------
__device__ float g_qlin[BB*TT*CC];
__device__ float g_kvlin[BB*TT*KVC];
__device__ __nv_bfloat16 g_qhi[BB*NH*TT*DH],  g_qlo[BB*NH*TT*DH];
__device__ __nv_bfloat16 g_khi[BB*NKV*TT*DH], g_klo[BB*NKV*TT*DH];
__device__ __nv_bfloat16 g_vhi[BB*NKV*TT*DH], g_vlo[BB*NKV*TT*DH];
__device__ __nv_bfloat16 g_xhi[BT*CC],   g_xlo[BT*CC];
__device__ __nv_bfloat16 g_wqhi[CC*CC],  g_wqlo[CC*CC];
__device__ __nv_bfloat16 g_wkvhi[KVC*CC],g_wkvlo[KVC*CC];
__device__ __nv_bfloat16 g_wphi[CC*CC],  g_wplo[CC*CC];
__device__ __nv_bfloat16 g_ahi[BT*CC],   g_alo[BT*CC];

// ======================= warp-MMA helpers (sm_80+ portable) =====================
__device__ __forceinline__ uint32_t smem_to_u32(const void* p) {
    uint32_t a;
    asm("{ .reg .u64 t; cvta.to.shared.u64 t, %1; cvt.u32.u64 %0, t; }" : "=r"(a) : "l"(p));
    return a;
}
__device__ __forceinline__ void ldsm_x4(uint32_t& r0, uint32_t& r1, uint32_t& r2,
                                        uint32_t& r3, uint32_t addr) {
    asm volatile("ldmatrix.sync.aligned.m8n8.x4.shared.b16 {%0,%1,%2,%3}, [%4];"
                 : "=r"(r0), "=r"(r1), "=r"(r2), "=r"(r3) : "r"(addr));
}
__device__ __forceinline__ void ldsm_x4_t(uint32_t& r0, uint32_t& r1, uint32_t& r2,
                                          uint32_t& r3, uint32_t addr) {
    asm volatile("ldmatrix.sync.aligned.m8n8.x4.trans.shared.b16 {%0,%1,%2,%3}, [%4];"
                 : "=r"(r0), "=r"(r1), "=r"(r2), "=r"(r3) : "r"(addr));
}
__device__ __forceinline__ void mma_bf16(float* d, const uint32_t* a, const uint32_t* b) {
    asm volatile("mma.sync.aligned.m16n8k16.row.col.f32.bf16.bf16.f32 "
                 "{%0,%1,%2,%3}, {%4,%5,%6,%7}, {%8,%9}, {%0,%1,%2,%3};"
                 : "+f"(d[0]), "+f"(d[1]), "+f"(d[2]), "+f"(d[3])
                 : "r"(a[0]), "r"(a[1]), "r"(a[2]), "r"(a[3]), "r"(b[0]), "r"(b[1]));
}
__device__ __forceinline__ uint32_t packbf2(float x, float y) {
    __nv_bfloat162 t = __floats2bfloat162_rn(x, y);
    return *(uint32_t*)&t;
}
#define SWZ(o) ((o) ^ (((o) >> 3) & 0x70))
#define CP_ASYNC16(dst, src) \
    asm volatile("cp.async.cg.shared.global [%0], [%1], 16;" :: "r"(dst), "l"(src))
#define CP_COMMIT() asm volatile("cp.async.commit_group;" ::: "memory")
#define CP_WAIT(n)  asm volatile("cp.async.wait_group %0;" :: "n"(n) : "memory")

// ================= HMMA GEMM: C[M,N] fp32 = A[M,K] @ B[N,K]^T ===================
#define GT_KC 64
#define GT_TILEB (128*128)
#define GT_STAGEB (4*GT_TILEB)
#define GT_SMEM (2*GT_STAGEB)     // 128 KB

extern __shared__ char gsm[];

__global__ void __launch_bounds__(256) gemm_mma(
        const __nv_bfloat16* __restrict__ Ahi, const __nv_bfloat16* __restrict__ Alo,
        const __nv_bfloat16* __restrict__ Bhi, const __nv_bfloat16* __restrict__ Blo,
        float* __restrict__ C, int N, int K) {
    const int tid = threadIdx.x;
    const int wid = tid >> 5, lane = tid & 31;
    const int wm = wid & 3, wn = wid >> 2;
    const int m0 = blockIdx.y * 128, n0 = blockIdx.x * 128;
    const int NIT = K / GT_KC;
    uint32_t sb = smem_to_u32(gsm);

    float acc[2][8][4];
#pragma unroll
    for (int i = 0; i < 2; i++)
#pragma unroll
        for (int j = 0; j < 8; j++)
#pragma unroll
            for (int q = 0; q < 4; q++) acc[i][j][q] = 0.f;

    auto cp_stage = [&](int stage, int k0) {
        uint32_t st = sb + stage * GT_STAGEB;
        const __nv_bfloat16* srcs[4] = {Ahi, Alo, Bhi, Blo};
        const int r0s[4] = {m0, m0, n0, n0};
#pragma unroll
        for (int tle = 0; tle < 4; tle++) {
#pragma unroll
            for (int i = 0; i < 4; i++) {
                int idx = tid + i * 256;
                int r = idx >> 3, cg = idx & 7;
                uint32_t off = (uint32_t)(r * 128 + cg * 16);
                CP_ASYNC16(st + tle * GT_TILEB + SWZ(off),
                           srcs[tle] + (size_t)(r0s[tle] + r) * K + k0 + cg * 8);
            }
        }
    };

    cp_stage(0, 0);
    CP_COMMIT();

    for (int it = 0; it < NIT; it++) {
        if (it + 1 < NIT) {
            cp_stage((it + 1) & 1, (it + 1) * GT_KC);
            CP_COMMIT();
            CP_WAIT(1);
        } else {
            CP_WAIT(0);
        }
        __syncthreads();

        uint32_t stb = sb + (it & 1) * GT_STAGEB;
        uint32_t smAhi = stb, smAlo = stb + GT_TILEB;
        uint32_t smBhi = stb + 2 * GT_TILEB, smBlo = stb + 3 * GT_TILEB;

#pragma unroll
        for (int ks = 0; ks < 4; ks++) {
            uint32_t colb = (uint32_t)(ks * 32 + (lane >> 4) * 16);
            uint32_t aHi[2][4], aLo[2][4];
#pragma unroll
            for (int mt = 0; mt < 2; mt++) {
                uint32_t off = (uint32_t)((wm * 32 + mt * 16 + (lane & 15)) * 128) + colb;
                uint32_t so = SWZ(off);
                ldsm_x4(aHi[mt][0], aHi[mt][1], aHi[mt][2], aHi[mt][3], smAhi + so);
                ldsm_x4(aLo[mt][0], aLo[mt][1], aLo[mt][2], aLo[mt][3], smAlo + so);
            }
            uint32_t bHi[8][2], bLo[8][2];
#pragma unroll
            for (int nt2 = 0; nt2 < 4; nt2++) {
                uint32_t off = (uint32_t)((wn * 64 + nt2 * 16 + (lane & 15)) * 128) + colb;
                uint32_t so = SWZ(off);
                uint32_t r0, r1, r2, r3;
                ldsm_x4(r0, r1, r2, r3, smBhi + so);
                bHi[2 * nt2][0] = r0; bHi[2 * nt2][1] = r2;
                bHi[2 * nt2 + 1][0] = r1; bHi[2 * nt2 + 1][1] = r3;
                ldsm_x4(r0, r1, r2, r3, smBlo + so);
                bLo[2 * nt2][0] = r0; bLo[2 * nt2][1] = r2;
                bLo[2 * nt2 + 1][0] = r1; bLo[2 * nt2 + 1][1] = r3;
            }
#pragma unroll
            for (int mt = 0; mt < 2; mt++)
#pragma unroll
                for (int nt = 0; nt < 8; nt++) {
                    mma_bf16(acc[mt][nt], aHi[mt], bHi[nt]);
                    mma_bf16(acc[mt][nt], aHi[mt], bLo[nt]);
                    mma_bf16(acc[mt][nt], aLo[mt], bHi[nt]);
                }
        }
        __syncthreads();
    }

#pragma unroll
    for (int mt = 0; mt < 2; mt++) {
        int row = m0 + wm * 32 + mt * 16 + (lane >> 2);
#pragma unroll
        for (int nt = 0; nt < 8; nt++) {
            int col = n0 + wn * 64 + nt * 8 + 2 * (lane & 3);
            *(float2*)(C + (size_t)row * N + col) =
                make_float2(acc[mt][nt][0], acc[mt][nt][1]);
            *(float2*)(C + (size_t)(row + 8) * N + col) =
                make_float2(acc[mt][nt][2], acc[mt][nt][3]);
        }
    }
}

// =================== fp32 -> bf16 hi/lo split (elementwise) =====================
__global__ void split_kernel(const float* __restrict__ in, __nv_bfloat16* __restrict__ hi,
                             __nv_bfloat16* __restrict__ lo, int n4) {
    int i = blockIdx.x * blockDim.x + threadIdx.x;
    if (i >= n4) return;
    float4 v = ((const float4*)in)[i];
    float vv[4] = {v.x, v.y, v.z, v.w};
    ushort4 uh, ul;
    unsigned short* ph = &uh.x; unsigned short* pl = &ul.x;
#pragma unroll
    for (int j = 0; j < 4; j++) {
        __nv_bfloat16 h = __float2bfloat16(vv[j]);
        __nv_bfloat16 l = __float2bfloat16(vv[j] - __bfloat162float(h));
        ph[j] = __bfloat16_as_ushort(h);
        pl[j] = __bfloat16_as_ushort(l);
    }
    ((ushort4*)hi)[i] = uh;
    ((ushort4*)lo)[i] = ul;
}

// ------------- fused RMSNorm + rotary -> bf16 hi/lo (position = HEAD index) -----
__global__ void normrope_kernel(const float* __restrict__ in,
                                __nv_bfloat16* __restrict__ ohi,
                                __nv_bfloat16* __restrict__ olo,
                                int rowstride, int nheads) {
    int w = (blockIdx.x * blockDim.x + threadIdx.x) >> 5;
    int lane = threadIdx.x & 31;
    int total = BB * TT * nheads;
    if (w >= total) return;
    int h = w % nheads;
    int t = (w / nheads) % TT;
    int b = w / (nheads * TT);

    const float* src = in + (size_t)(b * TT + t) * rowstride + h * DH;
    float4 v = *(const float4*)(src + lane * 4);
    float ss = v.x * v.x + v.y * v.y + v.z * v.z + v.w * v.w;
#pragma unroll
    for (int o = 16; o; o >>= 1) ss += __shfl_xor_sync(0xffffffffu, ss, o);
    float scale = rsqrtf(ss * (1.0f / 128.0f) + 1.1920929e-07f);

    float x[4] = {v.x * scale, v.y * scale, v.z * scale, v.w * scale};
    float y[4];
#pragma unroll
    for (int i = 0; i < 4; i++) {
        float part = __shfl_xor_sync(0xffffffffu, x[i], 16);
        int d = lane * 4 + i;
        int j = d & 63;
        float freq = (j < 32) ? powf(1.0f / 1024.0f, (float)j * (1.0f / 31.0f)) : 0.0f;
        float s, c;
        sincosf((float)h * freq, &s, &c);
        if (d < 64) y[i] = x[i] * c + part * s;
        else        y[i] = -part * s + x[i] * c;
    }
    size_t off = ((size_t)(b * nheads + h) * TT + t) * DH + lane * 4;
    ushort4 uh, ul;
    unsigned short* ph = &uh.x; unsigned short* pl = &ul.x;
#pragma unroll
    for (int i = 0; i < 4; i++) {
        __nv_bfloat16 hh = __float2bfloat16(y[i]);
        __nv_bfloat16 ll = __float2bfloat16(y[i] - __bfloat162float(hh));
        ph[i] = __bfloat16_as_ushort(hh);
        pl[i] = __bfloat16_as_ushort(ll);
    }
    *(ushort4*)(ohi + off) = uh;
    *(ushort4*)(olo + off) = ul;
}

// ------------- V transpose + bf16 hi/lo split -----------------------------------
__global__ void vtrans_kernel(const float* __restrict__ kvlin,
                              __nv_bfloat16* __restrict__ vhi,
                              __nv_bfloat16* __restrict__ vlo) {
    int idx = blockIdx.x * blockDim.x + threadIdx.x;
    const int total = BB * TT * NKV * DH / 4;
    if (idx >= total) return;
    int d4 = idx & (DH / 4 - 1);
    int h = (idx >> 5) & (NKV - 1);
    int t = (idx >> 7) & (TT - 1);
    int b = idx >> 18;
    float4 v = *(const float4*)(kvlin + (size_t)(b * TT + t) * KVC + NKV * DH + h * DH + d4 * 4);
    float vv[4] = {v.x, v.y, v.z, v.w};
    ushort4 uh, ul;
    unsigned short* ph = &uh.x; unsigned short* pl = &ul.x;
#pragma unroll
    for (int j = 0; j < 4; j++) {
        __nv_bfloat16 hh = __float2bfloat16(vv[j]);
        __nv_bfloat16 ll = __float2bfloat16(vv[j] - __bfloat162float(hh));
        ph[j] = __bfloat16_as_ushort(hh);
        pl[j] = __bfloat16_as_ushort(ll);
    }
    size_t off = ((size_t)(b * NKV + h) * TT + t) * DH + d4 * 4;
    *(ushort4*)(vhi + off) = uh;
    *(ushort4*)(vlo + off) = ul;
}

// ================= HMMA flash attention: 128q x 64k, 8 warps ====================
// smem: Q hi/lo resident (64KB), K/V hi/lo double-buffered (2x64KB) = 192KB.
// Each tile stored as [2 dh-halves][rows][64 bf16] with SW128 swizzle per half.
#define FQ 128
#define FK 64
#define FHALF_Q 16384
#define FHALF_KV 8192
#define FSM_QH 0
#define FSM_QL 32768
#define FSM_KV0 65536
#define FSTAGE 65536
#define FLASH_SMEM 196608

__global__ void __launch_bounds__(256) flash_hmma(
        const __nv_bfloat16* __restrict__ qhi, const __nv_bfloat16* __restrict__ qlo,
        const __nv_bfloat16* __restrict__ khi, const __nv_bfloat16* __restrict__ klo,
        const __nv_bfloat16* __restrict__ vhi, const __nv_bfloat16* __restrict__ vlo,
        __nv_bfloat16* __restrict__ ahi, __nv_bfloat16* __restrict__ alo) {
    const int tid = threadIdx.x, wid = tid >> 5, lane = tid & 31;
    const int qt = blockIdx.x, h = blockIdx.y, b = blockIdx.z;
    const int kvh = h >> 2;
    uint32_t sb = smem_to_u32(gsm);

    const __nv_bfloat16* Qh_g = qhi + ((size_t)(b * NH + h) * TT + qt * FQ) * DH;
    const __nv_bfloat16* Ql_g = qlo + ((size_t)(b * NH + h) * TT + qt * FQ) * DH;
    const __nv_bfloat16* Kh_g = khi + (size_t)(b * NKV + kvh) * TT * DH;
    const __nv_bfloat16* Kl_g = klo + (size_t)(b * NKV + kvh) * TT * DH;
    const __nv_bfloat16* Vh_g = vhi + (size_t)(b * NKV + kvh) * TT * DH;
    const __nv_bfloat16* Vl_g = vlo + (size_t)(b * NKV + kvh) * TT * DH;

    // Q hi/lo -> smem (64KB)
    {
        const __nv_bfloat16* srcs[2] = {Qh_g, Ql_g};
        const uint32_t dsts[2] = {FSM_QH, FSM_QL};
#pragma unroll
        for (int a = 0; a < 2; a++)
#pragma unroll
            for (int i = 0; i < 8; i++) {
                int idx = tid + i * 256;                     // 0..2047
                int hf = idx >> 10, r = (idx >> 3) & 127, cg = idx & 7;
                CP_ASYNC16(sb + dsts[a] + hf * FHALF_Q + SWZ((uint32_t)(r * 128 + cg * 16)),
                           srcs[a] + (size_t)r * DH + hf * 64 + cg * 8);
            }
    }
    auto cp_kv = [&](int stage, int kt2) {
        uint32_t dstb = sb + FSM_KV0 + stage * FSTAGE;
        const __nv_bfloat16* srcs[4] = {Kh_g, Kl_g, Vh_g, Vl_g};
#pragma unroll
        for (int a = 0; a < 4; a++) {
            const __nv_bfloat16* src = srcs[a] + (size_t)kt2 * FK * DH;
#pragma unroll
            for (int i = 0; i < 4; i++) {
                int idx = tid + i * 256;                     // 0..1023
                int hf = idx >> 9, r = (idx >> 3) & 63, cg = idx & 7;
                CP_ASYNC16(dstb + a * 16384 + hf * FHALF_KV + SWZ((uint32_t)(r * 128 + cg * 16)),
                           src + (size_t)r * DH + hf * 64 + cg * 8);
            }
        }
    };
    cp_kv(0, 0);
    CP_COMMIT();

    const int ntiles = 2 * qt + 2;
    const int grow_lo = qt * FQ + wid * 16 + (lane >> 2);    // +8 for hi rows
    const float scl = 0.08838834764831845f;                   // 1/sqrt(128)

    float m_lo = -1e30f, m_hi = -1e30f, l_lo = 0.f, l_hi = 0.f;
    float o[16][4];
#pragma unroll
    for (int n = 0; n < 16; n++)
#pragma unroll
        for (int q = 0; q < 4; q++) o[n][q] = 0.f;

    for (int kt = 0; kt < ntiles; kt++) {
        if (kt + 1 < ntiles) { cp_kv((kt + 1) & 1, kt + 1); CP_COMMIT(); CP_WAIT(1); }
        else CP_WAIT(0);
        __syncthreads();
        uint32_t kvb = sb + FSM_KV0 + (kt & 1) * FSTAGE;
        uint32_t smKh = kvb, smKl = kvb + 16384, smVh = kvb + 32768, smVl = kvb + 49152;

        // ---- S = Q K^T (bf16x3) ----
        float s[8][4];
#pragma unroll
        for (int n = 0; n < 8; n++)
#pragma unroll
            for (int q = 0; q < 4; q++) s[n][q] = 0.f;
#pragma unroll
        for (int ks = 0; ks < 8; ks++) {
            int hf = ks >> 2;
            uint32_t colb = (uint32_t)((ks & 3) * 32 + (lane >> 4) * 16);
            uint32_t aoff = SWZ((uint32_t)((wid * 16 + (lane & 15)) * 128) + colb);
            uint32_t aHi[4], aLo[4];
            ldsm_x4(aHi[0], aHi[1], aHi[2], aHi[3], sb + FSM_QH + hf * FHALF_Q + aoff);
            ldsm_x4(aLo[0], aLo[1], aLo[2], aLo[3], sb + FSM_QL + hf * FHALF_Q + aoff);
#pragma unroll
            for (int nt2 = 0; nt2 < 4; nt2++) {
                uint32_t boff = hf * FHALF_KV +
                    SWZ((uint32_t)((nt2 * 16 + (lane & 15)) * 128) + colb);
                uint32_t r0, r1, r2, r3;
                uint32_t bh0[2], bh1[2], bl0[2], bl1[2];
                ldsm_x4(r0, r1, r2, r3, smKh + boff);
                bh0[0] = r0; bh0[1] = r2; bh1[0] = r1; bh1[1] = r3;
                ldsm_x4(r0, r1, r2, r3, smKl + boff);
                bl0[0] = r0; bl0[1] = r2; bl1[0] = r1; bl1[1] = r3;
                mma_bf16(s[2 * nt2], aHi, bh0);
                mma_bf16(s[2 * nt2], aHi, bl0);
                mma_bf16(s[2 * nt2], aLo, bh0);
                mma_bf16(s[2 * nt2 + 1], aHi, bh1);
                mma_bf16(s[2 * nt2 + 1], aHi, bl1);
                mma_bf16(s[2 * nt2 + 1], aLo, bh1);
            }
        }

        // ---- mask + online softmax (rows owned by quads) ----
        float mx_lo = -1e30f, mx_hi = -1e30f;
#pragma unroll
        for (int nt = 0; nt < 8; nt++)
#pragma unroll
            for (int j = 0; j < 2; j++) {
                int gc = kt * FK + nt * 8 + (lane & 3) * 2 + j;
                s[nt][j]     = (gc <= grow_lo)     ? s[nt][j] * scl     : -1e30f;
                s[nt][j + 2] = (gc <= grow_lo + 8) ? s[nt][j + 2] * scl : -1e30f;
                mx_lo = fmaxf(mx_lo, s[nt][j]);
                mx_hi = fmaxf(mx_hi, s[nt][j + 2]);
            }
        mx_lo = fmaxf(mx_lo, __shfl_xor_sync(0xffffffffu, mx_lo, 1));
        mx_lo = fmaxf(mx_lo, __shfl_xor_sync(0xffffffffu, mx_lo, 2));
        mx_hi = fmaxf(mx_hi, __shfl_xor_sync(0xffffffffu, mx_hi, 1));
        mx_hi = fmaxf(mx_hi, __shfl_xor_sync(0xffffffffu, mx_hi, 2));
        float mn_lo = fmaxf(m_lo, mx_lo), mn_hi = fmaxf(m_hi, mx_hi);
        float cr_lo = __expf(m_lo - mn_lo), cr_hi = __expf(m_hi - mn_hi);
        m_lo = mn_lo; m_hi = mn_hi;
        float rs_lo = 0.f, rs_hi = 0.f;
#pragma unroll
        for (int nt = 0; nt < 8; nt++)
#pragma unroll
            for (int j = 0; j < 2; j++) {
                s[nt][j] = __expf(s[nt][j] - mn_lo);
                s[nt][j + 2] = __expf(s[nt][j + 2] - mn_hi);
                rs_lo += s[nt][j];
                rs_hi += s[nt][j + 2];
            }
        rs_lo += __shfl_xor_sync(0xffffffffu, rs_lo, 1);
        rs_lo += __shfl_xor_sync(0xffffffffu, rs_lo, 2);
        rs_hi += __shfl_xor_sync(0xffffffffu, rs_hi, 1);
        rs_hi += __shfl_xor_sync(0xffffffffu, rs_hi, 2);
        l_lo = l_lo * cr_lo + rs_lo;
        l_hi = l_hi * cr_hi + rs_hi;
#pragma unroll
        for (int n = 0; n < 16; n++) {
            o[n][0] *= cr_lo; o[n][1] *= cr_lo;
            o[n][2] *= cr_hi; o[n][3] *= cr_hi;
        }

        // ---- P C-frags -> A-frags (hi/lo) ----
        uint32_t aPh[4][4], aPl[4][4];
#pragma unroll
        for (int kc = 0; kc < 4; kc++) {
            float* c0 = s[2 * kc];
            float* c1 = s[2 * kc + 1];
            float v00 = c0[0], v01 = c0[1], v02 = c0[2], v03 = c0[3];
            float v10 = c1[0], v11 = c1[1], v12 = c1[2], v13 = c1[3];
            uint32_t h00 = packbf2(v00, v01);
            uint32_t h01 = packbf2(v02, v03);
            uint32_t h10 = packbf2(v10, v11);
            uint32_t h11 = packbf2(v12, v13);
            aPh[kc][0] = h00; aPh[kc][1] = h01; aPh[kc][2] = h10; aPh[kc][3] = h11;
            __nv_bfloat162 t;
            t = *(__nv_bfloat162*)&h00;
            aPl[kc][0] = packbf2(v00 - __bfloat162float(t.x), v01 - __bfloat162float(t.y));
            t = *(__nv_bfloat162*)&h01;
            aPl[kc][1] = packbf2(v02 - __bfloat162float(t.x), v03 - __bfloat162float(t.y));
            t = *(__nv_bfloat162*)&h10;
            aPl[kc][2] = packbf2(v10 - __bfloat162float(t.x), v11 - __bfloat162float(t.y));
            t = *(__nv_bfloat162*)&h11;
            aPl[kc][3] = packbf2(v12 - __bfloat162float(t.x), v13 - __bfloat162float(t.y));
        }

        // ---- O += P V (bf16x3), V B-frags via ldmatrix.trans ----
#pragma unroll
        for (int kc = 0; kc < 4; kc++) {
#pragma unroll
            for (int hf = 0; hf < 2; hf++)
#pragma unroll
                for (int dt = 0; dt < 4; dt++) {
                    uint32_t voff = hf * FHALF_KV +
                        SWZ((uint32_t)((kc * 16 + (lane & 15)) * 128 +
                                       dt * 32 + (lane >> 4) * 16));
                    uint32_t r0, r1, r2, r3;
                    uint32_t bh0[2], bh1[2], bl0[2], bl1[2];
                    ldsm_x4_t(r0, r1, r2, r3, smVh + voff);
                    bh0[0] = r0; bh0[1] = r1; bh1[0] = r2; bh1[1] = r3;
                    ldsm_x4_t(r0, r1, r2, r3, smVl + voff);
                    bl0[0] = r0; bl0[1] = r1; bl1[0] = r2; bl1[1] = r3;
                    int n = hf * 8 + dt * 2;
                    mma_bf16(o[n], aPh[kc], bh0);
                    mma_bf16(o[n], aPh[kc], bl0);
                    mma_bf16(o[n], aPl[kc], bh0);
                    mma_bf16(o[n + 1], aPh[kc], bh1);
                    mma_bf16(o[n + 1], aPh[kc], bl1);
                    mma_bf16(o[n + 1], aPl[kc], bh1);
                }
        }
        __syncthreads();
    }

    // ---- epilogue: normalize, split to bf16 hi/lo, write ahi/alo ----
    float li_lo = 1.0f / l_lo, li_hi = 1.0f / l_hi;
    int t_lo = qt * FQ + wid * 16 + (lane >> 2);
    size_t base_lo = ((size_t)b * TT + t_lo) * CC + h * DH;
    size_t base_hi = base_lo + (size_t)8 * CC;
#pragma unroll
    for (int n = 0; n < 16; n++) {
        int d = n * 8 + (lane & 3) * 2;
        float v0 = o[n][0] * li_lo, v1 = o[n][1] * li_lo;
        float v2 = o[n][2] * li_hi, v3 = o[n][3] * li_hi;
        uint32_t h01 = packbf2(v0, v1);
        __nv_bfloat162 t = *(__nv_bfloat162*)&h01;
        uint32_t l01 = packbf2(v0 - __bfloat162float(t.x), v1 - __bfloat162float(t.y));
        uint32_t h23 = packbf2(v2, v3);
        t = *(__nv_bfloat162*)&h23;
        uint32_t l23 = packbf2(v2 - __bfloat162float(t.x), v3 - __bfloat162float(t.y));
        *(uint32_t*)(ahi + base_lo + d) = h01;
        *(uint32_t*)(alo + base_lo + d) = l01;
        *(uint32_t*)(ahi + base_hi + d) = h23;
        *(uint32_t*)(alo + base_hi + d) = l23;
    }
}

// ------------- tail zero --------------------------------------------------------
__global__ void tailzero_kernel(float* out, int start, int total) {
    int i = start + blockIdx.x * blockDim.x + threadIdx.x;
    if (i < total) out[i] = 0.f;
}

// ------------- launcher --------------------------------------------------------
extern "C" void kernel_launch(void* const* d_in, const int* in_sizes, int n_in,
                              void* d_out, int out_size) {
    const float* x     = (const float*)d_in[0];
    const float* Wq    = (const float*)d_in[1];
    const float* Wkv   = (const float*)d_in[2];
    const float* Wproj = (const float*)d_in[3];
    float* out = (float*)d_out;

    float *qlin, *kvlin;
    __nv_bfloat16 *qhi, *qlo, *khi, *klo, *vhi, *vlo;
    __nv_bfloat16 *xhi, *xlo, *wqhi, *wqlo, *wkvhi, *wkvlo, *wphi, *wplo, *ahi, *alo;
    cudaGetSymbolAddress((void**)&qlin, g_qlin);
    cudaGetSymbolAddress((void**)&kvlin, g_kvlin);
    cudaGetSymbolAddress((void**)&qhi, g_qhi);   cudaGetSymbolAddress((void**)&qlo, g_qlo);
    cudaGetSymbolAddress((void**)&khi, g_khi);   cudaGetSymbolAddress((void**)&klo, g_klo);
    cudaGetSymbolAddress((void**)&vhi, g_vhi);   cudaGetSymbolAddress((void**)&vlo, g_vlo);
    cudaGetSymbolAddress((void**)&xhi, g_xhi);   cudaGetSymbolAddress((void**)&xlo, g_xlo);
    cudaGetSymbolAddress((void**)&wqhi, g_wqhi); cudaGetSymbolAddress((void**)&wqlo, g_wqlo);
    cudaGetSymbolAddress((void**)&wkvhi, g_wkvhi); cudaGetSymbolAddress((void**)&wkvlo, g_wkvlo);
    cudaGetSymbolAddress((void**)&wphi, g_wphi); cudaGetSymbolAddress((void**)&wplo, g_wplo);
    cudaGetSymbolAddress((void**)&ahi, g_ahi);   cudaGetSymbolAddress((void**)&alo, g_alo);

    cudaFuncSetAttribute(gemm_mma, cudaFuncAttributeMaxDynamicSharedMemorySize, GT_SMEM);
    cudaFuncSetAttribute(flash_hmma, cudaFuncAttributeMaxDynamicSharedMemorySize, FLASH_SMEM);

    // 0) split fp32 operands into bf16 hi/lo
    {
        int n4;
        n4 = BT * CC / 4;  split_kernel<<<(n4 + 255) / 256, 256>>>(x, xhi, xlo, n4);
        n4 = CC * CC / 4;  split_kernel<<<(n4 + 255) / 256, 256>>>(Wq, wqhi, wqlo, n4);
        n4 = KVC * CC / 4; split_kernel<<<(n4 + 255) / 256, 256>>>(Wkv, wkvhi, wkvlo, n4);
        n4 = CC * CC / 4;  split_kernel<<<(n4 + 255) / 256, 256>>>(Wproj, wphi, wplo, n4);
    }
    // 1) Q = x @ Wq^T
    {
        dim3 g(CC / 128, BT / 128);
        gemm_mma<<<g, 256, GT_SMEM>>>(xhi, xlo, wqhi, wqlo, qlin, CC, CC);
    }
    // 2) KV = x @ Wkv^T
    {
        dim3 g(KVC / 128, BT / 128);
        gemm_mma<<<g, 256, GT_SMEM>>>(xhi, xlo, wkvhi, wkvlo, kvlin, KVC, CC);
    }
    // 3) RMSNorm + RoPE on Q -> bf16 hi/lo [b,h,t,d]
    {
        int rows = BB * TT * NH;
        normrope_kernel<<<(rows * 32 + 255) / 256, 256>>>(qlin, qhi, qlo, CC, NH);
    }
    // 4) RMSNorm + RoPE on K -> bf16 hi/lo [b,kvh,t,d]
    {
        int rows = BB * TT * NKV;
        normrope_kernel<<<(rows * 32 + 255) / 256, 256>>>(kvlin, khi, klo, KVC, NKV);
    }
    // 5) V transpose + split -> bf16 hi/lo [b,kvh,t,d]
    {
        int total = BB * TT * NKV * DH / 4;
        vtrans_kernel<<<(total + 255) / 256, 256>>>(kvlin, vhi, vlo);
    }
    // 6) HMMA flash attention -> ahi/alo (bf16 hi/lo, [b,t,h*dh])
    {
        dim3 g(TT / FQ, NH, BB);
        flash_hmma<<<g, 256, FLASH_SMEM>>>(qhi, qlo, khi, klo, vhi, vlo, ahi, alo);
    }
    // 7) y = attn @ Wproj^T
    {
        dim3 g(CC / 128, BT / 128);
        gemm_mma<<<g, 256, GT_SMEM>>>(ahi, alo, wphi, wplo, out, CC, CC);
    }
    // 8) trailing scalar output
    {
        int btc = BB * TT * CC;
        if (out_size > btc) {
            int rem = out_size - btc;
            tailzero_kernel<<<(rem + 255) / 256, 256>>>(out, btc, out_size);
        }
    }
}

// round 10
// speedup vs baseline: 3.2132x; 1.0060x over previous
#include <cuda_runtime.h>
#include <cuda_bf16.h>
#include <math.h>
#include <stdint.h>

#define BB 2
#define TT 2048
#define CC 2048
#define NH 16
#define NKV 4
#define DH 128
#define BT (BB*TT)          // 4096
#define KVC (2*NKV*DH)      // 1024

// ---------------- scratch (static device globals; no allocation) ----------------
__device__ float g_qlin[BB*TT*CC];
__device__ float g_kvlin[BB*TT*KVC];
__device__ __nv_bfloat16 g_qhi[BB*NH*TT*DH],  g_qlo[BB*NH*TT*DH];
__device__ __nv_bfloat16 g_khi[BB*NKV*TT*DH], g_klo[BB*NKV*TT*DH];
__device__ __nv_bfloat16 g_vhi[BB*NKV*TT*DH], g_vlo[BB*NKV*TT*DH];
__device__ __nv_bfloat16 g_xhi[BT*CC],   g_xlo[BT*CC];
__device__ __nv_bfloat16 g_wqhi[CC*CC],  g_wqlo[CC*CC];
__device__ __nv_bfloat16 g_wkvhi[KVC*CC],g_wkvlo[KVC*CC];
__device__ __nv_bfloat16 g_wphi[CC*CC],  g_wplo[CC*CC];
__device__ __nv_bfloat16 g_ahi[BT*CC],   g_alo[BT*CC];

// ======================= warp-MMA helpers (sm_80+ portable) =====================
__device__ __forceinline__ uint32_t smem_to_u32(const void* p) {
    uint32_t a;
    asm("{ .reg .u64 t; cvta.to.shared.u64 t, %1; cvt.u32.u64 %0, t; }" : "=r"(a) : "l"(p));
    return a;
}
__device__ __forceinline__ void ldsm_x4(uint32_t& r0, uint32_t& r1, uint32_t& r2,
                                        uint32_t& r3, uint32_t addr) {
    asm volatile("ldmatrix.sync.aligned.m8n8.x4.shared.b16 {%0,%1,%2,%3}, [%4];"
                 : "=r"(r0), "=r"(r1), "=r"(r2), "=r"(r3) : "r"(addr));
}
__device__ __forceinline__ void ldsm_x4_t(uint32_t& r0, uint32_t& r1, uint32_t& r2,
                                          uint32_t& r3, uint32_t addr) {
    asm volatile("ldmatrix.sync.aligned.m8n8.x4.trans.shared.b16 {%0,%1,%2,%3}, [%4];"
                 : "=r"(r0), "=r"(r1), "=r"(r2), "=r"(r3) : "r"(addr));
}
__device__ __forceinline__ void mma_bf16(float* d, const uint32_t* a, const uint32_t* b) {
    asm volatile("mma.sync.aligned.m16n8k16.row.col.f32.bf16.bf16.f32 "
                 "{%0,%1,%2,%3}, {%4,%5,%6,%7}, {%8,%9}, {%0,%1,%2,%3};"
                 : "+f"(d[0]), "+f"(d[1]), "+f"(d[2]), "+f"(d[3])
                 : "r"(a[0]), "r"(a[1]), "r"(a[2]), "r"(a[3]), "r"(b[0]), "r"(b[1]));
}
__device__ __forceinline__ uint32_t packbf2(float x, float y) {
    __nv_bfloat162 t = __floats2bfloat162_rn(x, y);
    return *(uint32_t*)&t;
}
#define SWZ(o) ((o) ^ (((o) >> 3) & 0x70))
#define CP_ASYNC16(dst, src) \
    asm volatile("cp.async.cg.shared.global [%0], [%1], 16;" :: "r"(dst), "l"(src))
#define CP_COMMIT() asm volatile("cp.async.commit_group;" ::: "memory")
#define CP_WAIT(n)  asm volatile("cp.async.wait_group %0;" :: "n"(n) : "memory")

// ================= HMMA GEMM: C[M,N] fp32 = A[M,K] @ B[N,K]^T ===================
// bf16x3 split, 3-stage cp.async pipeline, ONE __syncthreads per iter.
// Optionally fuses two B/C column groups (Q + KV) in one launch.
#define GT_KC 64
#define GT_TILEB (128*128)
#define GT_STAGEB (4*GT_TILEB)      // 64 KB
#define GT_SMEM (3*GT_STAGEB)       // 192 KB

extern __shared__ char gsm[];

__global__ void __launch_bounds__(256) gemm_mma(
        const __nv_bfloat16* __restrict__ Ahi, const __nv_bfloat16* __restrict__ Alo,
        const __nv_bfloat16* __restrict__ Bhi1, const __nv_bfloat16* __restrict__ Blo1,
        float* __restrict__ C1, int N1, int nx1,
        const __nv_bfloat16* __restrict__ Bhi2, const __nv_bfloat16* __restrict__ Blo2,
        float* __restrict__ C2, int N2, int K) {
    const int tid = threadIdx.x;
    const int wid = tid >> 5, lane = tid & 31;
    const int wm = wid & 3, wn = wid >> 2;
    const int m0 = blockIdx.y * 128;
    const int NIT = K / GT_KC;
    uint32_t sb = smem_to_u32(gsm);

    // select column group (fused Q+KV support)
    const __nv_bfloat16 *Bhi, *Blo; float* C; int N, n0;
    if ((int)blockIdx.x < nx1) {
        Bhi = Bhi1; Blo = Blo1; C = C1; N = N1; n0 = blockIdx.x * 128;
    } else {
        Bhi = Bhi2; Blo = Blo2; C = C2; N = N2; n0 = (blockIdx.x - nx1) * 128;
    }

    float acc[2][8][4];
#pragma unroll
    for (int i = 0; i < 2; i++)
#pragma unroll
        for (int j = 0; j < 8; j++)
#pragma unroll
            for (int q = 0; q < 4; q++) acc[i][j][q] = 0.f;

    auto cp_stage = [&](int stage, int k0) {
        uint32_t st = sb + stage * GT_STAGEB;
        const __nv_bfloat16* srcs[4] = {Ahi, Alo, Bhi, Blo};
        const int r0s[4] = {m0, m0, n0, n0};
#pragma unroll
        for (int tle = 0; tle < 4; tle++) {
#pragma unroll
            for (int i = 0; i < 4; i++) {
                int idx = tid + i * 256;
                int r = idx >> 3, cg = idx & 7;
                uint32_t off = (uint32_t)(r * 128 + cg * 16);
                CP_ASYNC16(st + tle * GT_TILEB + SWZ(off),
                           srcs[tle] + (size_t)(r0s[tle] + r) * K + k0 + cg * 8);
            }
        }
    };

    cp_stage(0, 0);
    CP_COMMIT();
    cp_stage(1, GT_KC);
    CP_COMMIT();

    int st_c = 0;       // compute stage (it % 3)
    int st_p = 2;       // prefetch stage ((it+2) % 3)
    for (int it = 0; it < NIT; it++) {
        if (it + 1 < NIT) CP_WAIT(1); else CP_WAIT(0);   // stage `it` resident
        __syncthreads();   // data visible + all threads done with stage st_p's old use
        if (it + 2 < NIT) {
            cp_stage(st_p, (it + 2) * GT_KC);
            CP_COMMIT();
        }

        uint32_t stb = sb + st_c * GT_STAGEB;
        uint32_t smAhi = stb, smAlo = stb + GT_TILEB;
        uint32_t smBhi = stb + 2 * GT_TILEB, smBlo = stb + 3 * GT_TILEB;

#pragma unroll
        for (int ks = 0; ks < 4; ks++) {
            uint32_t colb = (uint32_t)(ks * 32 + (lane >> 4) * 16);
            uint32_t aHi[2][4], aLo[2][4];
#pragma unroll
            for (int mt = 0; mt < 2; mt++) {
                uint32_t off = (uint32_t)((wm * 32 + mt * 16 + (lane & 15)) * 128) + colb;
                uint32_t so = SWZ(off);
                ldsm_x4(aHi[mt][0], aHi[mt][1], aHi[mt][2], aHi[mt][3], smAhi + so);
                ldsm_x4(aLo[mt][0], aLo[mt][1], aLo[mt][2], aLo[mt][3], smAlo + so);
            }
            uint32_t bHi[8][2], bLo[8][2];
#pragma unroll
            for (int nt2 = 0; nt2 < 4; nt2++) {
                uint32_t off = (uint32_t)((wn * 64 + nt2 * 16 + (lane & 15)) * 128) + colb;
                uint32_t so = SWZ(off);
                uint32_t r0, r1, r2, r3;
                ldsm_x4(r0, r1, r2, r3, smBhi + so);
                bHi[2 * nt2][0] = r0; bHi[2 * nt2][1] = r2;
                bHi[2 * nt2 + 1][0] = r1; bHi[2 * nt2 + 1][1] = r3;
                ldsm_x4(r0, r1, r2, r3, smBlo + so);
                bLo[2 * nt2][0] = r0; bLo[2 * nt2][1] = r2;
                bLo[2 * nt2 + 1][0] = r1; bLo[2 * nt2 + 1][1] = r3;
            }
#pragma unroll
            for (int mt = 0; mt < 2; mt++)
#pragma unroll
                for (int nt = 0; nt < 8; nt++) {
                    mma_bf16(acc[mt][nt], aHi[mt], bHi[nt]);
                    mma_bf16(acc[mt][nt], aHi[mt], bLo[nt]);
                    mma_bf16(acc[mt][nt], aLo[mt], bHi[nt]);
                }
        }
        st_c = (st_c == 2) ? 0 : st_c + 1;
        st_p = (st_p == 2) ? 0 : st_p + 1;
    }

#pragma unroll
    for (int mt = 0; mt < 2; mt++) {
        int row = m0 + wm * 32 + mt * 16 + (lane >> 2);
#pragma unroll
        for (int nt = 0; nt < 8; nt++) {
            int col = n0 + wn * 64 + nt * 8 + 2 * (lane & 3);
            *(float2*)(C + (size_t)row * N + col) =
                make_float2(acc[mt][nt][0], acc[mt][nt][1]);
            *(float2*)(C + (size_t)(row + 8) * N + col) =
                make_float2(acc[mt][nt][2], acc[mt][nt][3]);
        }
    }
}

// =================== fp32 -> bf16 hi/lo split (elementwise) =====================
__global__ void split_kernel(const float* __restrict__ in, __nv_bfloat16* __restrict__ hi,
                             __nv_bfloat16* __restrict__ lo, int n4) {
    int i = blockIdx.x * blockDim.x + threadIdx.x;
    if (i >= n4) return;
    float4 v = ((const float4*)in)[i];
    float vv[4] = {v.x, v.y, v.z, v.w};
    ushort4 uh, ul;
    unsigned short* ph = &uh.x; unsigned short* pl = &ul.x;
#pragma unroll
    for (int j = 0; j < 4; j++) {
        __nv_bfloat16 h = __float2bfloat16(vv[j]);
        __nv_bfloat16 l = __float2bfloat16(vv[j] - __bfloat162float(h));
        ph[j] = __bfloat16_as_ushort(h);
        pl[j] = __bfloat16_as_ushort(l);
    }
    ((ushort4*)hi)[i] = uh;
    ((ushort4*)lo)[i] = ul;
}

// ------------- fused RMSNorm + rotary -> bf16 hi/lo (position = HEAD index) -----
__global__ void normrope_kernel(const float* __restrict__ in,
                                __nv_bfloat16* __restrict__ ohi,
                                __nv_bfloat16* __restrict__ olo,
                                int rowstride, int nheads) {
    int w = (blockIdx.x * blockDim.x + threadIdx.x) >> 5;
    int lane = threadIdx.x & 31;
    int total = BB * TT * nheads;
    if (w >= total) return;
    int h = w % nheads;
    int t = (w / nheads) % TT;
    int b = w / (nheads * TT);

    const float* src = in + (size_t)(b * TT + t) * rowstride + h * DH;
    float4 v = *(const float4*)(src + lane * 4);
    float ss = v.x * v.x + v.y * v.y + v.z * v.z + v.w * v.w;
#pragma unroll
    for (int o = 16; o; o >>= 1) ss += __shfl_xor_sync(0xffffffffu, ss, o);
    float scale = rsqrtf(ss * (1.0f / 128.0f) + 1.1920929e-07f);

    float x[4] = {v.x * scale, v.y * scale, v.z * scale, v.w * scale};
    float y[4];
#pragma unroll
    for (int i = 0; i < 4; i++) {
        float part = __shfl_xor_sync(0xffffffffu, x[i], 16);
        int d = lane * 4 + i;
        int j = d & 63;
        float freq = (j < 32) ? powf(1.0f / 1024.0f, (float)j * (1.0f / 31.0f)) : 0.0f;
        float s, c;
        sincosf((float)h * freq, &s, &c);
        if (d < 64) y[i] = x[i] * c + part * s;
        else        y[i] = -part * s + x[i] * c;
    }
    size_t off = ((size_t)(b * nheads + h) * TT + t) * DH + lane * 4;
    ushort4 uh, ul;
    unsigned short* ph = &uh.x; unsigned short* pl = &ul.x;
#pragma unroll
    for (int i = 0; i < 4; i++) {
        __nv_bfloat16 hh = __float2bfloat16(y[i]);
        __nv_bfloat16 ll = __float2bfloat16(y[i] - __bfloat162float(hh));
        ph[i] = __bfloat16_as_ushort(hh);
        pl[i] = __bfloat16_as_ushort(ll);
    }
    *(ushort4*)(ohi + off) = uh;
    *(ushort4*)(olo + off) = ul;
}

// ------------- V transpose + bf16 hi/lo split -----------------------------------
__global__ void vtrans_kernel(const float* __restrict__ kvlin,
                              __nv_bfloat16* __restrict__ vhi,
                              __nv_bfloat16* __restrict__ vlo) {
    int idx = blockIdx.x * blockDim.x + threadIdx.x;
    const int total = BB * TT * NKV * DH / 4;
    if (idx >= total) return;
    int d4 = idx & (DH / 4 - 1);
    int h = (idx >> 5) & (NKV - 1);
    int t = (idx >> 7) & (TT - 1);
    int b = idx >> 18;
    float4 v = *(const float4*)(kvlin + (size_t)(b * TT + t) * KVC + NKV * DH + h * DH + d4 * 4);
    float vv[4] = {v.x, v.y, v.z, v.w};
    ushort4 uh, ul;
    unsigned short* ph = &uh.x; unsigned short* pl = &ul.x;
#pragma unroll
    for (int j = 0; j < 4; j++) {
        __nv_bfloat16 hh = __float2bfloat16(vv[j]);
        __nv_bfloat16 ll = __float2bfloat16(vv[j] - __bfloat162float(hh));
        ph[j] = __bfloat16_as_ushort(hh);
        pl[j] = __bfloat16_as_ushort(ll);
    }
    size_t off = ((size_t)(b * NKV + h) * TT + t) * DH + d4 * 4;
    *(ushort4*)(vhi + off) = uh;
    *(ushort4*)(vlo + off) = ul;
}

// ================= HMMA flash attention: 128q x 64k, 8 warps ====================
// smem: Q hi/lo resident (64KB), K/V hi/lo double-buffered (2x64KB) = 192KB.
// ONE __syncthreads per k-tile.
#define FQ 128
#define FK 64
#define FHALF_Q 16384
#define FHALF_KV 8192
#define FSM_QH 0
#define FSM_QL 32768
#define FSM_KV0 65536
#define FSTAGE 65536
#define FLASH_SMEM 196608

__global__ void __launch_bounds__(256) flash_hmma(
        const __nv_bfloat16* __restrict__ qhi, const __nv_bfloat16* __restrict__ qlo,
        const __nv_bfloat16* __restrict__ khi, const __nv_bfloat16* __restrict__ klo,
        const __nv_bfloat16* __restrict__ vhi, const __nv_bfloat16* __restrict__ vlo,
        __nv_bfloat16* __restrict__ ahi, __nv_bfloat16* __restrict__ alo) {
    const int tid = threadIdx.x, wid = tid >> 5, lane = tid & 31;
    const int qt = blockIdx.x, h = blockIdx.y, b = blockIdx.z;
    const int kvh = h >> 2;
    uint32_t sb = smem_to_u32(gsm);

    const __nv_bfloat16* Qh_g = qhi + ((size_t)(b * NH + h) * TT + qt * FQ) * DH;
    const __nv_bfloat16* Ql_g = qlo + ((size_t)(b * NH + h) * TT + qt * FQ) * DH;
    const __nv_bfloat16* Kh_g = khi + (size_t)(b * NKV + kvh) * TT * DH;
    const __nv_bfloat16* Kl_g = klo + (size_t)(b * NKV + kvh) * TT * DH;
    const __nv_bfloat16* Vh_g = vhi + (size_t)(b * NKV + kvh) * TT * DH;
    const __nv_bfloat16* Vl_g = vlo + (size_t)(b * NKV + kvh) * TT * DH;

    // Q hi/lo -> smem (64KB), grouped with kv(0) into commit group 0
    {
        const __nv_bfloat16* srcs[2] = {Qh_g, Ql_g};
        const uint32_t dsts[2] = {FSM_QH, FSM_QL};
#pragma unroll
        for (int a = 0; a < 2; a++)
#pragma unroll
            for (int i = 0; i < 8; i++) {
                int idx = tid + i * 256;
                int hf = idx >> 10, r = (idx >> 3) & 127, cg = idx & 7;
                CP_ASYNC16(sb + dsts[a] + hf * FHALF_Q + SWZ((uint32_t)(r * 128 + cg * 16)),
                           srcs[a] + (size_t)r * DH + hf * 64 + cg * 8);
            }
    }
    auto cp_kv = [&](int stage, int kt2) {
        uint32_t dstb = sb + FSM_KV0 + stage * FSTAGE;
        const __nv_bfloat16* srcs[4] = {Kh_g, Kl_g, Vh_g, Vl_g};
#pragma unroll
        for (int a = 0; a < 4; a++) {
            const __nv_bfloat16* src = srcs[a] + (size_t)kt2 * FK * DH;
#pragma unroll
            for (int i = 0; i < 4; i++) {
                int idx = tid + i * 256;
                int hf = idx >> 9, r = (idx >> 3) & 63, cg = idx & 7;
                CP_ASYNC16(dstb + a * 16384 + hf * FHALF_KV + SWZ((uint32_t)(r * 128 + cg * 16)),
                           src + (size_t)r * DH + hf * 64 + cg * 8);
            }
        }
    };
    cp_kv(0, 0);
    CP_COMMIT();

    const int ntiles = 2 * qt + 2;
    const int grow_lo = qt * FQ + wid * 16 + (lane >> 2);
    const float scl = 0.08838834764831845f;

    float m_lo = -1e30f, m_hi = -1e30f, l_lo = 0.f, l_hi = 0.f;
    float o[16][4];
#pragma unroll
    for (int n = 0; n < 16; n++)
#pragma unroll
        for (int q = 0; q < 4; q++) o[n][q] = 0.f;

    for (int kt = 0; kt < ntiles; kt++) {
        CP_WAIT(0);          // group kt (and Q on kt=0) complete
        __syncthreads();     // visible to all; stage (kt+1)&1 free of compute(kt-1)
        if (kt + 1 < ntiles) { cp_kv((kt + 1) & 1, kt + 1); CP_COMMIT(); }

        uint32_t kvb = sb + FSM_KV0 + (kt & 1) * FSTAGE;
        uint32_t smKh = kvb, smKl = kvb + 16384, smVh = kvb + 32768, smVl = kvb + 49152;

        // ---- S = Q K^T (bf16x3) ----
        float s[8][4];
#pragma unroll
        for (int n = 0; n < 8; n++)
#pragma unroll
            for (int q = 0; q < 4; q++) s[n][q] = 0.f;
#pragma unroll
        for (int ks = 0; ks < 8; ks++) {
            int hf = ks >> 2;
            uint32_t colb = (uint32_t)((ks & 3) * 32 + (lane >> 4) * 16);
            uint32_t aoff = SWZ((uint32_t)((wid * 16 + (lane & 15)) * 128) + colb);
            uint32_t aHi[4], aLo[4];
            ldsm_x4(aHi[0], aHi[1], aHi[2], aHi[3], sb + FSM_QH + hf * FHALF_Q + aoff);
            ldsm_x4(aLo[0], aLo[1], aLo[2], aLo[3], sb + FSM_QL + hf * FHALF_Q + aoff);
#pragma unroll
            for (int nt2 = 0; nt2 < 4; nt2++) {
                uint32_t boff = hf * FHALF_KV +
                    SWZ((uint32_t)((nt2 * 16 + (lane & 15)) * 128) + colb);
                uint32_t r0, r1, r2, r3;
                uint32_t bh0[2], bh1[2], bl0[2], bl1[2];
                ldsm_x4(r0, r1, r2, r3, smKh + boff);
                bh0[0] = r0; bh0[1] = r2; bh1[0] = r1; bh1[1] = r3;
                ldsm_x4(r0, r1, r2, r3, smKl + boff);
                bl0[0] = r0; bl0[1] = r2; bl1[0] = r1; bl1[1] = r3;
                mma_bf16(s[2 * nt2], aHi, bh0);
                mma_bf16(s[2 * nt2], aHi, bl0);
                mma_bf16(s[2 * nt2], aLo, bh0);
                mma_bf16(s[2 * nt2 + 1], aHi, bh1);
                mma_bf16(s[2 * nt2 + 1], aHi, bl1);
                mma_bf16(s[2 * nt2 + 1], aLo, bh1);
            }
        }

        // ---- mask + online softmax ----
        float mx_lo = -1e30f, mx_hi = -1e30f;
#pragma unroll
        for (int nt = 0; nt < 8; nt++)
#pragma unroll
            for (int j = 0; j < 2; j++) {
                int gc = kt * FK + nt * 8 + (lane & 3) * 2 + j;
                s[nt][j]     = (gc <= grow_lo)     ? s[nt][j] * scl     : -1e30f;
                s[nt][j + 2] = (gc <= grow_lo + 8) ? s[nt][j + 2] * scl : -1e30f;
                mx_lo = fmaxf(mx_lo, s[nt][j]);
                mx_hi = fmaxf(mx_hi, s[nt][j + 2]);
            }
        mx_lo = fmaxf(mx_lo, __shfl_xor_sync(0xffffffffu, mx_lo, 1));
        mx_lo = fmaxf(mx_lo, __shfl_xor_sync(0xffffffffu, mx_lo, 2));
        mx_hi = fmaxf(mx_hi, __shfl_xor_sync(0xffffffffu, mx_hi, 1));
        mx_hi = fmaxf(mx_hi, __shfl_xor_sync(0xffffffffu, mx_hi, 2));
        float mn_lo = fmaxf(m_lo, mx_lo), mn_hi = fmaxf(m_hi, mx_hi);
        float cr_lo = __expf(m_lo - mn_lo), cr_hi = __expf(m_hi - mn_hi);
        m_lo = mn_lo; m_hi = mn_hi;
        float rs_lo = 0.f, rs_hi = 0.f;
#pragma unroll
        for (int nt = 0; nt < 8; nt++)
#pragma unroll
            for (int j = 0; j < 2; j++) {
                s[nt][j] = __expf(s[nt][j] - mn_lo);
                s[nt][j + 2] = __expf(s[nt][j + 2] - mn_hi);
                rs_lo += s[nt][j];
                rs_hi += s[nt][j + 2];
            }
        rs_lo += __shfl_xor_sync(0xffffffffu, rs_lo, 1);
        rs_lo += __shfl_xor_sync(0xffffffffu, rs_lo, 2);
        rs_hi += __shfl_xor_sync(0xffffffffu, rs_hi, 1);
        rs_hi += __shfl_xor_sync(0xffffffffu, rs_hi, 2);
        l_lo = l_lo * cr_lo + rs_lo;
        l_hi = l_hi * cr_hi + rs_hi;
#pragma unroll
        for (int n = 0; n < 16; n++) {
            o[n][0] *= cr_lo; o[n][1] *= cr_lo;
            o[n][2] *= cr_hi; o[n][3] *= cr_hi;
        }

        // ---- P C-frags -> A-frags (hi/lo) ----
        uint32_t aPh[4][4], aPl[4][4];
#pragma unroll
        for (int kc = 0; kc < 4; kc++) {
            float* c0 = s[2 * kc];
            float* c1 = s[2 * kc + 1];
            float v00 = c0[0], v01 = c0[1], v02 = c0[2], v03 = c0[3];
            float v10 = c1[0], v11 = c1[1], v12 = c1[2], v13 = c1[3];
            uint32_t h00 = packbf2(v00, v01);
            uint32_t h01 = packbf2(v02, v03);
            uint32_t h10 = packbf2(v10, v11);
            uint32_t h11 = packbf2(v12, v13);
            aPh[kc][0] = h00; aPh[kc][1] = h01; aPh[kc][2] = h10; aPh[kc][3] = h11;
            __nv_bfloat162 t;
            t = *(__nv_bfloat162*)&h00;
            aPl[kc][0] = packbf2(v00 - __bfloat162float(t.x), v01 - __bfloat162float(t.y));
            t = *(__nv_bfloat162*)&h01;
            aPl[kc][1] = packbf2(v02 - __bfloat162float(t.x), v03 - __bfloat162float(t.y));
            t = *(__nv_bfloat162*)&h10;
            aPl[kc][2] = packbf2(v10 - __bfloat162float(t.x), v11 - __bfloat162float(t.y));
            t = *(__nv_bfloat162*)&h11;
            aPl[kc][3] = packbf2(v12 - __bfloat162float(t.x), v13 - __bfloat162float(t.y));
        }

        // ---- O += P V (bf16x3), V B-frags via ldmatrix.trans ----
#pragma unroll
        for (int kc = 0; kc < 4; kc++) {
#pragma unroll
            for (int hf = 0; hf < 2; hf++)
#pragma unroll
                for (int dt = 0; dt < 4; dt++) {
                    uint32_t voff = hf * FHALF_KV +
                        SWZ((uint32_t)((kc * 16 + (lane & 15)) * 128 +
                                       dt * 32 + (lane >> 4) * 16));
                    uint32_t r0, r1, r2, r3;
                    uint32_t bh0[2], bh1[2], bl0[2], bl1[2];
                    ldsm_x4_t(r0, r1, r2, r3, smVh + voff);
                    bh0[0] = r0; bh0[1] = r1; bh1[0] = r2; bh1[1] = r3;
                    ldsm_x4_t(r0, r1, r2, r3, smVl + voff);
                    bl0[0] = r0; bl0[1] = r1; bl1[0] = r2; bl1[1] = r3;
                    int n = hf * 8 + dt * 2;
                    mma_bf16(o[n], aPh[kc], bh0);
                    mma_bf16(o[n], aPh[kc], bl0);
                    mma_bf16(o[n], aPl[kc], bh0);
                    mma_bf16(o[n + 1], aPh[kc], bh1);
                    mma_bf16(o[n + 1], aPh[kc], bl1);
                    mma_bf16(o[n + 1], aPl[kc], bh1);
                }
        }
    }

    // ---- epilogue ----
    float li_lo = 1.0f / l_lo, li_hi = 1.0f / l_hi;
    int t_lo = qt * FQ + wid * 16 + (lane >> 2);
    size_t base_lo = ((size_t)b * TT + t_lo) * CC + h * DH;
    size_t base_hi = base_lo + (size_t)8 * CC;
#pragma unroll
    for (int n = 0; n < 16; n++) {
        int d = n * 8 + (lane & 3) * 2;
        float v0 = o[n][0] * li_lo, v1 = o[n][1] * li_lo;
        float v2 = o[n][2] * li_hi, v3 = o[n][3] * li_hi;
        uint32_t h01 = packbf2(v0, v1);
        __nv_bfloat162 t = *(__nv_bfloat162*)&h01;
        uint32_t l01 = packbf2(v0 - __bfloat162float(t.x), v1 - __bfloat162float(t.y));
        uint32_t h23 = packbf2(v2, v3);
        t = *(__nv_bfloat162*)&h23;
        uint32_t l23 = packbf2(v2 - __bfloat162float(t.x), v3 - __bfloat162float(t.y));
        *(uint32_t*)(ahi + base_lo + d) = h01;
        *(uint32_t*)(alo + base_lo + d) = l01;
        *(uint32_t*)(ahi + base_hi + d) = h23;
        *(uint32_t*)(alo + base_hi + d) = l23;
    }
}

// ------------- tail zero --------------------------------------------------------
__global__ void tailzero_kernel(float* out, int start, int total) {
    int i = start + blockIdx.x * blockDim.x + threadIdx.x;
    if (i < total) out[i] = 0.f;
}

// ------------- launcher --------------------------------------------------------
extern "C" void kernel_launch(void* const* d_in, const int* in_sizes, int n_in,
                              void* d_out, int out_size) {
    const float* x     = (const float*)d_in[0];
    const float* Wq    = (const float*)d_in[1];
    const float* Wkv   = (const float*)d_in[2];
    const float* Wproj = (const float*)d_in[3];
    float* out = (float*)d_out;

    float *qlin, *kvlin;
    __nv_bfloat16 *qhi, *qlo, *khi, *klo, *vhi, *vlo;
    __nv_bfloat16 *xhi, *xlo, *wqhi, *wqlo, *wkvhi, *wkvlo, *wphi, *wplo, *ahi, *alo;
    cudaGetSymbolAddress((void**)&qlin, g_qlin);
    cudaGetSymbolAddress((void**)&kvlin, g_kvlin);
    cudaGetSymbolAddress((void**)&qhi, g_qhi);   cudaGetSymbolAddress((void**)&qlo, g_qlo);
    cudaGetSymbolAddress((void**)&khi, g_khi);   cudaGetSymbolAddress((void**)&klo, g_klo);
    cudaGetSymbolAddress((void**)&vhi, g_vhi);   cudaGetSymbolAddress((void**)&vlo, g_vlo);
    cudaGetSymbolAddress((void**)&xhi, g_xhi);   cudaGetSymbolAddress((void**)&xlo, g_xlo);
    cudaGetSymbolAddress((void**)&wqhi, g_wqhi); cudaGetSymbolAddress((void**)&wqlo, g_wqlo);
    cudaGetSymbolAddress((void**)&wkvhi, g_wkvhi); cudaGetSymbolAddress((void**)&wkvlo, g_wkvlo);
    cudaGetSymbolAddress((void**)&wphi, g_wphi); cudaGetSymbolAddress((void**)&wplo, g_wplo);
    cudaGetSymbolAddress((void**)&ahi, g_ahi);   cudaGetSymbolAddress((void**)&alo, g_alo);

    cudaFuncSetAttribute(gemm_mma, cudaFuncAttributeMaxDynamicSharedMemorySize, GT_SMEM);
    cudaFuncSetAttribute(flash_hmma, cudaFuncAttributeMaxDynamicSharedMemorySize, FLASH_SMEM);

    // 0) split fp32 operands into bf16 hi/lo
    {
        int n4;
        n4 = BT * CC / 4;  split_kernel<<<(n4 + 255) / 256, 256>>>(x, xhi, xlo, n4);
        n4 = CC * CC / 4;  split_kernel<<<(n4 + 255) / 256, 256>>>(Wq, wqhi, wqlo, n4);
        n4 = KVC * CC / 4; split_kernel<<<(n4 + 255) / 256, 256>>>(Wkv, wkvhi, wkvlo, n4);
        n4 = CC * CC / 4;  split_kernel<<<(n4 + 255) / 256, 256>>>(Wproj, wphi, wplo, n4);
    }
    // 1+2) fused [Q | KV] = x @ [Wq | Wkv]^T
    {
        dim3 g(CC / 128 + KVC / 128, BT / 128);   // 24 x 32
        gemm_mma<<<g, 256, GT_SMEM>>>(xhi, xlo,
                                      wqhi, wqlo, qlin, CC, CC / 128,
                                      wkvhi, wkvlo, kvlin, KVC, CC);
    }
    // 3) RMSNorm + RoPE on Q -> bf16 hi/lo [b,h,t,d]
    {
        int rows = BB * TT * NH;
        normrope_kernel<<<(rows * 32 + 255) / 256, 256>>>(qlin, qhi, qlo, CC, NH);
    }
    // 4) RMSNorm + RoPE on K -> bf16 hi/lo [b,kvh,t,d]
    {
        int rows = BB * TT * NKV;
        normrope_kernel<<<(rows * 32 + 255) / 256, 256>>>(kvlin, khi, klo, KVC, NKV);
    }
    // 5) V transpose + split -> bf16 hi/lo [b,kvh,t,d]
    {
        int total = BB * TT * NKV * DH / 4;
        vtrans_kernel<<<(total + 255) / 256, 256>>>(kvlin, vhi, vlo);
    }
    // 6) HMMA flash attention -> ahi/alo
    {
        dim3 g(TT / FQ, NH, BB);
        flash_hmma<<<g, 256, FLASH_SMEM>>>(qhi, qlo, khi, klo, vhi, vlo, ahi, alo);
    }
    // 7) y = attn @ Wproj^T
    {
        dim3 g(CC / 128, BT / 128);
        gemm_mma<<<g, 256, GT_SMEM>>>(ahi, alo,
                                      wphi, wplo, out, CC, CC / 128,
                                      wphi, wplo, out, CC, CC);
    }
    // 8) trailing scalar output
    {
        int btc = BB * TT * CC;
        if (out_size > btc) {
            int rem = out_size - btc;
            tailzero_kernel<<<(rem + 255) / 256, 256>>>(out, btc, out_size);
        }
    }
}

// round 11
// speedup vs baseline: 3.3543x; 1.0439x over previous
#include <cuda_runtime.h>
#include <cuda_bf16.h>
#include <math.h>
#include <stdint.h>

#define BB 2
#define TT 2048
#define CC 2048
#define NH 16
#define NKV 4
#define DH 128
#define BT (BB*TT)          // 4096
#define KVC (2*NKV*DH)      // 1024

// ---------------- scratch (static device globals; no allocation) ----------------
__device__ float g_qlin[BB*TT*CC];
__device__ float g_kvlin[BB*TT*KVC];
__device__ __nv_bfloat16 g_qhi[BB*NH*TT*DH],  g_qlo[BB*NH*TT*DH];
__device__ __nv_bfloat16 g_khi[BB*NKV*TT*DH], g_klo[BB*NKV*TT*DH];
__device__ __nv_bfloat16 g_vhi[BB*NKV*TT*DH], g_vlo[BB*NKV*TT*DH];
__device__ __nv_bfloat16 g_xhi[BT*CC],   g_xlo[BT*CC];
__device__ __nv_bfloat16 g_wqhi[CC*CC],  g_wqlo[CC*CC];
__device__ __nv_bfloat16 g_wkvhi[KVC*CC],g_wkvlo[KVC*CC];
__device__ __nv_bfloat16 g_wphi[CC*CC],  g_wplo[CC*CC];
__device__ __nv_bfloat16 g_ahi[BT*CC],   g_alo[BT*CC];

// ======================= warp-MMA helpers (sm_80+ portable) =====================
__device__ __forceinline__ uint32_t smem_to_u32(const void* p) {
    uint32_t a;
    asm("{ .reg .u64 t; cvta.to.shared.u64 t, %1; cvt.u32.u64 %0, t; }" : "=r"(a) : "l"(p));
    return a;
}
__device__ __forceinline__ void ldsm_x4(uint32_t& r0, uint32_t& r1, uint32_t& r2,
                                        uint32_t& r3, uint32_t addr) {
    asm volatile("ldmatrix.sync.aligned.m8n8.x4.shared.b16 {%0,%1,%2,%3}, [%4];"
                 : "=r"(r0), "=r"(r1), "=r"(r2), "=r"(r3) : "r"(addr));
}
__device__ __forceinline__ void ldsm_x4_t(uint32_t& r0, uint32_t& r1, uint32_t& r2,
                                          uint32_t& r3, uint32_t addr) {
    asm volatile("ldmatrix.sync.aligned.m8n8.x4.trans.shared.b16 {%0,%1,%2,%3}, [%4];"
                 : "=r"(r0), "=r"(r1), "=r"(r2), "=r"(r3) : "r"(addr));
}
__device__ __forceinline__ void mma_bf16(float* d, const uint32_t* a, const uint32_t* b) {
    asm volatile("mma.sync.aligned.m16n8k16.row.col.f32.bf16.bf16.f32 "
                 "{%0,%1,%2,%3}, {%4,%5,%6,%7}, {%8,%9}, {%0,%1,%2,%3};"
                 : "+f"(d[0]), "+f"(d[1]), "+f"(d[2]), "+f"(d[3])
                 : "r"(a[0]), "r"(a[1]), "r"(a[2]), "r"(a[3]), "r"(b[0]), "r"(b[1]));
}
__device__ __forceinline__ uint32_t packbf2(float x, float y) {
    __nv_bfloat162 t = __floats2bfloat162_rn(x, y);
    return *(uint32_t*)&t;
}
#define SWZ(o)   ((o) ^ (((o) >> 3) & 0x70))   // SW128 (128B rows)
#define SWZ64(o) ((o) ^ (((o) >> 3) & 0x30))   // SW64  (64B rows)
#define CP_ASYNC16(dst, src) \
    asm volatile("cp.async.cg.shared.global [%0], [%1], 16;" :: "r"(dst), "l"(src))
#define CP_COMMIT() asm volatile("cp.async.commit_group;" ::: "memory")
#define CP_WAIT(n)  asm volatile("cp.async.wait_group %0;" :: "n"(n) : "memory")

// ================= HMMA GEMM: C[M,N] fp32 = A[M,K] @ B[N,K]^T ===================
// bf16x3 split. CTA tile 128x64, 8 warps (4M x 2N), warp tile 32x32, K-chunk 32.
// 3-stage cp.async, 24KB/stage = 72KB smem -> 2 CTAs/SM (16 warps/SM).
#define GT_KC 32
#define GT_AT 8192              // A tile: 128 rows x 64B (hi or lo)
#define GT_BT 4096              // B tile: 64 rows x 64B
#define GT_STAGEB 24576         // Ahi, Alo, Bhi, Blo
#define GT_SMEM (3*GT_STAGEB)   // 73728

extern __shared__ char gsm[];

__global__ void __launch_bounds__(256, 2) gemm_mma(
        const __nv_bfloat16* __restrict__ Ahi, const __nv_bfloat16* __restrict__ Alo,
        const __nv_bfloat16* __restrict__ Bhi1, const __nv_bfloat16* __restrict__ Blo1,
        float* __restrict__ C1, int N1, int nx1,
        const __nv_bfloat16* __restrict__ Bhi2, const __nv_bfloat16* __restrict__ Blo2,
        float* __restrict__ C2, int N2, int K) {
    const int tid = threadIdx.x;
    const int wid = tid >> 5, lane = tid & 31;
    const int wm = wid & 3, wn = wid >> 2;       // 4 M-warps x 2 N-warps
    const int m0 = blockIdx.y * 128;
    const int NIT = K / GT_KC;                   // 64
    uint32_t sb = smem_to_u32(gsm);

    const __nv_bfloat16 *Bhi, *Blo; float* C; int N, n0;
    if ((int)blockIdx.x < nx1) {
        Bhi = Bhi1; Blo = Blo1; C = C1; N = N1; n0 = blockIdx.x * 64;
    } else {
        Bhi = Bhi2; Blo = Blo2; C = C2; N = N2; n0 = (blockIdx.x - nx1) * 64;
    }

    float acc[2][4][4];
#pragma unroll
    for (int i = 0; i < 2; i++)
#pragma unroll
        for (int j = 0; j < 4; j++)
#pragma unroll
            for (int q = 0; q < 4; q++) acc[i][j][q] = 0.f;

    // stage: [Ahi 8K][Alo 8K][Bhi 4K][Blo 4K], 64B rows, SW64 swizzle
    auto cp_stage = [&](int stage, int k0) {
        uint32_t st = sb + stage * GT_STAGEB;
        {   // A hi/lo: 512 chunks each (2 per thread per tile)
            const __nv_bfloat16* srcs[2] = {Ahi, Alo};
#pragma unroll
            for (int a = 0; a < 2; a++)
#pragma unroll
                for (int j = 0; j < 2; j++) {
                    int c = tid + j * 256;            // 0..511
                    int r = c >> 2, cg = c & 3;
                    CP_ASYNC16(st + a * GT_AT + SWZ64((uint32_t)(r * 64 + cg * 16)),
                               srcs[a] + (size_t)(m0 + r) * K + k0 + cg * 8);
                }
        }
        {   // B hi/lo: 256 chunks each (1 per thread per tile)
            const __nv_bfloat16* srcs[2] = {Bhi, Blo};
#pragma unroll
            for (int a = 0; a < 2; a++) {
                int r = tid >> 2, cg = tid & 3;
                CP_ASYNC16(st + 2 * GT_AT + a * GT_BT + SWZ64((uint32_t)(r * 64 + cg * 16)),
                           srcs[a] + (size_t)(n0 + r) * K + k0 + cg * 8);
            }
        }
    };

    cp_stage(0, 0);
    CP_COMMIT();
    cp_stage(1, GT_KC);
    CP_COMMIT();

    int st_c = 0, st_p = 2;
    for (int it = 0; it < NIT; it++) {
        if (it + 1 < NIT) CP_WAIT(1); else CP_WAIT(0);
        __syncthreads();
        if (it + 2 < NIT) {
            cp_stage(st_p, (it + 2) * GT_KC);
            CP_COMMIT();
        }

        uint32_t stb = sb + st_c * GT_STAGEB;
        uint32_t smAhi = stb, smAlo = stb + GT_AT;
        uint32_t smBhi = stb + 2 * GT_AT, smBlo = stb + 2 * GT_AT + GT_BT;

#pragma unroll
        for (int ks = 0; ks < 2; ks++) {
            uint32_t colb = (uint32_t)(ks * 32 + (lane >> 4) * 16);
            uint32_t aHi[2][4], aLo[2][4];
#pragma unroll
            for (int mt = 0; mt < 2; mt++) {
                uint32_t so = SWZ64((uint32_t)((wm * 32 + mt * 16 + (lane & 15)) * 64) + colb);
                ldsm_x4(aHi[mt][0], aHi[mt][1], aHi[mt][2], aHi[mt][3], smAhi + so);
                ldsm_x4(aLo[mt][0], aLo[mt][1], aLo[mt][2], aLo[mt][3], smAlo + so);
            }
            uint32_t bHi[4][2], bLo[4][2];
#pragma unroll
            for (int nt2 = 0; nt2 < 2; nt2++) {
                uint32_t so = SWZ64((uint32_t)((wn * 32 + nt2 * 16 + (lane & 15)) * 64) + colb);
                uint32_t r0, r1, r2, r3;
                ldsm_x4(r0, r1, r2, r3, smBhi + so);
                bHi[2 * nt2][0] = r0; bHi[2 * nt2][1] = r2;
                bHi[2 * nt2 + 1][0] = r1; bHi[2 * nt2 + 1][1] = r3;
                ldsm_x4(r0, r1, r2, r3, smBlo + so);
                bLo[2 * nt2][0] = r0; bLo[2 * nt2][1] = r2;
                bLo[2 * nt2 + 1][0] = r1; bLo[2 * nt2 + 1][1] = r3;
            }
#pragma unroll
            for (int mt = 0; mt < 2; mt++)
#pragma unroll
                for (int nt = 0; nt < 4; nt++) {
                    mma_bf16(acc[mt][nt], aHi[mt], bHi[nt]);
                    mma_bf16(acc[mt][nt], aHi[mt], bLo[nt]);
                    mma_bf16(acc[mt][nt], aLo[mt], bHi[nt]);
                }
        }
        st_c = (st_c == 2) ? 0 : st_c + 1;
        st_p = (st_p == 2) ? 0 : st_p + 1;
    }

#pragma unroll
    for (int mt = 0; mt < 2; mt++) {
        int row = m0 + wm * 32 + mt * 16 + (lane >> 2);
#pragma unroll
        for (int nt = 0; nt < 4; nt++) {
            int col = n0 + wn * 32 + nt * 8 + 2 * (lane & 3);
            *(float2*)(C + (size_t)row * N + col) =
                make_float2(acc[mt][nt][0], acc[mt][nt][1]);
            *(float2*)(C + (size_t)(row + 8) * N + col) =
                make_float2(acc[mt][nt][2], acc[mt][nt][3]);
        }
    }
}

// =================== fp32 -> bf16 hi/lo split (elementwise) =====================
__global__ void split_kernel(const float* __restrict__ in, __nv_bfloat16* __restrict__ hi,
                             __nv_bfloat16* __restrict__ lo, int n4) {
    int i = blockIdx.x * blockDim.x + threadIdx.x;
    if (i >= n4) return;
    float4 v = ((const float4*)in)[i];
    float vv[4] = {v.x, v.y, v.z, v.w};
    ushort4 uh, ul;
    unsigned short* ph = &uh.x; unsigned short* pl = &ul.x;
#pragma unroll
    for (int j = 0; j < 4; j++) {
        __nv_bfloat16 h = __float2bfloat16(vv[j]);
        __nv_bfloat16 l = __float2bfloat16(vv[j] - __bfloat162float(h));
        ph[j] = __bfloat16_as_ushort(h);
        pl[j] = __bfloat16_as_ushort(l);
    }
    ((ushort4*)hi)[i] = uh;
    ((ushort4*)lo)[i] = ul;
}

// ------------- fused RMSNorm + rotary -> bf16 hi/lo (position = HEAD index) -----
__global__ void normrope_kernel(const float* __restrict__ in,
                                __nv_bfloat16* __restrict__ ohi,
                                __nv_bfloat16* __restrict__ olo,
                                int rowstride, int nheads) {
    int w = (blockIdx.x * blockDim.x + threadIdx.x) >> 5;
    int lane = threadIdx.x & 31;
    int total = BB * TT * nheads;
    if (w >= total) return;
    int h = w % nheads;
    int t = (w / nheads) % TT;
    int b = w / (nheads * TT);

    const float* src = in + (size_t)(b * TT + t) * rowstride + h * DH;
    float4 v = *(const float4*)(src + lane * 4);
    float ss = v.x * v.x + v.y * v.y + v.z * v.z + v.w * v.w;
#pragma unroll
    for (int o = 16; o; o >>= 1) ss += __shfl_xor_sync(0xffffffffu, ss, o);
    float scale = rsqrtf(ss * (1.0f / 128.0f) + 1.1920929e-07f);

    float x[4] = {v.x * scale, v.y * scale, v.z * scale, v.w * scale};
    float y[4];
#pragma unroll
    for (int i = 0; i < 4; i++) {
        float part = __shfl_xor_sync(0xffffffffu, x[i], 16);
        int d = lane * 4 + i;
        int j = d & 63;
        float freq = (j < 32) ? powf(1.0f / 1024.0f, (float)j * (1.0f / 31.0f)) : 0.0f;
        float s, c;
        sincosf((float)h * freq, &s, &c);
        if (d < 64) y[i] = x[i] * c + part * s;
        else        y[i] = -part * s + x[i] * c;
    }
    size_t off = ((size_t)(b * nheads + h) * TT + t) * DH + lane * 4;
    ushort4 uh, ul;
    unsigned short* ph = &uh.x; unsigned short* pl = &ul.x;
#pragma unroll
    for (int i = 0; i < 4; i++) {
        __nv_bfloat16 hh = __float2bfloat16(y[i]);
        __nv_bfloat16 ll = __float2bfloat16(y[i] - __bfloat162float(hh));
        ph[i] = __bfloat16_as_ushort(hh);
        pl[i] = __bfloat16_as_ushort(ll);
    }
    *(ushort4*)(ohi + off) = uh;
    *(ushort4*)(olo + off) = ul;
}

// ------------- V transpose + bf16 hi/lo split -----------------------------------
__global__ void vtrans_kernel(const float* __restrict__ kvlin,
                              __nv_bfloat16* __restrict__ vhi,
                              __nv_bfloat16* __restrict__ vlo) {
    int idx = blockIdx.x * blockDim.x + threadIdx.x;
    const int total = BB * TT * NKV * DH / 4;
    if (idx >= total) return;
    int d4 = idx & (DH / 4 - 1);
    int h = (idx >> 5) & (NKV - 1);
    int t = (idx >> 7) & (TT - 1);
    int b = idx >> 18;
    float4 v = *(const float4*)(kvlin + (size_t)(b * TT + t) * KVC + NKV * DH + h * DH + d4 * 4);
    float vv[4] = {v.x, v.y, v.z, v.w};
    ushort4 uh, ul;
    unsigned short* ph = &uh.x; unsigned short* pl = &ul.x;
#pragma unroll
    for (int j = 0; j < 4; j++) {
        __nv_bfloat16 hh = __float2bfloat16(vv[j]);
        __nv_bfloat16 ll = __float2bfloat16(vv[j] - __bfloat162float(hh));
        ph[j] = __bfloat16_as_ushort(hh);
        pl[j] = __bfloat16_as_ushort(ll);
    }
    size_t off = ((size_t)(b * NKV + h) * TT + t) * DH + d4 * 4;
    *(ushort4*)(vhi + off) = uh;
    *(ushort4*)(vlo + off) = ul;
}

// ================= HMMA flash attention: 128q x 64k, 8 warps ====================
// smem: Q hi/lo resident (64KB), K/V hi/lo double-buffered (2x64KB) = 192KB.
// qt REVERSED (heavy blocks launch first -> shorter tail).
#define FQ 128
#define FK 64
#define FHALF_Q 16384
#define FHALF_KV 8192
#define FSM_QH 0
#define FSM_QL 32768
#define FSM_KV0 65536
#define FSTAGE 65536
#define FLASH_SMEM 196608

__global__ void __launch_bounds__(256) flash_hmma(
        const __nv_bfloat16* __restrict__ qhi, const __nv_bfloat16* __restrict__ qlo,
        const __nv_bfloat16* __restrict__ khi, const __nv_bfloat16* __restrict__ klo,
        const __nv_bfloat16* __restrict__ vhi, const __nv_bfloat16* __restrict__ vlo,
        __nv_bfloat16* __restrict__ ahi, __nv_bfloat16* __restrict__ alo) {
    const int tid = threadIdx.x, wid = tid >> 5, lane = tid & 31;
    const int qt = gridDim.x - 1 - blockIdx.x;   // heavy (large-qt) blocks first
    const int h = blockIdx.y, b = blockIdx.z;
    const int kvh = h >> 2;
    uint32_t sb = smem_to_u32(gsm);

    const __nv_bfloat16* Qh_g = qhi + ((size_t)(b * NH + h) * TT + qt * FQ) * DH;
    const __nv_bfloat16* Ql_g = qlo + ((size_t)(b * NH + h) * TT + qt * FQ) * DH;
    const __nv_bfloat16* Kh_g = khi + (size_t)(b * NKV + kvh) * TT * DH;
    const __nv_bfloat16* Kl_g = klo + (size_t)(b * NKV + kvh) * TT * DH;
    const __nv_bfloat16* Vh_g = vhi + (size_t)(b * NKV + kvh) * TT * DH;
    const __nv_bfloat16* Vl_g = vlo + (size_t)(b * NKV + kvh) * TT * DH;

    {
        const __nv_bfloat16* srcs[2] = {Qh_g, Ql_g};
        const uint32_t dsts[2] = {FSM_QH, FSM_QL};
#pragma unroll
        for (int a = 0; a < 2; a++)
#pragma unroll
            for (int i = 0; i < 8; i++) {
                int idx = tid + i * 256;
                int hf = idx >> 10, r = (idx >> 3) & 127, cg = idx & 7;
                CP_ASYNC16(sb + dsts[a] + hf * FHALF_Q + SWZ((uint32_t)(r * 128 + cg * 16)),
                           srcs[a] + (size_t)r * DH + hf * 64 + cg * 8);
            }
    }
    auto cp_kv = [&](int stage, int kt2) {
        uint32_t dstb = sb + FSM_KV0 + stage * FSTAGE;
        const __nv_bfloat16* srcs[4] = {Kh_g, Kl_g, Vh_g, Vl_g};
#pragma unroll
        for (int a = 0; a < 4; a++) {
            const __nv_bfloat16* src = srcs[a] + (size_t)kt2 * FK * DH;
#pragma unroll
            for (int i = 0; i < 4; i++) {
                int idx = tid + i * 256;
                int hf = idx >> 9, r = (idx >> 3) & 63, cg = idx & 7;
                CP_ASYNC16(dstb + a * 16384 + hf * FHALF_KV + SWZ((uint32_t)(r * 128 + cg * 16)),
                           src + (size_t)r * DH + hf * 64 + cg * 8);
            }
        }
    };
    cp_kv(0, 0);
    CP_COMMIT();

    const int ntiles = 2 * qt + 2;
    const int grow_lo = qt * FQ + wid * 16 + (lane >> 2);
    const float scl = 0.08838834764831845f;

    float m_lo = -1e30f, m_hi = -1e30f, l_lo = 0.f, l_hi = 0.f;
    float o[16][4];
#pragma unroll
    for (int n = 0; n < 16; n++)
#pragma unroll
        for (int q = 0; q < 4; q++) o[n][q] = 0.f;

    for (int kt = 0; kt < ntiles; kt++) {
        CP_WAIT(0);
        __syncthreads();
        if (kt + 1 < ntiles) { cp_kv((kt + 1) & 1, kt + 1); CP_COMMIT(); }

        uint32_t kvb = sb + FSM_KV0 + (kt & 1) * FSTAGE;
        uint32_t smKh = kvb, smKl = kvb + 16384, smVh = kvb + 32768, smVl = kvb + 49152;

        // ---- S = Q K^T (bf16x3) ----
        float s[8][4];
#pragma unroll
        for (int n = 0; n < 8; n++)
#pragma unroll
            for (int q = 0; q < 4; q++) s[n][q] = 0.f;
#pragma unroll
        for (int ks = 0; ks < 8; ks++) {
            int hf = ks >> 2;
            uint32_t colb = (uint32_t)((ks & 3) * 32 + (lane >> 4) * 16);
            uint32_t aoff = SWZ((uint32_t)((wid * 16 + (lane & 15)) * 128) + colb);
            uint32_t aHi[4], aLo[4];
            ldsm_x4(aHi[0], aHi[1], aHi[2], aHi[3], sb + FSM_QH + hf * FHALF_Q + aoff);
            ldsm_x4(aLo[0], aLo[1], aLo[2], aLo[3], sb + FSM_QL + hf * FHALF_Q + aoff);
#pragma unroll
            for (int nt2 = 0; nt2 < 4; nt2++) {
                uint32_t boff = hf * FHALF_KV +
                    SWZ((uint32_t)((nt2 * 16 + (lane & 15)) * 128) + colb);
                uint32_t r0, r1, r2, r3;
                uint32_t bh0[2], bh1[2], bl0[2], bl1[2];
                ldsm_x4(r0, r1, r2, r3, smKh + boff);
                bh0[0] = r0; bh0[1] = r2; bh1[0] = r1; bh1[1] = r3;
                ldsm_x4(r0, r1, r2, r3, smKl + boff);
                bl0[0] = r0; bl0[1] = r2; bl1[0] = r1; bl1[1] = r3;
                mma_bf16(s[2 * nt2], aHi, bh0);
                mma_bf16(s[2 * nt2], aHi, bl0);
                mma_bf16(s[2 * nt2], aLo, bh0);
                mma_bf16(s[2 * nt2 + 1], aHi, bh1);
                mma_bf16(s[2 * nt2 + 1], aHi, bl1);
                mma_bf16(s[2 * nt2 + 1], aLo, bh1);
            }
        }

        // ---- mask + online softmax ----
        float mx_lo = -1e30f, mx_hi = -1e30f;
#pragma unroll
        for (int nt = 0; nt < 8; nt++)
#pragma unroll
            for (int j = 0; j < 2; j++) {
                int gc = kt * FK + nt * 8 + (lane & 3) * 2 + j;
                s[nt][j]     = (gc <= grow_lo)     ? s[nt][j] * scl     : -1e30f;
                s[nt][j + 2] = (gc <= grow_lo + 8) ? s[nt][j + 2] * scl : -1e30f;
                mx_lo = fmaxf(mx_lo, s[nt][j]);
                mx_hi = fmaxf(mx_hi, s[nt][j + 2]);
            }
        mx_lo = fmaxf(mx_lo, __shfl_xor_sync(0xffffffffu, mx_lo, 1));
        mx_lo = fmaxf(mx_lo, __shfl_xor_sync(0xffffffffu, mx_lo, 2));
        mx_hi = fmaxf(mx_hi, __shfl_xor_sync(0xffffffffu, mx_hi, 1));
        mx_hi = fmaxf(mx_hi, __shfl_xor_sync(0xffffffffu, mx_hi, 2));
        float mn_lo = fmaxf(m_lo, mx_lo), mn_hi = fmaxf(m_hi, mx_hi);
        float cr_lo = __expf(m_lo - mn_lo), cr_hi = __expf(m_hi - mn_hi);
        m_lo = mn_lo; m_hi = mn_hi;
        float rs_lo = 0.f, rs_hi = 0.f;
#pragma unroll
        for (int nt = 0; nt < 8; nt++)
#pragma unroll
            for (int j = 0; j < 2; j++) {
                s[nt][j] = __expf(s[nt][j] - mn_lo);
                s[nt][j + 2] = __expf(s[nt][j + 2] - mn_hi);
                rs_lo += s[nt][j];
                rs_hi += s[nt][j + 2];
            }
        rs_lo += __shfl_xor_sync(0xffffffffu, rs_lo, 1);
        rs_lo += __shfl_xor_sync(0xffffffffu, rs_lo, 2);
        rs_hi += __shfl_xor_sync(0xffffffffu, rs_hi, 1);
        rs_hi += __shfl_xor_sync(0xffffffffu, rs_hi, 2);
        l_lo = l_lo * cr_lo + rs_lo;
        l_hi = l_hi * cr_hi + rs_hi;
#pragma unroll
        for (int n = 0; n < 16; n++) {
            o[n][0] *= cr_lo; o[n][1] *= cr_lo;
            o[n][2] *= cr_hi; o[n][3] *= cr_hi;
        }

        // ---- P C-frags -> A-frags (hi/lo) ----
        uint32_t aPh[4][4], aPl[4][4];
#pragma unroll
        for (int kc = 0; kc < 4; kc++) {
            float* c0 = s[2 * kc];
            float* c1 = s[2 * kc + 1];
            float v00 = c0[0], v01 = c0[1], v02 = c0[2], v03 = c0[3];
            float v10 = c1[0], v11 = c1[1], v12 = c1[2], v13 = c1[3];
            uint32_t h00 = packbf2(v00, v01);
            uint32_t h01 = packbf2(v02, v03);
            uint32_t h10 = packbf2(v10, v11);
            uint32_t h11 = packbf2(v12, v13);
            aPh[kc][0] = h00; aPh[kc][1] = h01; aPh[kc][2] = h10; aPh[kc][3] = h11;
            __nv_bfloat162 t;
            t = *(__nv_bfloat162*)&h00;
            aPl[kc][0] = packbf2(v00 - __bfloat162float(t.x), v01 - __bfloat162float(t.y));
            t = *(__nv_bfloat162*)&h01;
            aPl[kc][1] = packbf2(v02 - __bfloat162float(t.x), v03 - __bfloat162float(t.y));
            t = *(__nv_bfloat162*)&h10;
            aPl[kc][2] = packbf2(v10 - __bfloat162float(t.x), v11 - __bfloat162float(t.y));
            t = *(__nv_bfloat162*)&h11;
            aPl[kc][3] = packbf2(v12 - __bfloat162float(t.x), v13 - __bfloat162float(t.y));
        }

        // ---- O += P V (bf16x3) ----
#pragma unroll
        for (int kc = 0; kc < 4; kc++) {
#pragma unroll
            for (int hf = 0; hf < 2; hf++)
#pragma unroll
                for (int dt = 0; dt < 4; dt++) {
                    uint32_t voff = hf * FHALF_KV +
                        SWZ((uint32_t)((kc * 16 + (lane & 15)) * 128 +
                                       dt * 32 + (lane >> 4) * 16));
                    uint32_t r0, r1, r2, r3;
                    uint32_t bh0[2], bh1[2], bl0[2], bl1[2];
                    ldsm_x4_t(r0, r1, r2, r3, smVh + voff);
                    bh0[0] = r0; bh0[1] = r1; bh1[0] = r2; bh1[1] = r3;
                    ldsm_x4_t(r0, r1, r2, r3, smVl + voff);
                    bl0[0] = r0; bl0[1] = r1; bl1[0] = r2; bl1[1] = r3;
                    int n = hf * 8 + dt * 2;
                    mma_bf16(o[n], aPh[kc], bh0);
                    mma_bf16(o[n], aPh[kc], bl0);
                    mma_bf16(o[n], aPl[kc], bh0);
                    mma_bf16(o[n + 1], aPh[kc], bh1);
                    mma_bf16(o[n + 1], aPh[kc], bl1);
                    mma_bf16(o[n + 1], aPl[kc], bh1);
                }
        }
    }

    // ---- epilogue ----
    float li_lo = 1.0f / l_lo, li_hi = 1.0f / l_hi;
    int t_lo = qt * FQ + wid * 16 + (lane >> 2);
    size_t base_lo = ((size_t)b * TT + t_lo) * CC + h * DH;
    size_t base_hi = base_lo + (size_t)8 * CC;
#pragma unroll
    for (int n = 0; n < 16; n++) {
        int d = n * 8 + (lane & 3) * 2;
        float v0 = o[n][0] * li_lo, v1 = o[n][1] * li_lo;
        float v2 = o[n][2] * li_hi, v3 = o[n][3] * li_hi;
        uint32_t h01 = packbf2(v0, v1);
        __nv_bfloat162 t = *(__nv_bfloat162*)&h01;
        uint32_t l01 = packbf2(v0 - __bfloat162float(t.x), v1 - __bfloat162float(t.y));
        uint32_t h23 = packbf2(v2, v3);
        t = *(__nv_bfloat162*)&h23;
        uint32_t l23 = packbf2(v2 - __bfloat162float(t.x), v3 - __bfloat162float(t.y));
        *(uint32_t*)(ahi + base_lo + d) = h01;
        *(uint32_t*)(alo + base_lo + d) = l01;
        *(uint32_t*)(ahi + base_hi + d) = h23;
        *(uint32_t*)(alo + base_hi + d) = l23;
    }
}

// ------------- tail zero --------------------------------------------------------
__global__ void tailzero_kernel(float* out, int start, int total) {
    int i = start + blockIdx.x * blockDim.x + threadIdx.x;
    if (i < total) out[i] = 0.f;
}

// ------------- launcher --------------------------------------------------------
extern "C" void kernel_launch(void* const* d_in, const int* in_sizes, int n_in,
                              void* d_out, int out_size) {
    const float* x     = (const float*)d_in[0];
    const float* Wq    = (const float*)d_in[1];
    const float* Wkv   = (const float*)d_in[2];
    const float* Wproj = (const float*)d_in[3];
    float* out = (float*)d_out;

    float *qlin, *kvlin;
    __nv_bfloat16 *qhi, *qlo, *khi, *klo, *vhi, *vlo;
    __nv_bfloat16 *xhi, *xlo, *wqhi, *wqlo, *wkvhi, *wkvlo, *wphi, *wplo, *ahi, *alo;
    cudaGetSymbolAddress((void**)&qlin, g_qlin);
    cudaGetSymbolAddress((void**)&kvlin, g_kvlin);
    cudaGetSymbolAddress((void**)&qhi, g_qhi);   cudaGetSymbolAddress((void**)&qlo, g_qlo);
    cudaGetSymbolAddress((void**)&khi, g_khi);   cudaGetSymbolAddress((void**)&klo, g_klo);
    cudaGetSymbolAddress((void**)&vhi, g_vhi);   cudaGetSymbolAddress((void**)&vlo, g_vlo);
    cudaGetSymbolAddress((void**)&xhi, g_xhi);   cudaGetSymbolAddress((void**)&xlo, g_xlo);
    cudaGetSymbolAddress((void**)&wqhi, g_wqhi); cudaGetSymbolAddress((void**)&wqlo, g_wqlo);
    cudaGetSymbolAddress((void**)&wkvhi, g_wkvhi); cudaGetSymbolAddress((void**)&wkvlo, g_wkvlo);
    cudaGetSymbolAddress((void**)&wphi, g_wphi); cudaGetSymbolAddress((void**)&wplo, g_wplo);
    cudaGetSymbolAddress((void**)&ahi, g_ahi);   cudaGetSymbolAddress((void**)&alo, g_alo);

    cudaFuncSetAttribute(gemm_mma, cudaFuncAttributeMaxDynamicSharedMemorySize, GT_SMEM);
    cudaFuncSetAttribute(flash_hmma, cudaFuncAttributeMaxDynamicSharedMemorySize, FLASH_SMEM);

    // 0) split fp32 operands into bf16 hi/lo
    {
        int n4;
        n4 = BT * CC / 4;  split_kernel<<<(n4 + 255) / 256, 256>>>(x, xhi, xlo, n4);
        n4 = CC * CC / 4;  split_kernel<<<(n4 + 255) / 256, 256>>>(Wq, wqhi, wqlo, n4);
        n4 = KVC * CC / 4; split_kernel<<<(n4 + 255) / 256, 256>>>(Wkv, wkvhi, wkvlo, n4);
        n4 = CC * CC / 4;  split_kernel<<<(n4 + 255) / 256, 256>>>(Wproj, wphi, wplo, n4);
    }
    // 1+2) fused [Q | KV] = x @ [Wq | Wkv]^T
    {
        dim3 g(CC / 64 + KVC / 64, BT / 128);   // 48 x 32
        gemm_mma<<<g, 256, GT_SMEM>>>(xhi, xlo,
                                      wqhi, wqlo, qlin, CC, CC / 64,
                                      wkvhi, wkvlo, kvlin, KVC, CC);
    }
    // 3) RMSNorm + RoPE on Q -> bf16 hi/lo [b,h,t,d]
    {
        int rows = BB * TT * NH;
        normrope_kernel<<<(rows * 32 + 255) / 256, 256>>>(qlin, qhi, qlo, CC, NH);
    }
    // 4) RMSNorm + RoPE on K -> bf16 hi/lo [b,kvh,t,d]
    {
        int rows = BB * TT * NKV;
        normrope_kernel<<<(rows * 32 + 255) / 256, 256>>>(kvlin, khi, klo, KVC, NKV);
    }
    // 5) V transpose + split -> bf16 hi/lo [b,kvh,t,d]
    {
        int total = BB * TT * NKV * DH / 4;
        vtrans_kernel<<<(total + 255) / 256, 256>>>(kvlin, vhi, vlo);
    }
    // 6) HMMA flash attention -> ahi/alo
    {
        dim3 g(TT / FQ, NH, BB);
        flash_hmma<<<g, 256, FLASH_SMEM>>>(qhi, qlo, khi, klo, vhi, vlo, ahi, alo);
    }
    // 7) y = attn @ Wproj^T
    {
        dim3 g(CC / 64, BT / 128);
        gemm_mma<<<g, 256, GT_SMEM>>>(ahi, alo,
                                      wphi, wplo, out, CC, CC / 64,
                                      wphi, wplo, out, CC, CC);
    }
    // 8) trailing scalar output
    {
        int btc = BB * TT * CC;
        if (out_size > btc) {
            int rem = out_size - btc;
            tailzero_kernel<<<(rem + 255) / 256, 256>>>(out, btc, out_size);
        }
    }
}

// round 14
// speedup vs baseline: 3.4315x; 1.0230x over previous
#include <cuda_runtime.h>
#include <cuda_bf16.h>
#include <math.h>
#include <stdint.h>

#define BB 2
#define TT 2048
#define CC 2048
#define NH 16
#define NKV 4
#define DH 128
#define BT (BB*TT)          // 4096
#define KVC (2*NKV*DH)      // 1024

// ---------------- scratch (static device globals; no allocation) ----------------
__device__ float g_qlin[BB*TT*CC];
__device__ float g_kvlin[BB*TT*KVC];
__device__ __nv_bfloat16 g_qhi[BB*NH*TT*DH],  g_qlo[BB*NH*TT*DH];
__device__ __nv_bfloat16 g_khi[BB*NKV*TT*DH], g_klo[BB*NKV*TT*DH];
__device__ __nv_bfloat16 g_vhi[BB*NKV*TT*DH], g_vlo[BB*NKV*TT*DH];
__device__ __nv_bfloat16 g_xhi[BT*CC],   g_xlo[BT*CC];
__device__ __nv_bfloat16 g_wqhi[CC*CC],  g_wqlo[CC*CC];
__device__ __nv_bfloat16 g_wkvhi[KVC*CC],g_wkvlo[KVC*CC];
__device__ __nv_bfloat16 g_wphi[CC*CC],  g_wplo[CC*CC];
__device__ __nv_bfloat16 g_ahi[BT*CC],   g_alo[BT*CC];

// ======================= warp-MMA helpers (sm_80+ portable) =====================
__device__ __forceinline__ uint32_t smem_to_u32(const void* p) {
    uint32_t a;
    asm("{ .reg .u64 t; cvta.to.shared.u64 t, %1; cvt.u32.u64 %0, t; }" : "=r"(a) : "l"(p));
    return a;
}
__device__ __forceinline__ void ldsm_x4(uint32_t& r0, uint32_t& r1, uint32_t& r2,
                                        uint32_t& r3, uint32_t addr) {
    asm volatile("ldmatrix.sync.aligned.m8n8.x4.shared.b16 {%0,%1,%2,%3}, [%4];"
                 : "=r"(r0), "=r"(r1), "=r"(r2), "=r"(r3) : "r"(addr));
}
__device__ __forceinline__ void ldsm_x4_t(uint32_t& r0, uint32_t& r1, uint32_t& r2,
                                          uint32_t& r3, uint32_t addr) {
    asm volatile("ldmatrix.sync.aligned.m8n8.x4.trans.shared.b16 {%0,%1,%2,%3}, [%4];"
                 : "=r"(r0), "=r"(r1), "=r"(r2), "=r"(r3) : "r"(addr));
}
__device__ __forceinline__ void mma_bf16(float* d, const uint32_t* a, const uint32_t* b) {
    asm volatile("mma.sync.aligned.m16n8k16.row.col.f32.bf16.bf16.f32 "
                 "{%0,%1,%2,%3}, {%4,%5,%6,%7}, {%8,%9}, {%0,%1,%2,%3};"
                 : "+f"(d[0]), "+f"(d[1]), "+f"(d[2]), "+f"(d[3])
                 : "r"(a[0]), "r"(a[1]), "r"(a[2]), "r"(a[3]), "r"(b[0]), "r"(b[1]));
}
__device__ __forceinline__ uint32_t packbf2(float x, float y) {
    __nv_bfloat162 t = __floats2bfloat162_rn(x, y);
    return *(uint32_t*)&t;
}
#define SWZ(o)   ((o) ^ (((o) >> 3) & 0x70))   // SW128 (128B rows)
#define SWZ64(o) ((o) ^ (((o) >> 3) & 0x30))   // SW64  (64B rows)
#define CP_ASYNC16(dst, src) \
    asm volatile("cp.async.cg.shared.global [%0], [%1], 16;" :: "r"(dst), "l"(src))
#define CP_COMMIT() asm volatile("cp.async.commit_group;" ::: "memory")
#define CP_WAIT(n)  asm volatile("cp.async.wait_group %0;" :: "n"(n) : "memory")

// ================= HMMA GEMM: C[M,N] fp32 = A[M,K] @ B[N,K]^T ===================
// bf16x3 split. CTA tile 128x64, 8 warps (4M x 2N), warp tile 32x32, K-chunk 32.
// 3-stage cp.async, 24KB/stage = 72KB smem -> 2 CTAs/SM (16 warps/SM).
#define GT_KC 32
#define GT_AT 8192
#define GT_BT 4096
#define GT_STAGEB 24576
#define GT_SMEM (3*GT_STAGEB)   // 73728

extern __shared__ char gsm[];

__global__ void __launch_bounds__(256, 2) gemm_mma(
        const __nv_bfloat16* __restrict__ Ahi, const __nv_bfloat16* __restrict__ Alo,
        const __nv_bfloat16* __restrict__ Bhi1, const __nv_bfloat16* __restrict__ Blo1,
        float* __restrict__ C1, int N1, int nx1,
        const __nv_bfloat16* __restrict__ Bhi2, const __nv_bfloat16* __restrict__ Blo2,
        float* __restrict__ C2, int N2, int K) {
    const int tid = threadIdx.x;
    const int wid = tid >> 5, lane = tid & 31;
    const int wm = wid & 3, wn = wid >> 2;
    const int m0 = blockIdx.y * 128;
    const int NIT = K / GT_KC;
    uint32_t sb = smem_to_u32(gsm);

    const __nv_bfloat16 *Bhi, *Blo; float* C; int N, n0;
    if ((int)blockIdx.x < nx1) {
        Bhi = Bhi1; Blo = Blo1; C = C1; N = N1; n0 = blockIdx.x * 64;
    } else {
        Bhi = Bhi2; Blo = Blo2; C = C2; N = N2; n0 = (blockIdx.x - nx1) * 64;
    }

    float acc[2][4][4];
#pragma unroll
    for (int i = 0; i < 2; i++)
#pragma unroll
        for (int j = 0; j < 4; j++)
#pragma unroll
            for (int q = 0; q < 4; q++) acc[i][j][q] = 0.f;

    auto cp_stage = [&](int stage, int k0) {
        uint32_t st = sb + stage * GT_STAGEB;
        {
            const __nv_bfloat16* srcs[2] = {Ahi, Alo};
#pragma unroll
            for (int a = 0; a < 2; a++)
#pragma unroll
                for (int j = 0; j < 2; j++) {
                    int c = tid + j * 256;
                    int r = c >> 2, cg = c & 3;
                    CP_ASYNC16(st + a * GT_AT + SWZ64((uint32_t)(r * 64 + cg * 16)),
                               srcs[a] + (size_t)(m0 + r) * K + k0 + cg * 8);
                }
        }
        {
            const __nv_bfloat16* srcs[2] = {Bhi, Blo};
#pragma unroll
            for (int a = 0; a < 2; a++) {
                int r = tid >> 2, cg = tid & 3;
                CP_ASYNC16(st + 2 * GT_AT + a * GT_BT + SWZ64((uint32_t)(r * 64 + cg * 16)),
                           srcs[a] + (size_t)(n0 + r) * K + k0 + cg * 8);
            }
        }
    };

    cp_stage(0, 0);
    CP_COMMIT();
    cp_stage(1, GT_KC);
    CP_COMMIT();

    int st_c = 0, st_p = 2;
    for (int it = 0; it < NIT; it++) {
        if (it + 1 < NIT) CP_WAIT(1); else CP_WAIT(0);
        __syncthreads();
        if (it + 2 < NIT) {
            cp_stage(st_p, (it + 2) * GT_KC);
            CP_COMMIT();
        }

        uint32_t stb = sb + st_c * GT_STAGEB;
        uint32_t smAhi = stb, smAlo = stb + GT_AT;
        uint32_t smBhi = stb + 2 * GT_AT, smBlo = stb + 2 * GT_AT + GT_BT;

#pragma unroll
        for (int ks = 0; ks < 2; ks++) {
            uint32_t colb = (uint32_t)(ks * 32 + (lane >> 4) * 16);
            uint32_t aHi[2][4], aLo[2][4];
#pragma unroll
            for (int mt = 0; mt < 2; mt++) {
                uint32_t so = SWZ64((uint32_t)((wm * 32 + mt * 16 + (lane & 15)) * 64) + colb);
                ldsm_x4(aHi[mt][0], aHi[mt][1], aHi[mt][2], aHi[mt][3], smAhi + so);
                ldsm_x4(aLo[mt][0], aLo[mt][1], aLo[mt][2], aLo[mt][3], smAlo + so);
            }
            uint32_t bHi[4][2], bLo[4][2];
#pragma unroll
            for (int nt2 = 0; nt2 < 2; nt2++) {
                uint32_t so = SWZ64((uint32_t)((wn * 32 + nt2 * 16 + (lane & 15)) * 64) + colb);
                uint32_t r0, r1, r2, r3;
                ldsm_x4(r0, r1, r2, r3, smBhi + so);
                bHi[2 * nt2][0] = r0; bHi[2 * nt2][1] = r2;
                bHi[2 * nt2 + 1][0] = r1; bHi[2 * nt2 + 1][1] = r3;
                ldsm_x4(r0, r1, r2, r3, smBlo + so);
                bLo[2 * nt2][0] = r0; bLo[2 * nt2][1] = r2;
                bLo[2 * nt2 + 1][0] = r1; bLo[2 * nt2 + 1][1] = r3;
            }
#pragma unroll
            for (int mt = 0; mt < 2; mt++)
#pragma unroll
                for (int nt = 0; nt < 4; nt++) {
                    mma_bf16(acc[mt][nt], aHi[mt], bHi[nt]);
                    mma_bf16(acc[mt][nt], aHi[mt], bLo[nt]);
                    mma_bf16(acc[mt][nt], aLo[mt], bHi[nt]);
                }
        }
        st_c = (st_c == 2) ? 0 : st_c + 1;
        st_p = (st_p == 2) ? 0 : st_p + 1;
    }

#pragma unroll
    for (int mt = 0; mt < 2; mt++) {
        int row = m0 + wm * 32 + mt * 16 + (lane >> 2);
#pragma unroll
        for (int nt = 0; nt < 4; nt++) {
            int col = n0 + wn * 32 + nt * 8 + 2 * (lane & 3);
            *(float2*)(C + (size_t)row * N + col) =
                make_float2(acc[mt][nt][0], acc[mt][nt][1]);
            *(float2*)(C + (size_t)(row + 8) * N + col) =
                make_float2(acc[mt][nt][2], acc[mt][nt][3]);
        }
    }
}

// =================== fp32 -> bf16 hi/lo split (elementwise) =====================
__global__ void split_kernel(const float* __restrict__ in, __nv_bfloat16* __restrict__ hi,
                             __nv_bfloat16* __restrict__ lo, int n4) {
    int i = blockIdx.x * blockDim.x + threadIdx.x;
    if (i >= n4) return;
    float4 v = ((const float4*)in)[i];
    float vv[4] = {v.x, v.y, v.z, v.w};
    ushort4 uh, ul;
    unsigned short* ph = &uh.x; unsigned short* pl = &ul.x;
#pragma unroll
    for (int j = 0; j < 4; j++) {
        __nv_bfloat16 h = __float2bfloat16(vv[j]);
        __nv_bfloat16 l = __float2bfloat16(vv[j] - __bfloat162float(h));
        ph[j] = __bfloat16_as_ushort(h);
        pl[j] = __bfloat16_as_ushort(l);
    }
    ((ushort4*)hi)[i] = uh;
    ((ushort4*)lo)[i] = ul;
}

// ------------- fused RMSNorm + rotary -> bf16 hi/lo (position = HEAD index) -----
__global__ void normrope_kernel(const float* __restrict__ in,
                                __nv_bfloat16* __restrict__ ohi,
                                __nv_bfloat16* __restrict__ olo,
                                int rowstride, int nheads) {
    int w = (blockIdx.x * blockDim.x + threadIdx.x) >> 5;
    int lane = threadIdx.x & 31;
    int total = BB * TT * nheads;
    if (w >= total) return;
    int h = w % nheads;
    int t = (w / nheads) % TT;
    int b = w / (nheads * TT);

    const float* src = in + (size_t)(b * TT + t) * rowstride + h * DH;
    float4 v = *(const float4*)(src + lane * 4);
    float ss = v.x * v.x + v.y * v.y + v.z * v.z + v.w * v.w;
#pragma unroll
    for (int o = 16; o; o >>= 1) ss += __shfl_xor_sync(0xffffffffu, ss, o);
    float scale = rsqrtf(ss * (1.0f / 128.0f) + 1.1920929e-07f);

    float x[4] = {v.x * scale, v.y * scale, v.z * scale, v.w * scale};
    float y[4];
#pragma unroll
    for (int i = 0; i < 4; i++) {
        float part = __shfl_xor_sync(0xffffffffu, x[i], 16);
        int d = lane * 4 + i;
        int j = d & 63;
        float freq = (j < 32) ? powf(1.0f / 1024.0f, (float)j * (1.0f / 31.0f)) : 0.0f;
        float s, c;
        sincosf((float)h * freq, &s, &c);
        if (d < 64) y[i] = x[i] * c + part * s;
        else        y[i] = -part * s + x[i] * c;
    }
    size_t off = ((size_t)(b * nheads + h) * TT + t) * DH + lane * 4;
    ushort4 uh, ul;
    unsigned short* ph = &uh.x; unsigned short* pl = &ul.x;
#pragma unroll
    for (int i = 0; i < 4; i++) {
        __nv_bfloat16 hh = __float2bfloat16(y[i]);
        __nv_bfloat16 ll = __float2bfloat16(y[i] - __bfloat162float(hh));
        ph[i] = __bfloat16_as_ushort(hh);
        pl[i] = __bfloat16_as_ushort(ll);
    }
    *(ushort4*)(ohi + off) = uh;
    *(ushort4*)(olo + off) = ul;
}

// ------------- V transpose + bf16 hi/lo split -----------------------------------
__global__ void vtrans_kernel(const float* __restrict__ kvlin,
                              __nv_bfloat16* __restrict__ vhi,
                              __nv_bfloat16* __restrict__ vlo) {
    int idx = blockIdx.x * blockDim.x + threadIdx.x;
    const int total = BB * TT * NKV * DH / 4;
    if (idx >= total) return;
    int d4 = idx & (DH / 4 - 1);
    int h = (idx >> 5) & (NKV - 1);
    int t = (idx >> 7) & (TT - 1);
    int b = idx >> 18;
    float4 v = *(const float4*)(kvlin + (size_t)(b * TT + t) * KVC + NKV * DH + h * DH + d4 * 4);
    float vv[4] = {v.x, v.y, v.z, v.w};
    ushort4 uh, ul;
    unsigned short* ph = &uh.x; unsigned short* pl = &ul.x;
#pragma unroll
    for (int j = 0; j < 4; j++) {
        __nv_bfloat16 hh = __float2bfloat16(vv[j]);
        __nv_bfloat16 ll = __float2bfloat16(vv[j] - __bfloat162float(hh));
        ph[j] = __bfloat16_as_ushort(hh);
        pl[j] = __bfloat16_as_ushort(ll);
    }
    size_t off = ((size_t)(b * NKV + h) * TT + t) * DH + d4 * 4;
    *(ushort4*)(vhi + off) = uh;
    *(ushort4*)(vlo + off) = ul;
}

// ============ HMMA flash v2: 128q x 64k, 16 warps (warp-pair k-split) ===========
// Static-max softmax: scores bounded by sqrt(128)=11.32 < 12 (RMS-normed q,k),
// so p = exp(s - 12) needs NO running max / corrections; partial O and l are
// order-independent and warp-pairs combine once at the epilogue.
// warp w: q-rows 16*(w&7), k-half 32*(w>>3) of each 64-wide k-tile.
#define FQ 128
#define FK 64
#define FHALF_Q 16384
#define FHALF_KV 8192
#define FSM_QH 0
#define FSM_QL 32768
#define FSM_KV0 65536
#define FSTAGE 65536
#define FLASH_SMEM 196608
#define FTHREADS 512

__global__ void __launch_bounds__(FTHREADS) flash_hmma(
        const __nv_bfloat16* __restrict__ qhi, const __nv_bfloat16* __restrict__ qlo,
        const __nv_bfloat16* __restrict__ khi, const __nv_bfloat16* __restrict__ klo,
        const __nv_bfloat16* __restrict__ vhi, const __nv_bfloat16* __restrict__ vlo,
        __nv_bfloat16* __restrict__ ahi, __nv_bfloat16* __restrict__ alo) {
    const int tid = threadIdx.x, wid = tid >> 5, lane = tid & 31;
    const int qw = wid & 7;          // q-row group (16 rows)
    const int kh = wid >> 3;         // k-half (0: cols 0-31, 1: cols 32-63)
    const int qt = gridDim.x - 1 - blockIdx.x;   // heavy blocks first
    const int h = blockIdx.y, b = blockIdx.z;
    const int kvh = h >> 2;
    uint32_t sb = smem_to_u32(gsm);

    const __nv_bfloat16* Qh_g = qhi + ((size_t)(b * NH + h) * TT + qt * FQ) * DH;
    const __nv_bfloat16* Ql_g = qlo + ((size_t)(b * NH + h) * TT + qt * FQ) * DH;
    const __nv_bfloat16* Kh_g = khi + (size_t)(b * NKV + kvh) * TT * DH;
    const __nv_bfloat16* Kl_g = klo + (size_t)(b * NKV + kvh) * TT * DH;
    const __nv_bfloat16* Vh_g = vhi + (size_t)(b * NKV + kvh) * TT * DH;
    const __nv_bfloat16* Vl_g = vlo + (size_t)(b * NKV + kvh) * TT * DH;

    // Q hi/lo -> smem (64KB); grouped with kv(0) into commit group 0
    {
        const __nv_bfloat16* srcs[2] = {Qh_g, Ql_g};
        const uint32_t dsts[2] = {FSM_QH, FSM_QL};
#pragma unroll
        for (int a = 0; a < 2; a++)
#pragma unroll
            for (int i = 0; i < 4; i++) {
                int idx = tid + i * FTHREADS;   // 0..2047
                int hf = idx >> 10, r = (idx >> 3) & 127, cg = idx & 7;
                CP_ASYNC16(sb + dsts[a] + hf * FHALF_Q + SWZ((uint32_t)(r * 128 + cg * 16)),
                           srcs[a] + (size_t)r * DH + hf * 64 + cg * 8);
            }
    }
    // K/V hi/lo tile -> smem: each tile = 64 rows x 2 halves x 8 chunks = 1024
    // chunks of 16B; 512 threads x 2 iterations covers it (FIX: was 1 iteration,
    // leaving the hf=1 half uninitialized -> NaN).
    auto cp_kv = [&](int stage, int kt2) {
        uint32_t dstb = sb + FSM_KV0 + stage * FSTAGE;
        const __nv_bfloat16* srcs[4] = {Kh_g, Kl_g, Vh_g, Vl_g};
#pragma unroll
        for (int a = 0; a < 4; a++) {
            const __nv_bfloat16* src = srcs[a] + (size_t)kt2 * FK * DH;
#pragma unroll
            for (int i = 0; i < 2; i++) {
                int idx = tid + i * FTHREADS;   // 0..1023
                int hf = idx >> 9, r = (idx >> 3) & 63, cg = idx & 7;
                CP_ASYNC16(dstb + a * 16384 + hf * FHALF_KV + SWZ((uint32_t)(r * 128 + cg * 16)),
                           src + (size_t)r * DH + hf * 64 + cg * 8);
            }
        }
    };
    cp_kv(0, 0);
    CP_COMMIT();

    const int ntiles = 2 * qt + 2;
    const int grow_lo = qt * FQ + qw * 16 + (lane >> 2);
    const float scl = 0.08838834764831845f;   // 1/sqrt(128)
    const float SMAX = 12.0f;                 // static max bound (scores <= 11.32)

    float l_lo = 0.f, l_hi = 0.f;
    float o[16][4];
#pragma unroll
    for (int n = 0; n < 16; n++)
#pragma unroll
        for (int q = 0; q < 4; q++) o[n][q] = 0.f;

    for (int kt = 0; kt < ntiles; kt++) {
        CP_WAIT(0);
        __syncthreads();
        if (kt + 1 < ntiles) { cp_kv((kt + 1) & 1, kt + 1); CP_COMMIT(); }

        uint32_t kvb = sb + FSM_KV0 + (kt & 1) * FSTAGE;
        uint32_t smKh = kvb, smKl = kvb + 16384, smVh = kvb + 32768, smVl = kvb + 49152;

        // ---- S = Q K^T (bf16x3), this warp's 16 rows x 32 cols ----
        float s[4][4];
#pragma unroll
        for (int n = 0; n < 4; n++)
#pragma unroll
            for (int q = 0; q < 4; q++) s[n][q] = 0.f;
#pragma unroll
        for (int ks = 0; ks < 8; ks++) {
            int hf = ks >> 2;
            uint32_t colb = (uint32_t)((ks & 3) * 32 + (lane >> 4) * 16);
            uint32_t aoff = SWZ((uint32_t)((qw * 16 + (lane & 15)) * 128) + colb);
            uint32_t aHi[4], aLo[4];
            ldsm_x4(aHi[0], aHi[1], aHi[2], aHi[3], sb + FSM_QH + hf * FHALF_Q + aoff);
            ldsm_x4(aLo[0], aLo[1], aLo[2], aLo[3], sb + FSM_QL + hf * FHALF_Q + aoff);
#pragma unroll
            for (int nt2 = 0; nt2 < 2; nt2++) {
                uint32_t boff = hf * FHALF_KV +
                    SWZ((uint32_t)((kh * 32 + nt2 * 16 + (lane & 15)) * 128) + colb);
                uint32_t r0, r1, r2, r3;
                uint32_t bh0[2], bh1[2], bl0[2], bl1[2];
                ldsm_x4(r0, r1, r2, r3, smKh + boff);
                bh0[0] = r0; bh0[1] = r2; bh1[0] = r1; bh1[1] = r3;
                ldsm_x4(r0, r1, r2, r3, smKl + boff);
                bl0[0] = r0; bl0[1] = r2; bl1[0] = r1; bl1[1] = r3;
                mma_bf16(s[2 * nt2], aHi, bh0);
                mma_bf16(s[2 * nt2], aHi, bl0);
                mma_bf16(s[2 * nt2], aLo, bh0);
                mma_bf16(s[2 * nt2 + 1], aHi, bh1);
                mma_bf16(s[2 * nt2 + 1], aHi, bl1);
                mma_bf16(s[2 * nt2 + 1], aLo, bh1);
            }
        }

        // ---- mask + static-max exp; accumulate l ----
#pragma unroll
        for (int nt = 0; nt < 4; nt++)
#pragma unroll
            for (int j = 0; j < 2; j++) {
                int gc = kt * FK + kh * 32 + nt * 8 + (lane & 3) * 2 + j;
                float p0 = __expf(s[nt][j] * scl - SMAX);
                float p1 = __expf(s[nt][j + 2] * scl - SMAX);
                s[nt][j]     = (gc <= grow_lo)     ? p0 : 0.f;
                s[nt][j + 2] = (gc <= grow_lo + 8) ? p1 : 0.f;
                l_lo += s[nt][j];
                l_hi += s[nt][j + 2];
            }

        // ---- P C-frags -> A-frags (hi/lo), 2 k16 chunks ----
        uint32_t aPh[2][4], aPl[2][4];
#pragma unroll
        for (int kc = 0; kc < 2; kc++) {
            float* c0 = s[2 * kc];
            float* c1 = s[2 * kc + 1];
            uint32_t h00 = packbf2(c0[0], c0[1]);
            uint32_t h01 = packbf2(c0[2], c0[3]);
            uint32_t h10 = packbf2(c1[0], c1[1]);
            uint32_t h11 = packbf2(c1[2], c1[3]);
            aPh[kc][0] = h00; aPh[kc][1] = h01; aPh[kc][2] = h10; aPh[kc][3] = h11;
            __nv_bfloat162 t;
            t = *(__nv_bfloat162*)&h00;
            aPl[kc][0] = packbf2(c0[0] - __bfloat162float(t.x), c0[1] - __bfloat162float(t.y));
            t = *(__nv_bfloat162*)&h01;
            aPl[kc][1] = packbf2(c0[2] - __bfloat162float(t.x), c0[3] - __bfloat162float(t.y));
            t = *(__nv_bfloat162*)&h10;
            aPl[kc][2] = packbf2(c1[0] - __bfloat162float(t.x), c1[1] - __bfloat162float(t.y));
            t = *(__nv_bfloat162*)&h11;
            aPl[kc][3] = packbf2(c1[2] - __bfloat162float(t.x), c1[3] - __bfloat162float(t.y));
        }

        // ---- O += P V (bf16x3), this warp's k-range rows of V ----
#pragma unroll
        for (int kc = 0; kc < 2; kc++) {
#pragma unroll
            for (int hf = 0; hf < 2; hf++)
#pragma unroll
                for (int dt = 0; dt < 4; dt++) {
                    uint32_t voff = hf * FHALF_KV +
                        SWZ((uint32_t)((kh * 32 + kc * 16 + (lane & 15)) * 128 +
                                       dt * 32 + (lane >> 4) * 16));
                    uint32_t r0, r1, r2, r3;
                    uint32_t bh0[2], bh1[2], bl0[2], bl1[2];
                    ldsm_x4_t(r0, r1, r2, r3, smVh + voff);
                    bh0[0] = r0; bh0[1] = r1; bh1[0] = r2; bh1[1] = r3;
                    ldsm_x4_t(r0, r1, r2, r3, smVl + voff);
                    bl0[0] = r0; bl0[1] = r1; bl1[0] = r2; bl1[1] = r3;
                    int n = hf * 8 + dt * 2;
                    mma_bf16(o[n], aPh[kc], bh0);
                    mma_bf16(o[n], aPh[kc], bl0);
                    mma_bf16(o[n], aPl[kc], bh0);
                    mma_bf16(o[n + 1], aPh[kc], bh1);
                    mma_bf16(o[n + 1], aPh[kc], bl1);
                    mma_bf16(o[n + 1], aPl[kc], bh1);
                }
        }
    }

    // ---- reduce l within quad (rows owned by 4-lane groups) ----
    l_lo += __shfl_xor_sync(0xffffffffu, l_lo, 1);
    l_lo += __shfl_xor_sync(0xffffffffu, l_lo, 2);
    l_hi += __shfl_xor_sync(0xffffffffu, l_hi, 1);
    l_hi += __shfl_xor_sync(0xffffffffu, l_hi, 2);

    // ---- warp-pair combine via smem (reuse KV region) ----
    __syncthreads();   // mainloop smem use complete
    if (kh == 1) {
        if ((lane & 3) == 0) {
            *(float*)(gsm + FSM_KV0 + (qw * 16 + (lane >> 2)) * 4) = l_lo;
            *(float*)(gsm + FSM_KV0 + (qw * 16 + 8 + (lane >> 2)) * 4) = l_hi;
        }
        uint32_t ob = FSM_KV0 + 1024 + qw * 8192;
#pragma unroll
        for (int n = 0; n < 16; n++)
            *(float4*)(gsm + ob + (n * 32 + lane) * 16) =
                make_float4(o[n][0], o[n][1], o[n][2], o[n][3]);
    }
    __syncthreads();
    if (kh == 0) {
        l_lo += *(float*)(gsm + FSM_KV0 + (qw * 16 + (lane >> 2)) * 4);
        l_hi += *(float*)(gsm + FSM_KV0 + (qw * 16 + 8 + (lane >> 2)) * 4);
        uint32_t ob = FSM_KV0 + 1024 + qw * 8192;
#pragma unroll
        for (int n = 0; n < 16; n++) {
            float4 t = *(float4*)(gsm + ob + (n * 32 + lane) * 16);
            o[n][0] += t.x; o[n][1] += t.y; o[n][2] += t.z; o[n][3] += t.w;
        }

        float li_lo = 1.0f / l_lo, li_hi = 1.0f / l_hi;
        int t_lo = qt * FQ + qw * 16 + (lane >> 2);
        size_t base_lo = ((size_t)b * TT + t_lo) * CC + h * DH;
        size_t base_hi = base_lo + (size_t)8 * CC;
#pragma unroll
        for (int n = 0; n < 16; n++) {
            int d = n * 8 + (lane & 3) * 2;
            float v0 = o[n][0] * li_lo, v1 = o[n][1] * li_lo;
            float v2 = o[n][2] * li_hi, v3 = o[n][3] * li_hi;
            uint32_t h01 = packbf2(v0, v1);
            __nv_bfloat162 t = *(__nv_bfloat162*)&h01;
            uint32_t l01 = packbf2(v0 - __bfloat162float(t.x), v1 - __bfloat162float(t.y));
            uint32_t h23 = packbf2(v2, v3);
            t = *(__nv_bfloat162*)&h23;
            uint32_t l23 = packbf2(v2 - __bfloat162float(t.x), v3 - __bfloat162float(t.y));
            *(uint32_t*)(ahi + base_lo + d) = h01;
            *(uint32_t*)(alo + base_lo + d) = l01;
            *(uint32_t*)(ahi + base_hi + d) = h23;
            *(uint32_t*)(alo + base_hi + d) = l23;
        }
    }
}

// ------------- tail zero --------------------------------------------------------
__global__ void tailzero_kernel(float* out, int start, int total) {
    int i = start + blockIdx.x * blockDim.x + threadIdx.x;
    if (i < total) out[i] = 0.f;
}

// ------------- launcher --------------------------------------------------------
extern "C" void kernel_launch(void* const* d_in, const int* in_sizes, int n_in,
                              void* d_out, int out_size) {
    const float* x     = (const float*)d_in[0];
    const float* Wq    = (const float*)d_in[1];
    const float* Wkv   = (const float*)d_in[2];
    const float* Wproj = (const float*)d_in[3];
    float* out = (float*)d_out;

    float *qlin, *kvlin;
    __nv_bfloat16 *qhi, *qlo, *khi, *klo, *vhi, *vlo;
    __nv_bfloat16 *xhi, *xlo, *wqhi, *wqlo, *wkvhi, *wkvlo, *wphi, *wplo, *ahi, *alo;
    cudaGetSymbolAddress((void**)&qlin, g_qlin);
    cudaGetSymbolAddress((void**)&kvlin, g_kvlin);
    cudaGetSymbolAddress((void**)&qhi, g_qhi);   cudaGetSymbolAddress((void**)&qlo, g_qlo);
    cudaGetSymbolAddress((void**)&khi, g_khi);   cudaGetSymbolAddress((void**)&klo, g_klo);
    cudaGetSymbolAddress((void**)&vhi, g_vhi);   cudaGetSymbolAddress((void**)&vlo, g_vlo);
    cudaGetSymbolAddress((void**)&xhi, g_xhi);   cudaGetSymbolAddress((void**)&xlo, g_xlo);
    cudaGetSymbolAddress((void**)&wqhi, g_wqhi); cudaGetSymbolAddress((void**)&wqlo, g_wqlo);
    cudaGetSymbolAddress((void**)&wkvhi, g_wkvhi); cudaGetSymbolAddress((void**)&wkvlo, g_wkvlo);
    cudaGetSymbolAddress((void**)&wphi, g_wphi); cudaGetSymbolAddress((void**)&wplo, g_wplo);
    cudaGetSymbolAddress((void**)&ahi, g_ahi);   cudaGetSymbolAddress((void**)&alo, g_alo);

    cudaFuncSetAttribute(gemm_mma, cudaFuncAttributeMaxDynamicSharedMemorySize, GT_SMEM);
    cudaFuncSetAttribute(flash_hmma, cudaFuncAttributeMaxDynamicSharedMemorySize, FLASH_SMEM);

    // 0) split fp32 operands into bf16 hi/lo
    {
        int n4;
        n4 = BT * CC / 4;  split_kernel<<<(n4 + 255) / 256, 256>>>(x, xhi, xlo, n4);
        n4 = CC * CC / 4;  split_kernel<<<(n4 + 255) / 256, 256>>>(Wq, wqhi, wqlo, n4);
        n4 = KVC * CC / 4; split_kernel<<<(n4 + 255) / 256, 256>>>(Wkv, wkvhi, wkvlo, n4);
        n4 = CC * CC / 4;  split_kernel<<<(n4 + 255) / 256, 256>>>(Wproj, wphi, wplo, n4);
    }
    // 1+2) fused [Q | KV] = x @ [Wq | Wkv]^T
    {
        dim3 g(CC / 64 + KVC / 64, BT / 128);
        gemm_mma<<<g, 256, GT_SMEM>>>(xhi, xlo,
                                      wqhi, wqlo, qlin, CC, CC / 64,
                                      wkvhi, wkvlo, kvlin, KVC, CC);
    }
    // 3) RMSNorm + RoPE on Q -> bf16 hi/lo [b,h,t,d]
    {
        int rows = BB * TT * NH;
        normrope_kernel<<<(rows * 32 + 255) / 256, 256>>>(qlin, qhi, qlo, CC, NH);
    }
    // 4) RMSNorm + RoPE on K -> bf16 hi/lo [b,kvh,t,d]
    {
        int rows = BB * TT * NKV;
        normrope_kernel<<<(rows * 32 + 255) / 256, 256>>>(kvlin, khi, klo, KVC, NKV);
    }
    // 5) V transpose + split -> bf16 hi/lo [b,kvh,t,d]
    {
        int total = BB * TT * NKV * DH / 4;
        vtrans_kernel<<<(total + 255) / 256, 256>>>(kvlin, vhi, vlo);
    }
    // 6) HMMA flash v2 -> ahi/alo
    {
        dim3 g(TT / FQ, NH, BB);
        flash_hmma<<<g, FTHREADS, FLASH_SMEM>>>(qhi, qlo, khi, klo, vhi, vlo, ahi, alo);
    }
    // 7) y = attn @ Wproj^T
    {
        dim3 g(CC / 64, BT / 128);
        gemm_mma<<<g, 256, GT_SMEM>>>(ahi, alo,
                                      wphi, wplo, out, CC, CC / 64,
                                      wphi, wplo, out, CC, CC);
    }
    // 8) trailing scalar output
    {
        int btc = BB * TT * CC;
        if (out_size > btc) {
            int rem = out_size - btc;
            tailzero_kernel<<<(rem + 255) / 256, 256>>>(out, btc, out_size);
        }
    }
}

// round 17
// speedup vs baseline: 4.4112x; 1.2855x over previous
#include <cuda_runtime.h>
#include <cuda_bf16.h>
#include <math.h>
#include <stdint.h>

#define BB 2
#define TT 2048
#define CC 2048
#define NH 16
#define NKV 4
#define DH 128
#define BT (BB*TT)          // 4096
#define KVC (2*NKV*DH)      // 1024

// ---------------- scratch (static device globals; no allocation) ----------------
__device__ float g_qlin[BB*TT*CC];
__device__ float g_kvlin[BB*TT*KVC];
__device__ float g_attn[BB*TT*CC];                 // flash output (tf32-rounded fp32)
__device__ float g_xr[BT*CC];                      // tf32-rounded operands
__device__ float g_wqr[CC*CC];
__device__ float g_wkvr[KVC*CC];
__device__ float g_wpr[CC*CC];
__device__ __nv_bfloat16 g_qhi[BB*NH*TT*DH],  g_qlo[BB*NH*TT*DH];
__device__ __nv_bfloat16 g_khi[BB*NKV*TT*DH], g_klo[BB*NKV*TT*DH];
__device__ __nv_bfloat16 g_vhi[BB*NKV*TT*DH], g_vlo[BB*NKV*TT*DH];

// ======================= warp-MMA helpers (sm_80+ portable) =====================
__device__ __forceinline__ uint32_t smem_to_u32(const void* p) {
    uint32_t a;
    asm("{ .reg .u64 t; cvta.to.shared.u64 t, %1; cvt.u32.u64 %0, t; }" : "=r"(a) : "l"(p));
    return a;
}
__device__ __forceinline__ void ldsm_x4(uint32_t& r0, uint32_t& r1, uint32_t& r2,
                                        uint32_t& r3, uint32_t addr) {
    asm volatile("ldmatrix.sync.aligned.m8n8.x4.shared.b16 {%0,%1,%2,%3}, [%4];"
                 : "=r"(r0), "=r"(r1), "=r"(r2), "=r"(r3) : "r"(addr));
}
__device__ __forceinline__ void ldsm_x4_t(uint32_t& r0, uint32_t& r1, uint32_t& r2,
                                          uint32_t& r3, uint32_t addr) {
    asm volatile("ldmatrix.sync.aligned.m8n8.x4.trans.shared.b16 {%0,%1,%2,%3}, [%4];"
                 : "=r"(r0), "=r"(r1), "=r"(r2), "=r"(r3) : "r"(addr));
}
__device__ __forceinline__ void mma_bf16(float* d, const uint32_t* a, const uint32_t* b) {
    asm volatile("mma.sync.aligned.m16n8k16.row.col.f32.bf16.bf16.f32 "
                 "{%0,%1,%2,%3}, {%4,%5,%6,%7}, {%8,%9}, {%0,%1,%2,%3};"
                 : "+f"(d[0]), "+f"(d[1]), "+f"(d[2]), "+f"(d[3])
                 : "r"(a[0]), "r"(a[1]), "r"(a[2]), "r"(a[3]), "r"(b[0]), "r"(b[1]));
}
__device__ __forceinline__ void mma_tf32(float* d, const uint32_t* a, const uint32_t* b) {
    asm volatile("mma.sync.aligned.m16n8k8.row.col.f32.tf32.tf32.f32 "
                 "{%0,%1,%2,%3}, {%4,%5,%6,%7}, {%8,%9}, {%0,%1,%2,%3};"
                 : "+f"(d[0]), "+f"(d[1]), "+f"(d[2]), "+f"(d[3])
                 : "r"(a[0]), "r"(a[1]), "r"(a[2]), "r"(a[3]), "r"(b[0]), "r"(b[1]));
}
__device__ __forceinline__ uint32_t cvt_tf32(float x) {
    uint32_t r;
    asm("cvt.rna.tf32.f32 %0, %1;" : "=r"(r) : "f"(x));
    return r;
}
__device__ __forceinline__ uint32_t packbf2(float x, float y) {
    __nv_bfloat162 t = __floats2bfloat162_rn(x, y);
    return *(uint32_t*)&t;
}
#define SWZ(o)   ((o) ^ (((o) >> 3) & 0x70))   // SW128 (128B rows)
#define CP_ASYNC16(dst, src) \
    asm volatile("cp.async.cg.shared.global [%0], [%1], 16;" :: "r"(dst), "l"(src))
#define CP_COMMIT() asm volatile("cp.async.commit_group;" ::: "memory")
#define CP_WAIT(n)  asm volatile("cp.async.wait_group %0;" :: "n"(n) : "memory")

// ================ TF32 GEMM: C[M,N] fp32 = A[M,K] @ B[N,K]^T ====================
// Single-pass tf32 (operands pre-rounded in gmem). CTA tile 128x64, 8 warps
// (4M x 2N), warp tile 32x32, K-chunk 32 fp32 (128B rows, SW128).
// 3-stage cp.async, 24KB/stage = 72KB smem -> 2 CTAs/SM.
#define GT_KC 32
#define GT_AT 16384             // A tile: 128 rows x 128B
#define GT_BT 8192              // B tile: 64 rows x 128B
#define GT_STAGEB 24576
#define GT_SMEM (3*GT_STAGEB)   // 73728

extern __shared__ char gsm[];

__global__ void __launch_bounds__(256, 2) gemm_tf32(
        const float* __restrict__ A,
        const float* __restrict__ B1, float* __restrict__ C1, int N1, int nx1,
        const float* __restrict__ B2, float* __restrict__ C2, int N2, int K) {
    const int tid = threadIdx.x;
    const int wid = tid >> 5, lane = tid & 31;
    const int wm = wid & 3, wn = wid >> 2;
    const int m0 = blockIdx.y * 128;
    const int NIT = K / GT_KC;
    uint32_t sb = smem_to_u32(gsm);

    const float* B; float* C; int N, n0;
    if ((int)blockIdx.x < nx1) { B = B1; C = C1; N = N1; n0 = blockIdx.x * 64; }
    else { B = B2; C = C2; N = N2; n0 = (blockIdx.x - nx1) * 64; }

    float acc[2][4][4];
#pragma unroll
    for (int i = 0; i < 2; i++)
#pragma unroll
        for (int j = 0; j < 4; j++)
#pragma unroll
            for (int q = 0; q < 4; q++) acc[i][j][q] = 0.f;

    auto cp_stage = [&](int stage, int k0) {
        uint32_t st = sb + stage * GT_STAGEB;
        // A: 128 rows x 8 chunks of 16B = 1024 chunks
#pragma unroll
        for (int j = 0; j < 4; j++) {
            int idx = tid + j * 256;
            int r = idx >> 3, cg = idx & 7;
            CP_ASYNC16(st + SWZ((uint32_t)(r * 128 + cg * 16)),
                       A + (size_t)(m0 + r) * K + k0 + cg * 4);
        }
        // B: 64 rows x 8 chunks = 512 chunks
#pragma unroll
        for (int j = 0; j < 2; j++) {
            int idx = tid + j * 256;
            int r = idx >> 3, cg = idx & 7;
            CP_ASYNC16(st + GT_AT + SWZ((uint32_t)(r * 128 + cg * 16)),
                       B + (size_t)(n0 + r) * K + k0 + cg * 4);
        }
    };

    cp_stage(0, 0);
    CP_COMMIT();
    cp_stage(1, GT_KC);
    CP_COMMIT();

    int st_c = 0, st_p = 2;
    for (int it = 0; it < NIT; it++) {
        if (it + 1 < NIT) CP_WAIT(1); else CP_WAIT(0);
        __syncthreads();
        if (it + 2 < NIT) {
            cp_stage(st_p, (it + 2) * GT_KC);
            CP_COMMIT();
        }

        uint32_t smA = sb + st_c * GT_STAGEB;
        uint32_t smB = smA + GT_AT;

#pragma unroll
        for (int ks = 0; ks < 4; ks++) {
            // A frags (m16k8 tf32 via b16 ldsm.x4): matrices = (row,row+8) x (k0-3,k4-7)
            uint32_t a[2][4];
#pragma unroll
            for (int mt = 0; mt < 2; mt++) {
                uint32_t row = (uint32_t)(wm * 32 + mt * 16 + ((lane >> 3) & 1) * 8 + (lane & 7));
                uint32_t off = SWZ(row * 128 + (uint32_t)(ks * 32 + (lane >> 4) * 16));
                ldsm_x4(a[mt][0], a[mt][1], a[mt][2], a[mt][3], smA + off);
            }
            // B frags (k8n8 tf32): each ldsm.x4 covers n16 = two n8 tiles
            uint32_t b[4][2];
#pragma unroll
            for (int nb = 0; nb < 2; nb++) {
                uint32_t nrow = (uint32_t)(wn * 32 + nb * 16 + ((lane >> 4) & 1) * 8 + (lane & 7));
                uint32_t off = SWZ(nrow * 128 + (uint32_t)(ks * 32 + ((lane >> 3) & 1) * 16));
                uint32_t r0, r1, r2, r3;
                ldsm_x4(r0, r1, r2, r3, smB + off);
                b[2 * nb][0] = r0;     b[2 * nb][1] = r1;
                b[2 * nb + 1][0] = r2; b[2 * nb + 1][1] = r3;
            }
#pragma unroll
            for (int mt = 0; mt < 2; mt++)
#pragma unroll
                for (int nt = 0; nt < 4; nt++)
                    mma_tf32(acc[mt][nt], a[mt], b[nt]);
        }
        st_c = (st_c == 2) ? 0 : st_c + 1;
        st_p = (st_p == 2) ? 0 : st_p + 1;
    }

#pragma unroll
    for (int mt = 0; mt < 2; mt++) {
        int row = m0 + wm * 32 + mt * 16 + (lane >> 2);
#pragma unroll
        for (int nt = 0; nt < 4; nt++) {
            int col = n0 + wn * 32 + nt * 8 + 2 * (lane & 3);
            *(float2*)(C + (size_t)row * N + col) =
                make_float2(acc[mt][nt][0], acc[mt][nt][1]);
            *(float2*)(C + (size_t)(row + 8) * N + col) =
                make_float2(acc[mt][nt][2], acc[mt][nt][3]);
        }
    }
}

// ============== fp32 -> tf32-rounded fp32 (elementwise, replaces splits) ========
__global__ void roundtf_kernel(const float* __restrict__ in, float* __restrict__ outp,
                               int n4) {
    int i = blockIdx.x * blockDim.x + threadIdx.x;
    if (i >= n4) return;
    float4 v = ((const float4*)in)[i];
    v.x = __uint_as_float(cvt_tf32(v.x));
    v.y = __uint_as_float(cvt_tf32(v.y));
    v.z = __uint_as_float(cvt_tf32(v.z));
    v.w = __uint_as_float(cvt_tf32(v.w));
    ((float4*)outp)[i] = v;
}

// ------------- fused RMSNorm + rotary -> bf16 hi/lo (position = HEAD index) -----
__global__ void normrope_kernel(const float* __restrict__ in,
                                __nv_bfloat16* __restrict__ ohi,
                                __nv_bfloat16* __restrict__ olo,
                                int rowstride, int nheads) {
    int w = (blockIdx.x * blockDim.x + threadIdx.x) >> 5;
    int lane = threadIdx.x & 31;
    int total = BB * TT * nheads;
    if (w >= total) return;
    int h = w % nheads;
    int t = (w / nheads) % TT;
    int b = w / (nheads * TT);

    const float* src = in + (size_t)(b * TT + t) * rowstride + h * DH;
    float4 v = *(const float4*)(src + lane * 4);
    float ss = v.x * v.x + v.y * v.y + v.z * v.z + v.w * v.w;
#pragma unroll
    for (int o = 16; o; o >>= 1) ss += __shfl_xor_sync(0xffffffffu, ss, o);
    float scale = rsqrtf(ss * (1.0f / 128.0f) + 1.1920929e-07f);

    float x[4] = {v.x * scale, v.y * scale, v.z * scale, v.w * scale};
    float y[4];
#pragma unroll
    for (int i = 0; i < 4; i++) {
        float part = __shfl_xor_sync(0xffffffffu, x[i], 16);
        int d = lane * 4 + i;
        int j = d & 63;
        float freq = (j < 32) ? powf(1.0f / 1024.0f, (float)j * (1.0f / 31.0f)) : 0.0f;
        float s, c;
        sincosf((float)h * freq, &s, &c);
        if (d < 64) y[i] = x[i] * c + part * s;
        else        y[i] = -part * s + x[i] * c;
    }
    size_t off = ((size_t)(b * nheads + h) * TT + t) * DH + lane * 4;
    ushort4 uh, ul;
    unsigned short* ph = &uh.x; unsigned short* pl = &ul.x;
#pragma unroll
    for (int i = 0; i < 4; i++) {
        __nv_bfloat16 hh = __float2bfloat16(y[i]);
        __nv_bfloat16 ll = __float2bfloat16(y[i] - __bfloat162float(hh));
        ph[i] = __bfloat16_as_ushort(hh);
        pl[i] = __bfloat16_as_ushort(ll);
    }
    *(ushort4*)(ohi + off) = uh;
    *(ushort4*)(olo + off) = ul;
}

// ------------- V transpose + bf16 hi/lo split -----------------------------------
__global__ void vtrans_kernel(const float* __restrict__ kvlin,
                              __nv_bfloat16* __restrict__ vhi,
                              __nv_bfloat16* __restrict__ vlo) {
    int idx = blockIdx.x * blockDim.x + threadIdx.x;
    const int total = BB * TT * NKV * DH / 4;
    if (idx >= total) return;
    int d4 = idx & (DH / 4 - 1);
    int h = (idx >> 5) & (NKV - 1);
    int t = (idx >> 7) & (TT - 1);
    int b = idx >> 18;
    float4 v = *(const float4*)(kvlin + (size_t)(b * TT + t) * KVC + NKV * DH + h * DH + d4 * 4);
    float vv[4] = {v.x, v.y, v.z, v.w};
    ushort4 uh, ul;
    unsigned short* ph = &uh.x; unsigned short* pl = &ul.x;
#pragma unroll
    for (int j = 0; j < 4; j++) {
        __nv_bfloat16 hh = __float2bfloat16(vv[j]);
        __nv_bfloat16 ll = __float2bfloat16(vv[j] - __bfloat162float(hh));
        ph[j] = __bfloat16_as_ushort(hh);
        pl[j] = __bfloat16_as_ushort(ll);
    }
    size_t off = ((size_t)(b * NKV + h) * TT + t) * DH + d4 * 4;
    *(ushort4*)(vhi + off) = uh;
    *(ushort4*)(vlo + off) = ul;
}

// ============ HMMA flash v2: 128q x 64k, 16 warps (warp-pair k-split) ===========
// Static-max softmax (scores <= sqrt(128) < 12). Epilogue writes tf32-rounded
// fp32 attn (feeds the tf32 proj GEMM directly).
#define FQ 128
#define FK 64
#define FHALF_Q 16384
#define FHALF_KV 8192
#define FSM_QH 0
#define FSM_QL 32768
#define FSM_KV0 65536
#define FSTAGE 65536
#define FLASH_SMEM 196608
#define FTHREADS 512

__global__ void __launch_bounds__(FTHREADS) flash_hmma(
        const __nv_bfloat16* __restrict__ qhi, const __nv_bfloat16* __restrict__ qlo,
        const __nv_bfloat16* __restrict__ khi, const __nv_bfloat16* __restrict__ klo,
        const __nv_bfloat16* __restrict__ vhi, const __nv_bfloat16* __restrict__ vlo,
        float* __restrict__ attn) {
    const int tid = threadIdx.x, wid = tid >> 5, lane = tid & 31;
    const int qw = wid & 7;
    const int kh = wid >> 3;
    const int qt = gridDim.x - 1 - blockIdx.x;
    const int h = blockIdx.y, b = blockIdx.z;
    const int kvh = h >> 2;
    uint32_t sb = smem_to_u32(gsm);

    const __nv_bfloat16* Qh_g = qhi + ((size_t)(b * NH + h) * TT + qt * FQ) * DH;
    const __nv_bfloat16* Ql_g = qlo + ((size_t)(b * NH + h) * TT + qt * FQ) * DH;
    const __nv_bfloat16* Kh_g = khi + (size_t)(b * NKV + kvh) * TT * DH;
    const __nv_bfloat16* Kl_g = klo + (size_t)(b * NKV + kvh) * TT * DH;
    const __nv_bfloat16* Vh_g = vhi + (size_t)(b * NKV + kvh) * TT * DH;
    const __nv_bfloat16* Vl_g = vlo + (size_t)(b * NKV + kvh) * TT * DH;

    {
        const __nv_bfloat16* srcs[2] = {Qh_g, Ql_g};
        const uint32_t dsts[2] = {FSM_QH, FSM_QL};
#pragma unroll
        for (int a = 0; a < 2; a++)
#pragma unroll
            for (int i = 0; i < 4; i++) {
                int idx = tid + i * FTHREADS;
                int hf = idx >> 10, r = (idx >> 3) & 127, cg = idx & 7;
                CP_ASYNC16(sb + dsts[a] + hf * FHALF_Q + SWZ((uint32_t)(r * 128 + cg * 16)),
                           srcs[a] + (size_t)r * DH + hf * 64 + cg * 8);
            }
    }
    auto cp_kv = [&](int stage, int kt2) {
        uint32_t dstb = sb + FSM_KV0 + stage * FSTAGE;
        const __nv_bfloat16* srcs[4] = {Kh_g, Kl_g, Vh_g, Vl_g};
#pragma unroll
        for (int a = 0; a < 4; a++) {
            const __nv_bfloat16* src = srcs[a] + (size_t)kt2 * FK * DH;
#pragma unroll
            for (int i = 0; i < 2; i++) {
                int idx = tid + i * FTHREADS;
                int hf = idx >> 9, r = (idx >> 3) & 63, cg = idx & 7;
                CP_ASYNC16(dstb + a * 16384 + hf * FHALF_KV + SWZ((uint32_t)(r * 128 + cg * 16)),
                           src + (size_t)r * DH + hf * 64 + cg * 8);
            }
        }
    };
    cp_kv(0, 0);
    CP_COMMIT();

    const int ntiles = 2 * qt + 2;
    const int grow_lo = qt * FQ + qw * 16 + (lane >> 2);
    const float scl = 0.08838834764831845f;
    const float SMAX = 12.0f;

    float l_lo = 0.f, l_hi = 0.f;
    float o[16][4];
#pragma unroll
    for (int n = 0; n < 16; n++)
#pragma unroll
        for (int q = 0; q < 4; q++) o[n][q] = 0.f;

    for (int kt = 0; kt < ntiles; kt++) {
        CP_WAIT(0);
        __syncthreads();
        if (kt + 1 < ntiles) { cp_kv((kt + 1) & 1, kt + 1); CP_COMMIT(); }

        uint32_t kvb = sb + FSM_KV0 + (kt & 1) * FSTAGE;
        uint32_t smKh = kvb, smKl = kvb + 16384, smVh = kvb + 32768, smVl = kvb + 49152;

        float s[4][4];
#pragma unroll
        for (int n = 0; n < 4; n++)
#pragma unroll
            for (int q = 0; q < 4; q++) s[n][q] = 0.f;
#pragma unroll
        for (int ks = 0; ks < 8; ks++) {
            int hf = ks >> 2;
            uint32_t colb = (uint32_t)((ks & 3) * 32 + (lane >> 4) * 16);
            uint32_t aoff = SWZ((uint32_t)((qw * 16 + (lane & 15)) * 128) + colb);
            uint32_t aHi[4], aLo[4];
            ldsm_x4(aHi[0], aHi[1], aHi[2], aHi[3], sb + FSM_QH + hf * FHALF_Q + aoff);
            ldsm_x4(aLo[0], aLo[1], aLo[2], aLo[3], sb + FSM_QL + hf * FHALF_Q + aoff);
#pragma unroll
            for (int nt2 = 0; nt2 < 2; nt2++) {
                uint32_t boff = hf * FHALF_KV +
                    SWZ((uint32_t)((kh * 32 + nt2 * 16 + (lane & 15)) * 128) + colb);
                uint32_t r0, r1, r2, r3;
                uint32_t bh0[2], bh1[2], bl0[2], bl1[2];
                ldsm_x4(r0, r1, r2, r3, smKh + boff);
                bh0[0] = r0; bh0[1] = r2; bh1[0] = r1; bh1[1] = r3;
                ldsm_x4(r0, r1, r2, r3, smKl + boff);
                bl0[0] = r0; bl0[1] = r2; bl1[0] = r1; bl1[1] = r3;
                mma_bf16(s[2 * nt2], aHi, bh0);
                mma_bf16(s[2 * nt2], aHi, bl0);
                mma_bf16(s[2 * nt2], aLo, bh0);
                mma_bf16(s[2 * nt2 + 1], aHi, bh1);
                mma_bf16(s[2 * nt2 + 1], aHi, bl1);
                mma_bf16(s[2 * nt2 + 1], aLo, bh1);
            }
        }

#pragma unroll
        for (int nt = 0; nt < 4; nt++)
#pragma unroll
            for (int j = 0; j < 2; j++) {
                int gc = kt * FK + kh * 32 + nt * 8 + (lane & 3) * 2 + j;
                float p0 = __expf(s[nt][j] * scl - SMAX);
                float p1 = __expf(s[nt][j + 2] * scl - SMAX);
                s[nt][j]     = (gc <= grow_lo)     ? p0 : 0.f;
                s[nt][j + 2] = (gc <= grow_lo + 8) ? p1 : 0.f;
                l_lo += s[nt][j];
                l_hi += s[nt][j + 2];
            }

        uint32_t aPh[2][4], aPl[2][4];
#pragma unroll
        for (int kc = 0; kc < 2; kc++) {
            float* c0 = s[2 * kc];
            float* c1 = s[2 * kc + 1];
            uint32_t h00 = packbf2(c0[0], c0[1]);
            uint32_t h01 = packbf2(c0[2], c0[3]);
            uint32_t h10 = packbf2(c1[0], c1[1]);
            uint32_t h11 = packbf2(c1[2], c1[3]);
            aPh[kc][0] = h00; aPh[kc][1] = h01; aPh[kc][2] = h10; aPh[kc][3] = h11;
            __nv_bfloat162 t;
            t = *(__nv_bfloat162*)&h00;
            aPl[kc][0] = packbf2(c0[0] - __bfloat162float(t.x), c0[1] - __bfloat162float(t.y));
            t = *(__nv_bfloat162*)&h01;
            aPl[kc][1] = packbf2(c0[2] - __bfloat162float(t.x), c0[3] - __bfloat162float(t.y));
            t = *(__nv_bfloat162*)&h10;
            aPl[kc][2] = packbf2(c1[0] - __bfloat162float(t.x), c1[1] - __bfloat162float(t.y));
            t = *(__nv_bfloat162*)&h11;
            aPl[kc][3] = packbf2(c1[2] - __bfloat162float(t.x), c1[3] - __bfloat162float(t.y));
        }

#pragma unroll
        for (int kc = 0; kc < 2; kc++) {
#pragma unroll
            for (int hf = 0; hf < 2; hf++)
#pragma unroll
                for (int dt = 0; dt < 4; dt++) {
                    uint32_t voff = hf * FHALF_KV +
                        SWZ((uint32_t)((kh * 32 + kc * 16 + (lane & 15)) * 128 +
                                       dt * 32 + (lane >> 4) * 16));
                    uint32_t r0, r1, r2, r3;
                    uint32_t bh0[2], bh1[2], bl0[2], bl1[2];
                    ldsm_x4_t(r0, r1, r2, r3, smVh + voff);
                    bh0[0] = r0; bh0[1] = r1; bh1[0] = r2; bh1[1] = r3;
                    ldsm_x4_t(r0, r1, r2, r3, smVl + voff);
                    bl0[0] = r0; bl0[1] = r1; bl1[0] = r2; bl1[1] = r3;
                    int n = hf * 8 + dt * 2;
                    mma_bf16(o[n], aPh[kc], bh0);
                    mma_bf16(o[n], aPh[kc], bl0);
                    mma_bf16(o[n], aPl[kc], bh0);
                    mma_bf16(o[n + 1], aPh[kc], bh1);
                    mma_bf16(o[n + 1], aPh[kc], bl1);
                    mma_bf16(o[n + 1], aPl[kc], bh1);
                }
        }
    }

    l_lo += __shfl_xor_sync(0xffffffffu, l_lo, 1);
    l_lo += __shfl_xor_sync(0xffffffffu, l_lo, 2);
    l_hi += __shfl_xor_sync(0xffffffffu, l_hi, 1);
    l_hi += __shfl_xor_sync(0xffffffffu, l_hi, 2);

    __syncthreads();
    if (kh == 1) {
        if ((lane & 3) == 0) {
            *(float*)(gsm + FSM_KV0 + (qw * 16 + (lane >> 2)) * 4) = l_lo;
            *(float*)(gsm + FSM_KV0 + (qw * 16 + 8 + (lane >> 2)) * 4) = l_hi;
        }
        uint32_t ob = FSM_KV0 + 1024 + qw * 8192;
#pragma unroll
        for (int n = 0; n < 16; n++)
            *(float4*)(gsm + ob + (n * 32 + lane) * 16) =
                make_float4(o[n][0], o[n][1], o[n][2], o[n][3]);
    }
    __syncthreads();
    if (kh == 0) {
        l_lo += *(float*)(gsm + FSM_KV0 + (qw * 16 + (lane >> 2)) * 4);
        l_hi += *(float*)(gsm + FSM_KV0 + (qw * 16 + 8 + (lane >> 2)) * 4);
        uint32_t ob = FSM_KV0 + 1024 + qw * 8192;
#pragma unroll
        for (int n = 0; n < 16; n++) {
            float4 t = *(float4*)(gsm + ob + (n * 32 + lane) * 16);
            o[n][0] += t.x; o[n][1] += t.y; o[n][2] += t.z; o[n][3] += t.w;
        }

        float li_lo = 1.0f / l_lo, li_hi = 1.0f / l_hi;
        int t_lo = qt * FQ + qw * 16 + (lane >> 2);
        size_t base_lo = ((size_t)b * TT + t_lo) * CC + h * DH;
        size_t base_hi = base_lo + (size_t)8 * CC;
#pragma unroll
        for (int n = 0; n < 16; n++) {
            int d = n * 8 + (lane & 3) * 2;
            // tf32-rounded fp32 (feeds the tf32 proj GEMM with no extra pass)
            float v0 = __uint_as_float(cvt_tf32(o[n][0] * li_lo));
            float v1 = __uint_as_float(cvt_tf32(o[n][1] * li_lo));
            float v2 = __uint_as_float(cvt_tf32(o[n][2] * li_hi));
            float v3 = __uint_as_float(cvt_tf32(o[n][3] * li_hi));
            *(float2*)(attn + base_lo + d) = make_float2(v0, v1);
            *(float2*)(attn + base_hi + d) = make_float2(v2, v3);
        }
    }
}

// ------------- tail zero --------------------------------------------------------
__global__ void tailzero_kernel(float* out, int start, int total) {
    int i = start + blockIdx.x * blockDim.x + threadIdx.x;
    if (i < total) out[i] = 0.f;
}

// ------------- launcher --------------------------------------------------------
extern "C" void kernel_launch(void* const* d_in, const int* in_sizes, int n_in,
                              void* d_out, int out_size) {
    const float* x     = (const float*)d_in[0];
    const float* Wq    = (const float*)d_in[1];
    const float* Wkv   = (const float*)d_in[2];
    const float* Wproj = (const float*)d_in[3];
    float* out = (float*)d_out;

    float *qlin, *kvlin, *attn, *xr, *wqr, *wkvr, *wpr;
    __nv_bfloat16 *qhi, *qlo, *khi, *klo, *vhi, *vlo;
    cudaGetSymbolAddress((void**)&qlin, g_qlin);
    cudaGetSymbolAddress((void**)&kvlin, g_kvlin);
    cudaGetSymbolAddress((void**)&attn, g_attn);
    cudaGetSymbolAddress((void**)&xr, g_xr);
    cudaGetSymbolAddress((void**)&wqr, g_wqr);
    cudaGetSymbolAddress((void**)&wkvr, g_wkvr);
    cudaGetSymbolAddress((void**)&wpr, g_wpr);
    cudaGetSymbolAddress((void**)&qhi, g_qhi);   cudaGetSymbolAddress((void**)&qlo, g_qlo);
    cudaGetSymbolAddress((void**)&khi, g_khi);   cudaGetSymbolAddress((void**)&klo, g_klo);
    cudaGetSymbolAddress((void**)&vhi, g_vhi);   cudaGetSymbolAddress((void**)&vlo, g_vlo);

    cudaFuncSetAttribute(gemm_tf32, cudaFuncAttributeMaxDynamicSharedMemorySize, GT_SMEM);
    cudaFuncSetAttribute(flash_hmma, cudaFuncAttributeMaxDynamicSharedMemorySize, FLASH_SMEM);

    // 0) round operands to tf32 (replaces bf16 splits)
    {
        int n4;
        n4 = BT * CC / 4;  roundtf_kernel<<<(n4 + 255) / 256, 256>>>(x, xr, n4);
        n4 = CC * CC / 4;  roundtf_kernel<<<(n4 + 255) / 256, 256>>>(Wq, wqr, n4);
        n4 = KVC * CC / 4; roundtf_kernel<<<(n4 + 255) / 256, 256>>>(Wkv, wkvr, n4);
        n4 = CC * CC / 4;  roundtf_kernel<<<(n4 + 255) / 256, 256>>>(Wproj, wpr, n4);
    }
    // 1+2) fused [Q | KV] = x @ [Wq | Wkv]^T (tf32 single pass)
    {
        dim3 g(CC / 64 + KVC / 64, BT / 128);
        gemm_tf32<<<g, 256, GT_SMEM>>>(xr, wqr, qlin, CC, CC / 64, wkvr, kvlin, KVC, CC);
    }
    // 3) RMSNorm + RoPE on Q -> bf16 hi/lo [b,h,t,d]
    {
        int rows = BB * TT * NH;
        normrope_kernel<<<(rows * 32 + 255) / 256, 256>>>(qlin, qhi, qlo, CC, NH);
    }
    // 4) RMSNorm + RoPE on K -> bf16 hi/lo [b,kvh,t,d]
    {
        int rows = BB * TT * NKV;
        normrope_kernel<<<(rows * 32 + 255) / 256, 256>>>(kvlin, khi, klo, KVC, NKV);
    }
    // 5) V transpose + split -> bf16 hi/lo [b,kvh,t,d]
    {
        int total = BB * TT * NKV * DH / 4;
        vtrans_kernel<<<(total + 255) / 256, 256>>>(kvlin, vhi, vlo);
    }
    // 6) HMMA flash v2 -> attn (tf32-rounded fp32, [b,t,h*dh])
    {
        dim3 g(TT / FQ, NH, BB);
        flash_hmma<<<g, FTHREADS, FLASH_SMEM>>>(qhi, qlo, khi, klo, vhi, vlo, attn);
    }
    // 7) y = attn @ Wproj^T (tf32 single pass)
    {
        dim3 g(CC / 64, BT / 128);
        gemm_tf32<<<g, 256, GT_SMEM>>>(attn, wpr, out, CC, CC / 64, wpr, out, CC, CC);
    }
    // 8) trailing scalar output
    {
        int btc = BB * TT * CC;
        if (out_size > btc) {
            int rem = out_size - btc;
            tailzero_kernel<<<(rem + 255) / 256, 256>>>(out, btc, out_size);
        }
    }
}